// round 2
// baseline (speedup 1.0000x reference)
#include <cuda_runtime.h>
#include <math.h>

#define SEQ  512
#define PREV 512
#define TOT  1024
#define BSZ  8
#define DIN  1024
#define NH   16
#define HD   64

// ---------------- scratch (static device globals; no allocations) ----------------
__device__ float g_q   [SEQ * BSZ * DIN];       // (SEQ,BS,H*D)   16 MB
__device__ float g_k   [TOT * BSZ * DIN];       // (TOT,BS,H*D)   32 MB
__device__ float g_v   [TOT * BSZ * DIN];       // (TOT,BS,H*D)   32 MB
__device__ float g_p   [TOT * DIN];             // (TOT,H*D)       4 MB
__device__ float g_attn[(size_t)BSZ * NH * SEQ * TOT]; // (BS,H,SEQ,TOT) 256 MB
__device__ float g_awv [SEQ * BSZ * DIN];       // (SEQ,BS,H*D)   16 MB
__device__ float g_out [SEQ * BSZ * DIN];       // pre-LN         16 MB

// ---------------- generic fp32 tiled GEMM: C = gather(A0|A1) @ B (+resid) -------
// 128x128 tile, BK=8, 256 threads, 8x8 per thread.
// Rows [0,M0) come from A0, rows [M0,M) from A1 (concat along M).
// Columns < Nsplit go to C0, the rest to C1 (both with row stride Nsplit).
__global__ __launch_bounds__(256) void gemm_kernel(
    const float* __restrict__ A0, const float* __restrict__ A1, int M0,
    const float* __restrict__ B, int N, int K,
    float* __restrict__ C0, float* __restrict__ C1, int Nsplit,
    const float* __restrict__ resid)
{
    __shared__ float As[8][128];
    __shared__ float Bs[8][128];
    const int tid = threadIdx.x;
    const int tx = tid & 15;
    const int ty = tid >> 4;
    const int row0 = blockIdx.y * 128;
    const int col0 = blockIdx.x * 128;

    float acc[8][8];
#pragma unroll
    for (int i = 0; i < 8; i++)
#pragma unroll
        for (int j = 0; j < 8; j++) acc[i][j] = 0.f;

    const int la_r = tid >> 1;            // 0..127
    const int la_c = (tid & 1) * 4;       // 0 or 4
    const int lb_r = tid >> 5;            // 0..7
    const int lb_c = (tid & 31) * 4;      // 0..124

    const int gr = row0 + la_r;
    const float* Arow = (gr < M0) ? (A0 + (size_t)gr * K)
                                  : (A1 + (size_t)(gr - M0) * K);
    const float* Bp = B + (size_t)lb_r * N + col0 + lb_c;

    for (int k0 = 0; k0 < K; k0 += 8) {
        float4 av = *(const float4*)(Arow + k0 + la_c);
        As[la_c + 0][la_r] = av.x;
        As[la_c + 1][la_r] = av.y;
        As[la_c + 2][la_r] = av.z;
        As[la_c + 3][la_r] = av.w;
        *(float4*)&Bs[lb_r][lb_c] = *(const float4*)(Bp + (size_t)k0 * N);
        __syncthreads();
#pragma unroll
        for (int k = 0; k < 8; k++) {
            float a[8], b[8];
            *(float4*)&a[0] = *(const float4*)&As[k][ty * 8];
            *(float4*)&a[4] = *(const float4*)&As[k][ty * 8 + 4];
            *(float4*)&b[0] = *(const float4*)&Bs[k][tx * 8];
            *(float4*)&b[4] = *(const float4*)&Bs[k][tx * 8 + 4];
#pragma unroll
            for (int i = 0; i < 8; i++)
#pragma unroll
                for (int j = 0; j < 8; j++)
                    acc[i][j] += a[i] * b[j];
        }
        __syncthreads();
    }

#pragma unroll
    for (int i = 0; i < 8; i++) {
        const int r = row0 + ty * 8 + i;
#pragma unroll
        for (int j = 0; j < 8; j++) {
            const int c = col0 + tx * 8 + j;
            float val = acc[i][j];
            if (resid) val += resid[(size_t)r * N + c];
            if (c < Nsplit) C0[(size_t)r * Nsplit + c] = val;
            else            C1[(size_t)r * Nsplit + (c - Nsplit)] = val;
        }
    }
}

// ---------------- attention scores: content + rel-position + mask + scale -------
// score[i,j,b,h] = (q+u)[i]·k[j] + (q+v)[i]·p[j+511-i]   if j <= i+PREV else -inf
// One block = 64x64 (i,j) tile for one (b,h). 256 threads, 4x4 per thread.
__global__ __launch_bounds__(256) void scores_kernel(
    const float* __restrict__ q, const float* __restrict__ kmat,
    const float* __restrict__ p, const float* __restrict__ u,
    const float* __restrict__ vvec, float* __restrict__ attn)
{
    const int j0 = blockIdx.x * 64;
    const int i0 = blockIdx.y * 64;
    const int bh = blockIdx.z;
    const int b = bh >> 4, h = bh & 15;
    const int tid = threadIdx.x;
    float* out = attn + ((size_t)bh * SEQ + i0) * TOT + j0;

    const float NEG = -__int_as_float(0x7f800000); // -inf

    if (j0 - i0 >= 576) {           // whole tile masked (j_min > i_max + PREV)
        for (int t = tid; t < 64 * 64; t += 256)
            out[(size_t)(t >> 6) * TOT + (t & 63)] = NEG;
        return;
    }

    __shared__ float Qc[16][65], Qp[16][65], Ks[16][65], Ps[16][130];
    const int tx = tid & 15, ty = tid >> 4;
    const int ib = ty * 4, jb = tx * 4;
    const int rbase = j0 - i0 + 448;   // = j0 + 511 - (i0+63), always >= 0

    float acc[4][4] = {};
    for (int d0 = 0; d0 < HD; d0 += 16) {
        for (int t = tid; t < 1024; t += 256) {
            const int dd = t & 15, row = t >> 4;
            const int d = d0 + dd;
            const float qv = q[((size_t)(i0 + row) * BSZ + b) * DIN + h * HD + d];
            Qc[dd][row] = qv + u[h * HD + d];
            Qp[dd][row] = qv + vvec[h * HD + d];
            Ks[dd][row] = kmat[((size_t)(j0 + row) * BSZ + b) * DIN + h * HD + d];
        }
        for (int t = tid; t < 128 * 16; t += 256) {
            const int dd = t & 15, rr = t >> 4;
            int r = rbase + rr;
            if (r > TOT - 1) r = TOT - 1;    // clamped rows are masked anyway
            Ps[dd][rr] = p[(size_t)r * DIN + h * HD + d0 + dd];
        }
        __syncthreads();
#pragma unroll
        for (int dd = 0; dd < 16; dd++) {
            float qc[4], qp[4], kv[4];
#pragma unroll
            for (int a = 0; a < 4; a++) {
                qc[a] = Qc[dd][ib + a];
                qp[a] = Qp[dd][ib + a];
                kv[a] = Ks[dd][jb + a];
            }
#pragma unroll
            for (int a = 0; a < 4; a++)
#pragma unroll
                for (int c = 0; c < 4; c++)
                    acc[a][c] += qc[a] * kv[c]
                               + qp[a] * Ps[dd][jb + c + 63 - ib - a];
        }
        __syncthreads();
    }

#pragma unroll
    for (int a = 0; a < 4; a++) {
        const int i = i0 + ib + a;
#pragma unroll
        for (int c = 0; c < 4; c++) {
            const int j = j0 + jb + c;
            out[(size_t)(ib + a) * TOT + jb + c] =
                (j <= i + PREV) ? acc[a][c] * 0.125f : NEG;
        }
    }
}

// ---------------- row softmax over j (TOT=1024), one block per row -------------
__global__ __launch_bounds__(256) void softmax_kernel(float* __restrict__ attn)
{
    float* ptr = attn + (size_t)blockIdx.x * TOT;
    const int tid = threadIdx.x;
    float4 x = ((float4*)ptr)[tid];
    __shared__ float red[8];

    float m = fmaxf(fmaxf(x.x, x.y), fmaxf(x.z, x.w));
#pragma unroll
    for (int o = 16; o; o >>= 1) m = fmaxf(m, __shfl_xor_sync(0xffffffffu, m, o));
    if ((tid & 31) == 0) red[tid >> 5] = m;
    __syncthreads();
    m = red[0];
#pragma unroll
    for (int w = 1; w < 8; w++) m = fmaxf(m, red[w]);
    __syncthreads();

    const float e0 = __expf(x.x - m);
    const float e1 = __expf(x.y - m);
    const float e2 = __expf(x.z - m);
    const float e3 = __expf(x.w - m);
    float s = e0 + e1 + e2 + e3;
#pragma unroll
    for (int o = 16; o; o >>= 1) s += __shfl_xor_sync(0xffffffffu, s, o);
    if ((tid & 31) == 0) red[tid >> 5] = s;
    __syncthreads();
    s = red[0];
#pragma unroll
    for (int w = 1; w < 8; w++) s += red[w];

    const float inv = 1.f / s;
    ((float4*)ptr)[tid] = make_float4(e0 * inv, e1 * inv, e2 * inv, e3 * inv);
}

// ---------------- awv = attn @ V per (b,h). 64x64 output tile per block --------
__global__ __launch_bounds__(256) void av_kernel(
    const float* __restrict__ attn, const float* __restrict__ vmat,
    float* __restrict__ awv)
{
    const int i0 = blockIdx.x * 64;
    const int bh = blockIdx.y;
    const int b = bh >> 4, h = bh & 15;
    const int tid = threadIdx.x;
    const int tx = tid & 15, ty = tid >> 4;

    __shared__ float Att[16][65], Vs[16][65];
    float acc[4][4] = {};
    const float* arow = attn + ((size_t)bh * SEQ + i0) * TOT;
    const int jlim = i0 + 576;   // probs are exactly 0 beyond i0+63+PREV

    for (int j0 = 0; j0 < jlim; j0 += 16) {
        for (int t = tid; t < 1024; t += 256) {
            const int jj = t & 15, ii = t >> 4;
            Att[jj][ii] = arow[(size_t)ii * TOT + j0 + jj];
        }
        for (int t = tid; t < 1024; t += 256) {
            const int c = t & 63, jj = t >> 6;
            Vs[jj][c] = vmat[((size_t)(j0 + jj) * BSZ + b) * DIN + h * HD + c];
        }
        __syncthreads();
#pragma unroll
        for (int jj = 0; jj < 16; jj++) {
            float a4[4], b4[4];
#pragma unroll
            for (int a = 0; a < 4; a++) a4[a] = Att[jj][ty * 4 + a];
#pragma unroll
            for (int c = 0; c < 4; c++) b4[c] = Vs[jj][tx * 4 + c];
#pragma unroll
            for (int a = 0; a < 4; a++)
#pragma unroll
                for (int c = 0; c < 4; c++)
                    acc[a][c] += a4[a] * b4[c];
        }
        __syncthreads();
    }

#pragma unroll
    for (int a = 0; a < 4; a++) {
        const int i = i0 + ty * 4 + a;
#pragma unroll
        for (int c = 0; c < 4; c++)
            awv[(((size_t)i * BSZ + b) * NH + h) * HD + tx * 4 + c] = acc[a][c];
    }
}

// ---------------- LayerNorm over last dim (1024), one block per row ------------
__global__ __launch_bounds__(256) void ln_kernel(
    const float* __restrict__ x, const float* __restrict__ gamma,
    const float* __restrict__ beta, float* __restrict__ out)
{
    const size_t row = blockIdx.x;
    const int tid = threadIdx.x;
    const float4 v = ((const float4*)(x + row * DIN))[tid];
    __shared__ float red[8];

    float s = v.x + v.y + v.z + v.w;
#pragma unroll
    for (int o = 16; o; o >>= 1) s += __shfl_xor_sync(0xffffffffu, s, o);
    if ((tid & 31) == 0) red[tid >> 5] = s;
    __syncthreads();
    s = red[0];
#pragma unroll
    for (int w = 1; w < 8; w++) s += red[w];
    const float mu = s * (1.0f / DIN);
    __syncthreads();

    const float d0 = v.x - mu, d1 = v.y - mu, d2 = v.z - mu, d3 = v.w - mu;
    float s2 = d0 * d0 + d1 * d1 + d2 * d2 + d3 * d3;
#pragma unroll
    for (int o = 16; o; o >>= 1) s2 += __shfl_xor_sync(0xffffffffu, s2, o);
    if ((tid & 31) == 0) red[tid >> 5] = s2;
    __syncthreads();
    s2 = red[0];
#pragma unroll
    for (int w = 1; w < 8; w++) s2 += red[w];
    const float inv = rsqrtf(s2 * (1.0f / DIN) + 1e-5f);

    const float4 g  = ((const float4*)gamma)[tid];
    const float4 bb = ((const float4*)beta)[tid];
    float4 o4;
    o4.x = d0 * inv * g.x + bb.x;
    o4.y = d1 * inv * g.y + bb.y;
    o4.z = d2 * inv * g.z + bb.z;
    o4.w = d3 * inv * g.w + bb.w;
    ((float4*)(out + row * DIN))[tid] = o4;
}

// ---------------- launch ---------------------------------------------------------
extern "C" void kernel_launch(void* const* d_in, const int* in_sizes, int n_in,
                              void* d_out, int out_size)
{
    const float* input_ = (const float*)d_in[0];
    const float* pos    = (const float*)d_in[1];
    const float* memory = (const float*)d_in[2];
    const float* u      = (const float*)d_in[3];
    const float* vvec   = (const float*)d_in[4];
    // d_in[5] = mask (unused: mask is analytic, j <= i + PREV)
    const float* W_kv   = (const float*)d_in[6];
    const float* W_q    = (const float*)d_in[7];
    const float* W_p    = (const float*)d_in[8];
    const float* W_out  = (const float*)d_in[9];
    const float* gamma  = (const float*)d_in[10];
    const float* beta   = (const float*)d_in[11];
    float* out = (float*)d_out;

    float *pq, *pk, *pv, *pp, *pattn, *pawv, *pout;
    cudaGetSymbolAddress((void**)&pq,    g_q);
    cudaGetSymbolAddress((void**)&pk,    g_k);
    cudaGetSymbolAddress((void**)&pv,    g_v);
    cudaGetSymbolAddress((void**)&pp,    g_p);
    cudaGetSymbolAddress((void**)&pattn, g_attn);
    cudaGetSymbolAddress((void**)&pawv,  g_awv);
    cudaGetSymbolAddress((void**)&pout,  g_out);

    // 1) kv = concat(memory, input_) @ W_kv  -> split into K and V
    gemm_kernel<<<dim3(2048 / 128, 8192 / 128), 256>>>(
        memory, input_, PREV * BSZ, W_kv, 2 * DIN, DIN, pk, pv, DIN, nullptr);

    // 2) q = input_ @ W_q
    gemm_kernel<<<dim3(DIN / 128, (SEQ * BSZ) / 128), 256>>>(
        input_, input_, SEQ * BSZ, W_q, DIN, DIN, pq, nullptr, DIN, nullptr);

    // 3) p = pos_embs @ W_p
    gemm_kernel<<<dim3(DIN / 128, TOT / 128), 256>>>(
        pos, pos, TOT, W_p, DIN, DIN, pp, nullptr, DIN, nullptr);

    // 4) scores (content + shifted position + mask + scale)
    scores_kernel<<<dim3(TOT / 64, SEQ / 64, BSZ * NH), 256>>>(
        pq, pk, pp, u, vvec, pattn);

    // 5) softmax over j
    softmax_kernel<<<BSZ * NH * SEQ, 256>>>(pattn);

    // 6) awv = attn @ V
    av_kernel<<<dim3(SEQ / 64, BSZ * NH), 256>>>(pattn, pv, pawv);

    // 7) out_pre = input_ + awv @ W_out
    gemm_kernel<<<dim3(DIN / 128, (SEQ * BSZ) / 128), 256>>>(
        pawv, pawv, SEQ * BSZ, W_out, DIN, DIN, pout, nullptr, DIN, input_);

    // 8) LayerNorm -> d_out
    ln_kernel<<<SEQ * BSZ, 256>>>(pout, gamma, beta, out);
}

// round 3
// speedup vs baseline: 3.3568x; 3.3568x over previous
#include <cuda_runtime.h>
#include <math.h>

#define SEQ  512
#define PREV 512
#define TOT  1024
#define BSZ  8
#define DIN  1024
#define NH   16
#define HD   64

// ---------------- scratch (static device globals; no allocations) ----------------
__device__ float g_q   [SEQ * BSZ * DIN];                 // 16 MB
__device__ float g_k   [TOT * BSZ * DIN];                 // 32 MB
__device__ float g_v   [TOT * BSZ * DIN];                 // 32 MB
__device__ float g_p   [TOT * DIN];                       //  4 MB
__device__ float g_attn[(size_t)BSZ * NH * SEQ * TOT];    // 256 MB (scores -> probs)
__device__ float g_pos [(size_t)BSZ * NH * SEQ * TOT];    // 256 MB (pos scores)
__device__ float g_awv [SEQ * BSZ * DIN];                 // 16 MB
__device__ float g_out [SEQ * BSZ * DIN];                 // 16 MB

__device__ __forceinline__ unsigned f2tf32(float x) {
    unsigned r;
    asm("cvt.rna.tf32.f32 %0, %1;" : "=r"(r) : "f"(x));
    return r;
}

#define MMA_TF32(c, a, b)                                                      \
    asm volatile(                                                              \
        "mma.sync.aligned.m16n8k8.row.col.f32.tf32.tf32.f32 "                  \
        "{%0,%1,%2,%3},{%4,%5,%6,%7},{%8,%9},{%0,%1,%2,%3};"                   \
        : "+f"(c[0]), "+f"(c[1]), "+f"(c[2]), "+f"(c[3])                       \
        : "r"(a[0]), "r"(a[1]), "r"(a[2]), "r"(a[3]), "r"(b[0]), "r"(b[1]))

// ---------------- tensor-core tf32 GEMM, 128 x BN tile, BK=32, 256 threads ------
// MODE 0: C = concat(A0[,M0)|A1) @ B (row-major B), optional resid, optional
//         column split at Nsplit (C0 then C1, both row-stride ldc).
// MODE 1: content scores per z=(b*16+h): C = (A+bias) @ B^T  (B rows are n-index),
//         tile skipped if fully masked (col0 >= row0+640).
// MODE 2: position scores per z: C = (A+bias) @ B^T, tile skipped if never read.
// MODE 3: AV per z: C = A @ B (row-major B), k-band limited to row0+640.
template<int BN, int MODE>
__global__ __launch_bounds__(256) void tcgemm(
    const float* __restrict__ A0, const float* __restrict__ A1, int M0, long lda,
    const float* __restrict__ bias,
    const float* __restrict__ B, long ldb,
    float* __restrict__ C, float* __restrict__ C1, int Nsplit, long ldc,
    const float* __restrict__ resid,
    int M, int N, int K)
{
    constexpr int BM   = 128;
    constexpr int BK   = 32;
    constexpr int ASTR = BK + 4;   // 36: bank-conflict-free fragment reads
    constexpr int BSTR = BN + 8;   // conflict-free fragment reads
    constexpr int MT   = 2;        // 2 m16 tiles per warp (warp tile m = 32)
    constexpr int NT   = BN / 16;  // n8 tiles per warp  (warp tile n = BN/2)

    __shared__ float As[BM * ASTR];
    __shared__ float Bs[BK * BSTR];

    const int tid  = threadIdx.x;
    const int wid  = tid >> 5, lane = tid & 31;
    const int gid  = lane >> 2, tig = lane & 3;
    const int warp_m = (wid & 3) * 32;
    const int warp_n = (wid >> 2) * (BN / 2);
    const int row0 = blockIdx.y * BM;
    const int col0 = blockIdx.x * BN;
    const int z    = blockIdx.z;

    const float* Aptr = A0;
    const float* Bptr = B;
    const float* biasp = bias;
    float* Cptr = C;

    if (MODE == 1) {
        if (col0 >= row0 + 640) return;               // fully masked tile
        Aptr  += (size_t)z * HD;
        biasp += (size_t)(z & 15) * HD;
        Bptr  += (size_t)z * HD;
        Cptr  += (size_t)z * SEQ * TOT;
    }
    if (MODE == 2) {
        if (col0 + BN <= 384 - row0) return;          // never-read tile
        Aptr  += (size_t)z * HD;
        biasp += (size_t)(z & 15) * HD;
        Bptr  += (size_t)(z & 15) * HD;
        Cptr  += (size_t)z * SEQ * TOT;
    }
    if (MODE == 3) {
        Aptr += (size_t)z * SEQ * TOT;
        Bptr += (size_t)z * HD;
        Cptr += (size_t)z * HD;
    }

    int Klim = K;
    if (MODE == 3) Klim = min(K, row0 + 640);         // probs are 0 beyond band

    float c[MT][NT][4];
#pragma unroll
    for (int mt = 0; mt < MT; mt++)
#pragma unroll
        for (int nt = 0; nt < NT; nt++)
#pragma unroll
            for (int q = 0; q < 4; q++) c[mt][nt][q] = 0.f;

    for (int k0 = 0; k0 < Klim; k0 += BK) {
        // ---- load A tile (BM x BK), m-major, cvt to tf32, optional bias ----
#pragma unroll
        for (int it = 0; it < (BM * (BK / 4)) / 256; it++) {
            const int f  = tid + it * 256;
            const int m  = f >> 3;
            const int kc = (f & 7) * 4;
            const int gm = row0 + m;
            const int gk = k0 + kc;
            const float* src;
            if (MODE == 0)
                src = (gm < M0 ? A0 + (size_t)gm * lda
                               : A1 + (size_t)(gm - M0) * lda) + gk;
            else
                src = Aptr + (size_t)gm * lda + gk;
            float4 v = *(const float4*)src;
            if (MODE == 1 || MODE == 2) {
                v.x += biasp[gk];     v.y += biasp[gk + 1];
                v.z += biasp[gk + 2]; v.w += biasp[gk + 3];
            }
            As[m * ASTR + kc + 0] = __uint_as_float(f2tf32(v.x));
            As[m * ASTR + kc + 1] = __uint_as_float(f2tf32(v.y));
            As[m * ASTR + kc + 2] = __uint_as_float(f2tf32(v.z));
            As[m * ASTR + kc + 3] = __uint_as_float(f2tf32(v.w));
        }
        // ---- load B tile (BK x BN) ----
        if (MODE == 0 || MODE == 3) {
#pragma unroll
            for (int it = 0; it < (BK * BN / 4) / 256; it++) {
                const int f  = tid + it * 256;
                const int k  = f / (BN / 4);
                const int nc = (f % (BN / 4)) * 4;
                float4 v = *(const float4*)(Bptr + (size_t)(k0 + k) * ldb + col0 + nc);
                float4 w;
                w.x = __uint_as_float(f2tf32(v.x));
                w.y = __uint_as_float(f2tf32(v.y));
                w.z = __uint_as_float(f2tf32(v.z));
                w.w = __uint_as_float(f2tf32(v.w));
                *(float4*)&Bs[k * BSTR + nc] = w;
            }
        } else { // transposed source: element (k, n) = B[n*ldb + k]
#pragma unroll
            for (int it = 0; it < (BK * BN / 4) / 256; it++) {
                const int f  = tid + it * 256;
                const int n  = f % BN;
                const int k4 = (f / BN) * 4;
                float4 v = *(const float4*)(Bptr + (size_t)(col0 + n) * ldb + k0 + k4);
                Bs[(k4 + 0) * BSTR + n] = __uint_as_float(f2tf32(v.x));
                Bs[(k4 + 1) * BSTR + n] = __uint_as_float(f2tf32(v.y));
                Bs[(k4 + 2) * BSTR + n] = __uint_as_float(f2tf32(v.z));
                Bs[(k4 + 3) * BSTR + n] = __uint_as_float(f2tf32(v.w));
            }
        }
        __syncthreads();

#pragma unroll
        for (int ks = 0; ks < 4; ks++) {
            const int kk = ks * 8;
            unsigned a[MT][4], b[NT][2];
#pragma unroll
            for (int mt = 0; mt < MT; mt++) {
                const int m = warp_m + mt * 16 + gid;
                a[mt][0] = __float_as_uint(As[m * ASTR + kk + tig]);
                a[mt][1] = __float_as_uint(As[(m + 8) * ASTR + kk + tig]);
                a[mt][2] = __float_as_uint(As[m * ASTR + kk + tig + 4]);
                a[mt][3] = __float_as_uint(As[(m + 8) * ASTR + kk + tig + 4]);
            }
#pragma unroll
            for (int nt = 0; nt < NT; nt++) {
                const int n = warp_n + nt * 8 + gid;
                b[nt][0] = __float_as_uint(Bs[(kk + tig) * BSTR + n]);
                b[nt][1] = __float_as_uint(Bs[(kk + tig + 4) * BSTR + n]);
            }
#pragma unroll
            for (int mt = 0; mt < MT; mt++)
#pragma unroll
                for (int nt = 0; nt < NT; nt++)
                    MMA_TF32(c[mt][nt], a[mt], b[nt]);
        }
        __syncthreads();
    }

    // ---- epilogue ----
#pragma unroll
    for (int mt = 0; mt < MT; mt++) {
        const int r0 = row0 + warp_m + mt * 16 + gid;
#pragma unroll
        for (int nt = 0; nt < NT; nt++) {
            const int cb = col0 + warp_n + nt * 8 + 2 * tig;
#pragma unroll
            for (int half = 0; half < 2; half++) {
                const int r = r0 + half * 8;
#pragma unroll
                for (int e = 0; e < 2; e++) {
                    const int cc = cb + e;
                    float val = c[mt][nt][half * 2 + e];
                    if (MODE == 0) {
                        if (resid) val += resid[(size_t)r * ldc + cc];
                        if (cc < Nsplit) Cptr[(size_t)r * ldc + cc] = val;
                        else             C1 [(size_t)r * ldc + cc - Nsplit] = val;
                    } else {
                        Cptr[(size_t)r * ldc + cc] = val;
                    }
                }
            }
        }
    }
}

// ---- fused rel-shift + mask + scale + softmax: one block per (b,h,i) row ------
__global__ __launch_bounds__(256) void softmax_fused(
    float* __restrict__ attn, const float* __restrict__ pos_s)
{
    const int i = blockIdx.x & (SEQ - 1);
    const size_t row = blockIdx.x;
    float* cp = attn + row * TOT;
    const float* ps = pos_s + row * TOT;
    const int tid = threadIdx.x;
    const int j0 = tid * 4;
    const int roff = 511 - i;     // r = j + roff; valid iff r <= 1023
    __shared__ float red[8];
    const float NEG = -__int_as_float(0x7f800000);

    float4 cv = *(const float4*)(cp + j0);
    float v[4];
#pragma unroll
    for (int l = 0; l < 4; l++) {
        const int r = j0 + l + roff;
        const float pv = (r <= TOT - 1) ? ps[r] : 0.f;
        const float cvl = (&cv.x)[l];
        v[l] = (r <= TOT - 1) ? (cvl + pv) * 0.125f : NEG;
    }

    float m = fmaxf(fmaxf(v[0], v[1]), fmaxf(v[2], v[3]));
#pragma unroll
    for (int o = 16; o; o >>= 1) m = fmaxf(m, __shfl_xor_sync(0xffffffffu, m, o));
    if ((tid & 31) == 0) red[tid >> 5] = m;
    __syncthreads();
    m = red[0];
#pragma unroll
    for (int w = 1; w < 8; w++) m = fmaxf(m, red[w]);
    __syncthreads();

    float e[4], s = 0.f;
#pragma unroll
    for (int l = 0; l < 4; l++) { e[l] = __expf(v[l] - m); s += e[l]; }
#pragma unroll
    for (int o = 16; o; o >>= 1) s += __shfl_xor_sync(0xffffffffu, s, o);
    if ((tid & 31) == 0) red[tid >> 5] = s;
    __syncthreads();
    s = red[0];
#pragma unroll
    for (int w = 1; w < 8; w++) s += red[w];
    const float inv = 1.f / s;

    *(float4*)(cp + j0) = make_float4(e[0] * inv, e[1] * inv, e[2] * inv, e[3] * inv);
}

// ---------------- LayerNorm over last dim (1024), one block per row ------------
__global__ __launch_bounds__(256) void ln_kernel(
    const float* __restrict__ x, const float* __restrict__ gamma,
    const float* __restrict__ beta, float* __restrict__ out)
{
    const size_t row = blockIdx.x;
    const int tid = threadIdx.x;
    const float4 v = ((const float4*)(x + row * DIN))[tid];
    __shared__ float red[8];

    float s = v.x + v.y + v.z + v.w;
#pragma unroll
    for (int o = 16; o; o >>= 1) s += __shfl_xor_sync(0xffffffffu, s, o);
    if ((tid & 31) == 0) red[tid >> 5] = s;
    __syncthreads();
    s = red[0];
#pragma unroll
    for (int w = 1; w < 8; w++) s += red[w];
    const float mu = s * (1.0f / DIN);
    __syncthreads();

    const float d0 = v.x - mu, d1 = v.y - mu, d2 = v.z - mu, d3 = v.w - mu;
    float s2 = d0 * d0 + d1 * d1 + d2 * d2 + d3 * d3;
#pragma unroll
    for (int o = 16; o; o >>= 1) s2 += __shfl_xor_sync(0xffffffffu, s2, o);
    if ((tid & 31) == 0) red[tid >> 5] = s2;
    __syncthreads();
    s2 = red[0];
#pragma unroll
    for (int w = 1; w < 8; w++) s2 += red[w];
    const float inv = rsqrtf(s2 * (1.0f / DIN) + 1e-5f);

    const float4 g  = ((const float4*)gamma)[tid];
    const float4 bb = ((const float4*)beta)[tid];
    float4 o4;
    o4.x = d0 * inv * g.x + bb.x;
    o4.y = d1 * inv * g.y + bb.y;
    o4.z = d2 * inv * g.z + bb.z;
    o4.w = d3 * inv * g.w + bb.w;
    ((float4*)(out + row * DIN))[tid] = o4;
}

// ---------------- launch ---------------------------------------------------------
extern "C" void kernel_launch(void* const* d_in, const int* in_sizes, int n_in,
                              void* d_out, int out_size)
{
    const float* input_ = (const float*)d_in[0];
    const float* pos    = (const float*)d_in[1];
    const float* memory = (const float*)d_in[2];
    const float* u      = (const float*)d_in[3];
    const float* vvec   = (const float*)d_in[4];
    // d_in[5] = mask (analytic: j <= i + PREV)
    const float* W_kv   = (const float*)d_in[6];
    const float* W_q    = (const float*)d_in[7];
    const float* W_p    = (const float*)d_in[8];
    const float* W_out  = (const float*)d_in[9];
    const float* gamma  = (const float*)d_in[10];
    const float* beta   = (const float*)d_in[11];
    float* out = (float*)d_out;

    float *pq, *pk, *pv, *pp, *pattn, *ppos, *pawv, *pout;
    cudaGetSymbolAddress((void**)&pq,    g_q);
    cudaGetSymbolAddress((void**)&pk,    g_k);
    cudaGetSymbolAddress((void**)&pv,    g_v);
    cudaGetSymbolAddress((void**)&pp,    g_p);
    cudaGetSymbolAddress((void**)&pattn, g_attn);
    cudaGetSymbolAddress((void**)&ppos,  g_pos);
    cudaGetSymbolAddress((void**)&pawv,  g_awv);
    cudaGetSymbolAddress((void**)&pout,  g_out);

    // 1) kv = concat(memory, input_) @ W_kv  -> K | V split
    tcgemm<128, 0><<<dim3(2048 / 128, 8192 / 128), 256>>>(
        memory, input_, PREV * BSZ, DIN, nullptr, W_kv, 2 * DIN,
        pk, pv, DIN, DIN, nullptr, 8192, 2 * DIN, DIN);

    // 2) q = input_ @ W_q
    tcgemm<128, 0><<<dim3(DIN / 128, (SEQ * BSZ) / 128), 256>>>(
        input_, input_, SEQ * BSZ, DIN, nullptr, W_q, DIN,
        pq, nullptr, DIN, DIN, nullptr, SEQ * BSZ, DIN, DIN);

    // 3) p = pos_embs @ W_p
    tcgemm<128, 0><<<dim3(DIN / 128, TOT / 128), 256>>>(
        pos, pos, TOT, DIN, nullptr, W_p, DIN,
        pp, nullptr, DIN, DIN, nullptr, TOT, DIN, DIN);

    // 4) content scores: (q+u) @ k^T per (b,h)
    tcgemm<128, 1><<<dim3(TOT / 128, SEQ / 128, BSZ * NH), 256>>>(
        pq, nullptr, 0, BSZ * DIN, u, pk, BSZ * DIN,
        pattn, nullptr, 0, TOT, nullptr, SEQ, TOT, HD);

    // 5) position scores: (q+v) @ p^T per (b,h)
    tcgemm<128, 2><<<dim3(TOT / 128, SEQ / 128, BSZ * NH), 256>>>(
        pq, nullptr, 0, BSZ * DIN, vvec, pp, DIN,
        ppos, nullptr, 0, TOT, nullptr, SEQ, TOT, HD);

    // 6) fused rel-shift + mask + scale + softmax (in place into pattn)
    softmax_fused<<<BSZ * NH * SEQ, 256>>>(pattn, ppos);

    // 7) awv = attn @ V per (b,h)
    tcgemm<64, 3><<<dim3(1, SEQ / 128, BSZ * NH), 256>>>(
        pattn, nullptr, 0, TOT, nullptr, pv, BSZ * DIN,
        pawv, nullptr, 0, BSZ * DIN, nullptr, SEQ, HD, TOT);

    // 8) out_pre = input_ + awv @ W_out
    tcgemm<128, 0><<<dim3(DIN / 128, (SEQ * BSZ) / 128), 256>>>(
        pawv, pawv, SEQ * BSZ, DIN, nullptr, W_out, DIN,
        pout, nullptr, DIN, DIN, input_, SEQ * BSZ, DIN, DIN);

    // 9) LayerNorm -> d_out
    ln_kernel<<<SEQ * BSZ, 256>>>(pout, gamma, beta, out);
}

// round 4
// speedup vs baseline: 3.7256x; 1.1099x over previous
#include <cuda_runtime.h>
#include <math.h>

#define SEQ  512
#define PREV 512
#define TOT  1024
#define BSZ  8
#define DIN  1024
#define NH   16
#define HD   64

// ---------------- scratch (static device globals; no allocations) ----------------
__device__ float g_q   [SEQ * BSZ * DIN];                 // 16 MB
__device__ float g_k   [TOT * BSZ * DIN];                 // 32 MB
__device__ float g_v   [TOT * BSZ * DIN];                 // 32 MB
__device__ float g_p   [TOT * DIN];                       //  4 MB
__device__ float g_awv [SEQ * BSZ * DIN];                 // 16 MB
__device__ float g_out [SEQ * BSZ * DIN];                 // 16 MB

__device__ __forceinline__ unsigned f2tf32(float x) {
    unsigned r;
    asm("cvt.rna.tf32.f32 %0, %1;" : "=r"(r) : "f"(x));
    return r;
}
__device__ __forceinline__ float tf(float x) { return __uint_as_float(f2tf32(x)); }

#define MMA_TF32(c, a, b)                                                      \
    asm volatile(                                                              \
        "mma.sync.aligned.m16n8k8.row.col.f32.tf32.tf32.f32 "                  \
        "{%0,%1,%2,%3},{%4,%5,%6,%7},{%8,%9},{%0,%1,%2,%3};"                   \
        : "+f"(c[0]), "+f"(c[1]), "+f"(c[2]), "+f"(c[3])                       \
        : "r"(a[0]), "r"(a[1]), "r"(a[2]), "r"(a[3]), "r"(b[0]), "r"(b[1]))

// ---------------- tensor-core tf32 GEMM (projections), unchanged from R3 --------
template<int BN, int MODE>
__global__ __launch_bounds__(256) void tcgemm(
    const float* __restrict__ A0, const float* __restrict__ A1, int M0, long lda,
    const float* __restrict__ bias,
    const float* __restrict__ B, long ldb,
    float* __restrict__ C, float* __restrict__ C1, int Nsplit, long ldc,
    const float* __restrict__ resid,
    int M, int N, int K)
{
    constexpr int BM   = 128;
    constexpr int BK   = 32;
    constexpr int ASTR = BK + 4;
    constexpr int BSTR = BN + 8;
    constexpr int MT   = 2;
    constexpr int NT   = BN / 16;

    __shared__ float As[BM * ASTR];
    __shared__ float Bs[BK * BSTR];

    const int tid  = threadIdx.x;
    const int wid  = tid >> 5, lane = tid & 31;
    const int gid  = lane >> 2, tig = lane & 3;
    const int warp_m = (wid & 3) * 32;
    const int warp_n = (wid >> 2) * (BN / 2);
    const int row0 = blockIdx.y * BM;
    const int col0 = blockIdx.x * BN;

    float c[MT][NT][4];
#pragma unroll
    for (int mt = 0; mt < MT; mt++)
#pragma unroll
        for (int nt = 0; nt < NT; nt++)
#pragma unroll
            for (int q = 0; q < 4; q++) c[mt][nt][q] = 0.f;

    for (int k0 = 0; k0 < K; k0 += BK) {
#pragma unroll
        for (int it = 0; it < (BM * (BK / 4)) / 256; it++) {
            const int f  = tid + it * 256;
            const int m  = f >> 3;
            const int kc = (f & 7) * 4;
            const int gm = row0 + m;
            const int gk = k0 + kc;
            const float* src = (gm < M0 ? A0 + (size_t)gm * lda
                                        : A1 + (size_t)(gm - M0) * lda) + gk;
            float4 v = *(const float4*)src;
            As[m * ASTR + kc + 0] = tf(v.x);
            As[m * ASTR + kc + 1] = tf(v.y);
            As[m * ASTR + kc + 2] = tf(v.z);
            As[m * ASTR + kc + 3] = tf(v.w);
        }
#pragma unroll
        for (int it = 0; it < (BK * BN / 4) / 256; it++) {
            const int f  = tid + it * 256;
            const int k  = f / (BN / 4);
            const int nc = (f % (BN / 4)) * 4;
            float4 v = *(const float4*)(B + (size_t)(k0 + k) * ldb + col0 + nc);
            float4 w;
            w.x = tf(v.x); w.y = tf(v.y); w.z = tf(v.z); w.w = tf(v.w);
            *(float4*)&Bs[k * BSTR + nc] = w;
        }
        __syncthreads();

#pragma unroll
        for (int ks = 0; ks < 4; ks++) {
            const int kk = ks * 8;
            unsigned a[MT][4], b[NT][2];
#pragma unroll
            for (int mt = 0; mt < MT; mt++) {
                const int m = warp_m + mt * 16 + gid;
                a[mt][0] = __float_as_uint(As[m * ASTR + kk + tig]);
                a[mt][1] = __float_as_uint(As[(m + 8) * ASTR + kk + tig]);
                a[mt][2] = __float_as_uint(As[m * ASTR + kk + tig + 4]);
                a[mt][3] = __float_as_uint(As[(m + 8) * ASTR + kk + tig + 4]);
            }
#pragma unroll
            for (int nt = 0; nt < NT; nt++) {
                const int n = warp_n + nt * 8 + gid;
                b[nt][0] = __float_as_uint(Bs[(kk + tig) * BSTR + n]);
                b[nt][1] = __float_as_uint(Bs[(kk + tig + 4) * BSTR + n]);
            }
#pragma unroll
            for (int mt = 0; mt < MT; mt++)
#pragma unroll
                for (int nt = 0; nt < NT; nt++)
                    MMA_TF32(c[mt][nt], a[mt], b[nt]);
        }
        __syncthreads();
    }

#pragma unroll
    for (int mt = 0; mt < MT; mt++) {
        const int r0 = row0 + warp_m + mt * 16 + gid;
#pragma unroll
        for (int nt = 0; nt < NT; nt++) {
            const int cb = col0 + warp_n + nt * 8 + 2 * tig;
#pragma unroll
            for (int half = 0; half < 2; half++) {
                const int r = r0 + half * 8;
#pragma unroll
                for (int e = 0; e < 2; e++) {
                    const int cc = cb + e;
                    float val = c[mt][nt][half * 2 + e];
                    if (resid) val += resid[(size_t)r * ldc + cc];
                    if (cc < Nsplit) C [(size_t)r * ldc + cc] = val;
                    else             C1[(size_t)r * ldc + cc - Nsplit] = val;
                }
            }
        }
    }
}

// ================= fused flash attention (scores + shift + mask + softmax + PV) ==
// Block: one (b,h), 64 query rows. 256 threads (8 warps: 2 warps m x 4 warps n).
// Smem strides: A-operands 68, B-operands 72, pos-stage 132.
extern __shared__ float fa_sm[];

__global__ __launch_bounds__(256, 1) void flash_attn(
    const float* __restrict__ q,  const float* __restrict__ kg,
    const float* __restrict__ vg, const float* __restrict__ pg,
    const float* __restrict__ u,  const float* __restrict__ vbias,
    float* __restrict__ awv)
{
    float* sQu = fa_sm;                  // 64 x 68
    float* sQv = sQu + 64 * 68;          // 64 x 68
    float* sK  = sQv + 64 * 68;          // 64 x 72   [j][d]
    float* sV  = sK  + 64 * 72;          // 64 x 72   [j][c]
    float* sP  = sV  + 64 * 72;          // 128 x 72  [r][d]
    float* sSp = sP  + 128 * 72;         // 64 x 132  pos scores stage
    float* sS  = sSp + 64 * 132;         // 64 x 68   scores -> probs
    float* sM  = sS  + 64 * 68;          // 64 running max
    float* sL  = sM  + 64;               // 64 running sum
    float* sSc = sL  + 64;               // 64 rescale factor

    const int tid = threadIdx.x;
    const int wid = tid >> 5, lane = tid & 31;
    const int gid = lane >> 2, tig = lane & 3;
    const int i0 = blockIdx.x * 64;
    const int bh = blockIdx.y;
    const int b = bh >> 4, h = bh & 15;

    const int wm  = (wid & 1) * 32;      // warp m offset
    const int wn  = (wid >> 1) * 16;     // warp n offset, 64-wide ops
    const int wn2 = (wid >> 1) * 32;     // warp n offset, 128-wide S_p

    // ---- load Q tile once; build Qu = q+u, Qv = q+v (tf32) ----
    {
        const float* qb = q + ((size_t)i0 * BSZ + b) * DIN + h * HD;
#pragma unroll
        for (int it = 0; it < 4; it++) {
            const int f = tid + it * 256;
            const int r = f >> 4, c = (f & 15) * 4;
            float4 x  = *(const float4*)(qb + (size_t)r * BSZ * DIN + c);
            float4 uu = *(const float4*)(u + h * HD + c);
            float4 vv = *(const float4*)(vbias + h * HD + c);
            sQu[r * 68 + c + 0] = tf(x.x + uu.x);
            sQu[r * 68 + c + 1] = tf(x.y + uu.y);
            sQu[r * 68 + c + 2] = tf(x.z + uu.z);
            sQu[r * 68 + c + 3] = tf(x.w + uu.w);
            sQv[r * 68 + c + 0] = tf(x.x + vv.x);
            sQv[r * 68 + c + 1] = tf(x.y + vv.y);
            sQv[r * 68 + c + 2] = tf(x.z + vv.z);
            sQv[r * 68 + c + 3] = tf(x.w + vv.w);
        }
    }
    if (tid < 64) { sM[tid] = -1e30f; sL[tid] = 0.f; }

    float o[2][2][4];
#pragma unroll
    for (int mt = 0; mt < 2; mt++)
#pragma unroll
        for (int nt = 0; nt < 2; nt++)
#pragma unroll
            for (int e = 0; e < 4; e++) o[mt][nt][e] = 0.f;

    const int nsteps = i0 / 64 + 9;      // covers j <= i0+63+512

    for (int s = 0; s < nsteps; s++) {
        const int j0 = s * 64;
        __syncthreads();

        // ---- load K_j, V_j (64x64) natural row-major ----
        {
            const float* kb = kg + ((size_t)j0 * BSZ + b) * DIN + h * HD;
            const float* vb = vg + ((size_t)j0 * BSZ + b) * DIN + h * HD;
#pragma unroll
            for (int it = 0; it < 4; it++) {
                const int f = tid + it * 256;
                const int r = f >> 4, c = (f & 15) * 4;
                float4 x = *(const float4*)(kb + (size_t)r * BSZ * DIN + c);
                float4 w;
                w.x = tf(x.x); w.y = tf(x.y); w.z = tf(x.z); w.w = tf(x.w);
                *(float4*)&sK[r * 72 + c] = w;
                float4 y = *(const float4*)(vb + (size_t)r * BSZ * DIN + c);
                float4 w2;
                w2.x = tf(y.x); w2.y = tf(y.y); w2.z = tf(y.z); w2.w = tf(y.w);
                *(float4*)&sV[r * 72 + c] = w2;
            }
        }
        // ---- load P window (128 rows, clamp at 1023) ----
        {
            const int rbase = j0 - i0 + 448;
#pragma unroll
            for (int it = 0; it < 8; it++) {
                const int f = tid + it * 256;
                const int r = f >> 4, c = (f & 15) * 4;
                int gr = rbase + r; if (gr > TOT - 1) gr = TOT - 1;
                float4 x = *(const float4*)(pg + (size_t)gr * DIN + h * HD + c);
                float4 w;
                w.x = tf(x.x); w.y = tf(x.y); w.z = tf(x.z); w.w = tf(x.w);
                *(float4*)&sP[r * 72 + c] = w;
            }
        }
        __syncthreads();

        // ---- S_p = Qv @ P^T  (64 x 128), warp tile 32x32 ----
        float cp[2][4][4];
#pragma unroll
        for (int mt = 0; mt < 2; mt++)
#pragma unroll
            for (int nt = 0; nt < 4; nt++)
#pragma unroll
                for (int e = 0; e < 4; e++) cp[mt][nt][e] = 0.f;
#pragma unroll
        for (int kk = 0; kk < 64; kk += 8) {
            unsigned a[2][4], bf[4][2];
#pragma unroll
            for (int mt = 0; mt < 2; mt++) {
                const int m = wm + mt * 16 + gid;
                a[mt][0] = __float_as_uint(sQv[m * 68 + kk + tig]);
                a[mt][1] = __float_as_uint(sQv[(m + 8) * 68 + kk + tig]);
                a[mt][2] = __float_as_uint(sQv[m * 68 + kk + tig + 4]);
                a[mt][3] = __float_as_uint(sQv[(m + 8) * 68 + kk + tig + 4]);
            }
#pragma unroll
            for (int nt = 0; nt < 4; nt++) {
                const int n = wn2 + nt * 8 + gid;
                bf[nt][0] = __float_as_uint(sP[n * 72 + kk + tig]);
                bf[nt][1] = __float_as_uint(sP[n * 72 + kk + tig + 4]);
            }
#pragma unroll
            for (int mt = 0; mt < 2; mt++)
#pragma unroll
                for (int nt = 0; nt < 4; nt++)
                    MMA_TF32(cp[mt][nt], a[mt], bf[nt]);
        }
        // stage S_p to smem
#pragma unroll
        for (int mt = 0; mt < 2; mt++)
#pragma unroll
            for (int nt = 0; nt < 4; nt++)
#pragma unroll
                for (int hf = 0; hf < 2; hf++) {
                    const int li = wm + mt * 16 + gid + 8 * hf;
                    const int col = wn2 + nt * 8 + 2 * tig;
                    float2 w = make_float2(cp[mt][nt][hf * 2], cp[mt][nt][hf * 2 + 1]);
                    *(float2*)&sSp[li * 132 + col] = w;
                }

        // ---- S_c = Qu @ K^T (64 x 64), warp tile 32x16 ----
        float cc[2][2][4];
#pragma unroll
        for (int mt = 0; mt < 2; mt++)
#pragma unroll
            for (int nt = 0; nt < 2; nt++)
#pragma unroll
                for (int e = 0; e < 4; e++) cc[mt][nt][e] = 0.f;
#pragma unroll
        for (int kk = 0; kk < 64; kk += 8) {
            unsigned a[2][4], bf[2][2];
#pragma unroll
            for (int mt = 0; mt < 2; mt++) {
                const int m = wm + mt * 16 + gid;
                a[mt][0] = __float_as_uint(sQu[m * 68 + kk + tig]);
                a[mt][1] = __float_as_uint(sQu[(m + 8) * 68 + kk + tig]);
                a[mt][2] = __float_as_uint(sQu[m * 68 + kk + tig + 4]);
                a[mt][3] = __float_as_uint(sQu[(m + 8) * 68 + kk + tig + 4]);
            }
#pragma unroll
            for (int nt = 0; nt < 2; nt++) {
                const int n = wn + nt * 8 + gid;
                bf[nt][0] = __float_as_uint(sK[n * 72 + kk + tig]);
                bf[nt][1] = __float_as_uint(sK[n * 72 + kk + tig + 4]);
            }
#pragma unroll
            for (int mt = 0; mt < 2; mt++)
#pragma unroll
                for (int nt = 0; nt < 2; nt++)
                    MMA_TF32(cc[mt][nt], a[mt], bf[nt]);
        }
        __syncthreads();   // sSp visible

        // ---- combine: S = (S_c + shift-gathered S_p) * scale, mask ----
#pragma unroll
        for (int mt = 0; mt < 2; mt++)
#pragma unroll
            for (int nt = 0; nt < 2; nt++)
#pragma unroll
                for (int hf = 0; hf < 2; hf++) {
                    const int li = wm + mt * 16 + gid + 8 * hf;
                    const int ljb = wn + nt * 8 + 2 * tig;
                    float2 w;
#pragma unroll
                    for (int e = 0; e < 2; e++) {
                        const int lj = ljb + e;
                        float val = (cc[mt][nt][hf * 2 + e]
                                     + sSp[li * 132 + lj + 63 - li]) * 0.125f;
                        const bool ok = (j0 + lj) <= (i0 + li + PREV);
                        (&w.x)[e] = ok ? val : -1e30f;
                    }
                    *(float2*)&sS[li * 68 + ljb] = w;
                }
        __syncthreads();

        // ---- online softmax: 4 threads per row, 16 cols each ----
        {
            const int row = tid >> 2, seg = tid & 3;
            float* rp = sS + row * 68 + seg * 16;
            float4 xv[4];
            float mx = -1e30f;
#pragma unroll
            for (int t = 0; t < 4; t++) {
                xv[t] = *(const float4*)(rp + t * 4);
                mx = fmaxf(mx, fmaxf(fmaxf(xv[t].x, xv[t].y), fmaxf(xv[t].z, xv[t].w)));
            }
            mx = fmaxf(mx, __shfl_xor_sync(0xffffffffu, mx, 1));
            mx = fmaxf(mx, __shfl_xor_sync(0xffffffffu, mx, 2));
            const float mold = sM[row];
            const float mnew = fmaxf(mold, mx);
            float ssum = 0.f;
#pragma unroll
            for (int t = 0; t < 4; t++) {
                float e0 = __expf(xv[t].x - mnew);
                float e1 = __expf(xv[t].y - mnew);
                float e2 = __expf(xv[t].z - mnew);
                float e3 = __expf(xv[t].w - mnew);
                ssum += (e0 + e1) + (e2 + e3);
                float4 w;
                w.x = tf(e0); w.y = tf(e1); w.z = tf(e2); w.w = tf(e3);
                *(float4*)(rp + t * 4) = w;
            }
            ssum += __shfl_xor_sync(0xffffffffu, ssum, 1);
            ssum += __shfl_xor_sync(0xffffffffu, ssum, 2);
            if (seg == 0) {
                const float sc = __expf(mold - mnew);
                sM[row]  = mnew;
                sSc[row] = sc;
                sL[row]  = sL[row] * sc + ssum;
            }
        }
        __syncthreads();

        // ---- rescale O, then O += P @ V (64x64x64), warp tile 32x16 ----
#pragma unroll
        for (int mt = 0; mt < 2; mt++) {
            const float sc0 = sSc[wm + mt * 16 + gid];
            const float sc1 = sSc[wm + mt * 16 + gid + 8];
#pragma unroll
            for (int nt = 0; nt < 2; nt++) {
                o[mt][nt][0] *= sc0; o[mt][nt][1] *= sc0;
                o[mt][nt][2] *= sc1; o[mt][nt][3] *= sc1;
            }
        }
#pragma unroll
        for (int kk = 0; kk < 64; kk += 8) {
            unsigned a[2][4], bf[2][2];
#pragma unroll
            for (int mt = 0; mt < 2; mt++) {
                const int m = wm + mt * 16 + gid;
                a[mt][0] = __float_as_uint(sS[m * 68 + kk + tig]);
                a[mt][1] = __float_as_uint(sS[(m + 8) * 68 + kk + tig]);
                a[mt][2] = __float_as_uint(sS[m * 68 + kk + tig + 4]);
                a[mt][3] = __float_as_uint(sS[(m + 8) * 68 + kk + tig + 4]);
            }
#pragma unroll
            for (int nt = 0; nt < 2; nt++) {
                const int n = wn + nt * 8 + gid;
                bf[nt][0] = __float_as_uint(sV[(kk + tig) * 72 + n]);
                bf[nt][1] = __float_as_uint(sV[(kk + tig + 4) * 72 + n]);
            }
#pragma unroll
            for (int mt = 0; mt < 2; mt++)
#pragma unroll
                for (int nt = 0; nt < 2; nt++)
                    MMA_TF32(o[mt][nt], a[mt], bf[nt]);
        }
    }

    // ---- write awv = O / l ----
#pragma unroll
    for (int mt = 0; mt < 2; mt++)
#pragma unroll
        for (int nt = 0; nt < 2; nt++)
#pragma unroll
            for (int hf = 0; hf < 2; hf++) {
                const int li = wm + mt * 16 + gid + 8 * hf;
                const int c  = wn + nt * 8 + 2 * tig;
                const float inv = 1.f / sL[li];
                float2 w = make_float2(o[mt][nt][hf * 2] * inv,
                                       o[mt][nt][hf * 2 + 1] * inv);
                *(float2*)&awv[((size_t)(i0 + li) * BSZ + b) * DIN + h * HD + c] = w;
            }
}

// ---------------- LayerNorm over last dim (1024), one block per row ------------
__global__ __launch_bounds__(256) void ln_kernel(
    const float* __restrict__ x, const float* __restrict__ gamma,
    const float* __restrict__ beta, float* __restrict__ out)
{
    const size_t row = blockIdx.x;
    const int tid = threadIdx.x;
    const float4 v = ((const float4*)(x + row * DIN))[tid];
    __shared__ float red[8];

    float s = v.x + v.y + v.z + v.w;
#pragma unroll
    for (int o = 16; o; o >>= 1) s += __shfl_xor_sync(0xffffffffu, s, o);
    if ((tid & 31) == 0) red[tid >> 5] = s;
    __syncthreads();
    s = red[0];
#pragma unroll
    for (int w = 1; w < 8; w++) s += red[w];
    const float mu = s * (1.0f / DIN);
    __syncthreads();

    const float d0 = v.x - mu, d1 = v.y - mu, d2 = v.z - mu, d3 = v.w - mu;
    float s2 = d0 * d0 + d1 * d1 + d2 * d2 + d3 * d3;
#pragma unroll
    for (int o = 16; o; o >>= 1) s2 += __shfl_xor_sync(0xffffffffu, s2, o);
    if ((tid & 31) == 0) red[tid >> 5] = s2;
    __syncthreads();
    s2 = red[0];
#pragma unroll
    for (int w = 1; w < 8; w++) s2 += red[w];
    const float inv = rsqrtf(s2 * (1.0f / DIN) + 1e-5f);

    const float4 g  = ((const float4*)gamma)[tid];
    const float4 bb = ((const float4*)beta)[tid];
    float4 o4;
    o4.x = d0 * inv * g.x + bb.x;
    o4.y = d1 * inv * g.y + bb.y;
    o4.z = d2 * inv * g.z + bb.z;
    o4.w = d3 * inv * g.w + bb.w;
    ((float4*)(out + row * DIN))[tid] = o4;
}

// ---------------- launch ---------------------------------------------------------
extern "C" void kernel_launch(void* const* d_in, const int* in_sizes, int n_in,
                              void* d_out, int out_size)
{
    const float* input_ = (const float*)d_in[0];
    const float* pos    = (const float*)d_in[1];
    const float* memory = (const float*)d_in[2];
    const float* u      = (const float*)d_in[3];
    const float* vvec   = (const float*)d_in[4];
    // d_in[5] = mask (analytic: j <= i + PREV)
    const float* W_kv   = (const float*)d_in[6];
    const float* W_q    = (const float*)d_in[7];
    const float* W_p    = (const float*)d_in[8];
    const float* W_out  = (const float*)d_in[9];
    const float* gamma  = (const float*)d_in[10];
    const float* beta   = (const float*)d_in[11];
    float* out = (float*)d_out;

    float *pq, *pk, *pv, *pp, *pawv, *pout;
    cudaGetSymbolAddress((void**)&pq,   g_q);
    cudaGetSymbolAddress((void**)&pk,   g_k);
    cudaGetSymbolAddress((void**)&pv,   g_v);
    cudaGetSymbolAddress((void**)&pp,   g_p);
    cudaGetSymbolAddress((void**)&pawv, g_awv);
    cudaGetSymbolAddress((void**)&pout, g_out);

    const int FA_SMEM = (64*68*2 + 64*72*2 + 128*72 + 64*132 + 64*68 + 192) * 4;
    cudaFuncSetAttribute(flash_attn,
                         cudaFuncAttributeMaxDynamicSharedMemorySize, FA_SMEM);

    // 1) kv = concat(memory, input_) @ W_kv  -> K | V split
    tcgemm<128, 0><<<dim3(2048 / 128, 8192 / 128), 256>>>(
        memory, input_, PREV * BSZ, DIN, nullptr, W_kv, 2 * DIN,
        pk, pv, DIN, DIN, nullptr, 8192, 2 * DIN, DIN);

    // 2) q = input_ @ W_q
    tcgemm<128, 0><<<dim3(DIN / 128, (SEQ * BSZ) / 128), 256>>>(
        input_, input_, SEQ * BSZ, DIN, nullptr, W_q, DIN,
        pq, nullptr, DIN, DIN, nullptr, SEQ * BSZ, DIN, DIN);

    // 3) p = pos_embs @ W_p
    tcgemm<128, 0><<<dim3(DIN / 128, TOT / 128), 256>>>(
        pos, pos, TOT, DIN, nullptr, W_p, DIN,
        pp, nullptr, DIN, DIN, nullptr, TOT, DIN, DIN);

    // 4) fused attention -> awv
    flash_attn<<<dim3(SEQ / 64, BSZ * NH), 256, FA_SMEM>>>(
        pq, pk, pv, pp, u, vvec, pawv);

    // 5) out_pre = input_ + awv @ W_out
    tcgemm<128, 0><<<dim3(DIN / 128, (SEQ * BSZ) / 128), 256>>>(
        pawv, pawv, SEQ * BSZ, DIN, nullptr, W_out, DIN,
        pout, nullptr, DIN, DIN, input_, SEQ * BSZ, DIN, DIN);

    // 6) LayerNorm -> d_out
    ln_kernel<<<SEQ * BSZ, 256>>>(pout, gamma, beta, out);
}

// round 5
// speedup vs baseline: 4.2429x; 1.1388x over previous
#include <cuda_runtime.h>
#include <math.h>

#define SEQ  512
#define PREV 512
#define TOT  1024
#define BSZ  8
#define DIN  1024
#define NH   16
#define HD   64

// ---------------- scratch (static device globals; no allocations) ----------------
__device__ float g_q   [SEQ * BSZ * DIN];                 // 16 MB
__device__ float g_k   [TOT * BSZ * DIN];                 // 32 MB
__device__ float g_v   [TOT * BSZ * DIN];                 // 32 MB
__device__ float g_p   [TOT * DIN];                       //  4 MB
__device__ float g_awv [SEQ * BSZ * DIN];                 // 16 MB
__device__ float g_out [SEQ * BSZ * DIN];                 // 16 MB

__device__ __forceinline__ unsigned f2tf32(float x) {
    unsigned r;
    asm("cvt.rna.tf32.f32 %0, %1;" : "=r"(r) : "f"(x));
    return r;
}
__device__ __forceinline__ float tf(float x) { return __uint_as_float(f2tf32(x)); }

__device__ __forceinline__ unsigned smem_u32(const void* p) {
    return (unsigned)__cvta_generic_to_shared(p);
}
__device__ __forceinline__ void cp16(unsigned dst, const void* src) {
    asm volatile("cp.async.cg.shared.global [%0], [%1], 16;" :: "r"(dst), "l"(src));
}
#define CP_COMMIT() asm volatile("cp.async.commit_group;")
#define CP_WAIT1()  asm volatile("cp.async.wait_group 1;")

#define MMA_TF32(c, a, b)                                                      \
    asm volatile(                                                              \
        "mma.sync.aligned.m16n8k8.row.col.f32.tf32.tf32.f32 "                  \
        "{%0,%1,%2,%3},{%4,%5,%6,%7},{%8,%9},{%0,%1,%2,%3};"                   \
        : "+f"(c[0]), "+f"(c[1]), "+f"(c[2]), "+f"(c[3])                       \
        : "r"(a[0]), "r"(a[1]), "r"(a[2]), "r"(a[3]), "r"(b[0]), "r"(b[1]))

// ============ tf32 projection GEMM, cp.async double-buffered =====================
// C = gather(A0 rows [0,M0) | A1) @ B (row-major), optional resid, col split.
// BM=128, BN=128, BK=32, 256 threads, 2 blocks/SM.
extern __shared__ float dyn_sm[];

__global__ __launch_bounds__(256, 2) void tcgemm(
    const float* __restrict__ A0, const float* __restrict__ A1, int M0, long lda,
    const float* __restrict__ B, long ldb,
    float* __restrict__ C, float* __restrict__ C1, int Nsplit, long ldc,
    const float* __restrict__ resid, int K)
{
    constexpr int ASTR = 36;   // 128 x 36 per buffer
    constexpr int BSTR = 136;  //  32 x 136 per buffer
    float* As = dyn_sm;                       // 2 buffers
    float* Bs = dyn_sm + 2 * 128 * ASTR;

    const int tid  = threadIdx.x;
    const int wid  = tid >> 5, lane = tid & 31;
    const int gid  = lane >> 2, tig = lane & 3;
    const int warp_m = (wid & 3) * 32;
    const int warp_n = (wid >> 2) * 64;
    const int row0 = blockIdx.y * 128;
    const int col0 = blockIdx.x * 128;

    float c[2][8][4];
#pragma unroll
    for (int mt = 0; mt < 2; mt++)
#pragma unroll
        for (int nt = 0; nt < 8; nt++)
#pragma unroll
            for (int q = 0; q < 4; q++) c[mt][nt][q] = 0.f;

    auto issue = [&](int k0, int buf) {
        float* Ad = As + buf * 128 * ASTR;
        float* Bd = Bs + buf * 32 * BSTR;
#pragma unroll
        for (int it = 0; it < 4; it++) {
            const int idx = tid + it * 256;
            const int m = idx >> 3, kc = (idx & 7) * 4;
            const int gm = row0 + m;
            const float* src = (gm < M0 ? A0 + (size_t)gm * lda
                                        : A1 + (size_t)(gm - M0) * lda) + k0 + kc;
            cp16(smem_u32(Ad + m * ASTR + kc), src);
        }
#pragma unroll
        for (int it = 0; it < 4; it++) {
            const int idx = tid + it * 256;
            const int k = idx >> 5, nc = (idx & 31) * 4;
            cp16(smem_u32(Bd + k * BSTR + nc),
                 B + (size_t)(k0 + k) * ldb + col0 + nc);
        }
    };

    issue(0, 0); CP_COMMIT();
    const int nk = K / 32;

    for (int kt = 0; kt < nk; kt++) {
        if (kt + 1 < nk) issue((kt + 1) * 32, (kt + 1) & 1);
        CP_COMMIT();
        CP_WAIT1();
        __syncthreads();

        const float* Ab = As + (kt & 1) * 128 * ASTR;
        const float* Bb = Bs + (kt & 1) * 32 * BSTR;
#pragma unroll
        for (int ks = 0; ks < 4; ks++) {
            const int kk = ks * 8;
            unsigned a[2][4], b[8][2];
#pragma unroll
            for (int mt = 0; mt < 2; mt++) {
                const int m = warp_m + mt * 16 + gid;
                a[mt][0] = f2tf32(Ab[m * ASTR + kk + tig]);
                a[mt][1] = f2tf32(Ab[(m + 8) * ASTR + kk + tig]);
                a[mt][2] = f2tf32(Ab[m * ASTR + kk + tig + 4]);
                a[mt][3] = f2tf32(Ab[(m + 8) * ASTR + kk + tig + 4]);
            }
#pragma unroll
            for (int nt = 0; nt < 8; nt++) {
                const int n = warp_n + nt * 8 + gid;
                b[nt][0] = f2tf32(Bb[(kk + tig) * BSTR + n]);
                b[nt][1] = f2tf32(Bb[(kk + tig + 4) * BSTR + n]);
            }
#pragma unroll
            for (int mt = 0; mt < 2; mt++)
#pragma unroll
                for (int nt = 0; nt < 8; nt++)
                    MMA_TF32(c[mt][nt], a[mt], b[nt]);
        }
        __syncthreads();
    }

#pragma unroll
    for (int mt = 0; mt < 2; mt++) {
        const int r0 = row0 + warp_m + mt * 16 + gid;
#pragma unroll
        for (int nt = 0; nt < 8; nt++) {
            const int cb = col0 + warp_n + nt * 8 + 2 * tig;
#pragma unroll
            for (int half = 0; half < 2; half++) {
                const int r = r0 + half * 8;
#pragma unroll
                for (int e = 0; e < 2; e++) {
                    const int cc = cb + e;
                    float val = c[mt][nt][half * 2 + e];
                    if (resid) val += resid[(size_t)r * ldc + cc];
                    if (cc < Nsplit) C [(size_t)r * ldc + cc] = val;
                    else             C1[(size_t)r * ldc + cc - Nsplit] = val;
                }
            }
        }
    }
}

// ============ fused flash attention, cp.async double-buffered ====================
// Block: one (b,h), 64 query rows. 256 threads (2 m-warps x 4 n-warps).
__global__ __launch_bounds__(256, 1) void flash_attn(
    const float* __restrict__ q,  const float* __restrict__ kg,
    const float* __restrict__ vg, const float* __restrict__ pg,
    const float* __restrict__ u,  const float* __restrict__ vbias,
    float* __restrict__ awv)
{
    float* sQu = dyn_sm;                 // 64 x 68 (tf32)
    float* sQv = sQu + 64 * 68;          // 64 x 68 (tf32)
    float* sK  = sQv + 64 * 68;          // 2 x (64 x 68)  raw fp32
    float* sV  = sK  + 2 * 64 * 68;      // 2 x (64 x 72)  raw fp32
    float* sP  = sV  + 2 * 64 * 72;      // 2 x (128 x 68) raw fp32
    float* sSp = sP  + 2 * 128 * 68;     // 64 x 132
    float* sS  = sSp + 64 * 132;         // 64 x 68 (tf32 probs)
    float* sM  = sS  + 64 * 68;
    float* sL  = sM  + 64;
    float* sSc = sL  + 64;

    const int tid = threadIdx.x;
    const int wid = tid >> 5, lane = tid & 31;
    const int gid = lane >> 2, tig = lane & 3;
    const int i0 = (int)(gridDim.x - 1 - blockIdx.x) * 64;   // heavy tiles first
    const int bh = blockIdx.y;
    const int b = bh >> 4, h = bh & 15;

    const int wm  = (wid & 1) * 32;
    const int wn  = (wid >> 1) * 16;
    const int wn2 = (wid >> 1) * 32;

    const int nsteps = i0 / 64 + 9;

    auto issue_step = [&](int sn) {
        const int j0n = sn * 64;
        float* Kd = sK + (sn & 1) * (64 * 68);
        float* Vd = sV + (sn & 1) * (64 * 72);
        float* Pd = sP + (sn & 1) * (128 * 68);
        const float* kb = kg + ((size_t)j0n * BSZ + b) * DIN + h * HD;
        const float* vb = vg + ((size_t)j0n * BSZ + b) * DIN + h * HD;
#pragma unroll
        for (int it = 0; it < 4; it++) {
            const int f = tid + it * 256;
            const int r = f >> 4, c = (f & 15) * 4;
            cp16(smem_u32(Kd + r * 68 + c), kb + (size_t)r * BSZ * DIN + c);
            cp16(smem_u32(Vd + r * 72 + c), vb + (size_t)r * BSZ * DIN + c);
        }
        const int rbase = j0n - i0 + 448;
#pragma unroll
        for (int it = 0; it < 8; it++) {
            const int f = tid + it * 256;
            const int r = f >> 4, c = (f & 15) * 4;
            int gr = rbase + r; if (gr > TOT - 1) gr = TOT - 1;
            cp16(smem_u32(Pd + r * 68 + c), pg + (size_t)gr * DIN + h * HD + c);
        }
    };

    issue_step(0); CP_COMMIT();

    // ---- build Qu = tf32(q+u), Qv = tf32(q+v) (overlaps with prefetch) ----
    {
        const float* qb = q + ((size_t)i0 * BSZ + b) * DIN + h * HD;
#pragma unroll
        for (int it = 0; it < 4; it++) {
            const int f = tid + it * 256;
            const int r = f >> 4, c = (f & 15) * 4;
            float4 x  = *(const float4*)(qb + (size_t)r * BSZ * DIN + c);
            float4 uu = *(const float4*)(u + h * HD + c);
            float4 vv = *(const float4*)(vbias + h * HD + c);
            sQu[r * 68 + c + 0] = tf(x.x + uu.x);
            sQu[r * 68 + c + 1] = tf(x.y + uu.y);
            sQu[r * 68 + c + 2] = tf(x.z + uu.z);
            sQu[r * 68 + c + 3] = tf(x.w + uu.w);
            sQv[r * 68 + c + 0] = tf(x.x + vv.x);
            sQv[r * 68 + c + 1] = tf(x.y + vv.y);
            sQv[r * 68 + c + 2] = tf(x.z + vv.z);
            sQv[r * 68 + c + 3] = tf(x.w + vv.w);
        }
    }
    if (tid < 64) { sM[tid] = -1e30f; sL[tid] = 0.f; }

    float o[2][2][4];
#pragma unroll
    for (int mt = 0; mt < 2; mt++)
#pragma unroll
        for (int nt = 0; nt < 2; nt++)
#pragma unroll
            for (int e = 0; e < 4; e++) o[mt][nt][e] = 0.f;

    for (int s = 0; s < nsteps; s++) {
        const int j0 = s * 64;
        if (s + 1 < nsteps) issue_step(s + 1);
        CP_COMMIT();
        CP_WAIT1();
        __syncthreads();

        const float* Kb = sK + (s & 1) * (64 * 68);
        const float* Vb = sV + (s & 1) * (64 * 72);
        const float* Pb = sP + (s & 1) * (128 * 68);

        // ---- S_p = Qv @ P^T (64 x 128) ----
        float cp[2][4][4];
#pragma unroll
        for (int mt = 0; mt < 2; mt++)
#pragma unroll
            for (int nt = 0; nt < 4; nt++)
#pragma unroll
                for (int e = 0; e < 4; e++) cp[mt][nt][e] = 0.f;
#pragma unroll
        for (int kk = 0; kk < 64; kk += 8) {
            unsigned a[2][4], bf[4][2];
#pragma unroll
            for (int mt = 0; mt < 2; mt++) {
                const int m = wm + mt * 16 + gid;
                a[mt][0] = __float_as_uint(sQv[m * 68 + kk + tig]);
                a[mt][1] = __float_as_uint(sQv[(m + 8) * 68 + kk + tig]);
                a[mt][2] = __float_as_uint(sQv[m * 68 + kk + tig + 4]);
                a[mt][3] = __float_as_uint(sQv[(m + 8) * 68 + kk + tig + 4]);
            }
#pragma unroll
            for (int nt = 0; nt < 4; nt++) {
                const int n = wn2 + nt * 8 + gid;
                bf[nt][0] = f2tf32(Pb[n * 68 + kk + tig]);
                bf[nt][1] = f2tf32(Pb[n * 68 + kk + tig + 4]);
            }
#pragma unroll
            for (int mt = 0; mt < 2; mt++)
#pragma unroll
                for (int nt = 0; nt < 4; nt++)
                    MMA_TF32(cp[mt][nt], a[mt], bf[nt]);
        }
#pragma unroll
        for (int mt = 0; mt < 2; mt++)
#pragma unroll
            for (int nt = 0; nt < 4; nt++)
#pragma unroll
                for (int hf = 0; hf < 2; hf++) {
                    const int li = wm + mt * 16 + gid + 8 * hf;
                    const int col = wn2 + nt * 8 + 2 * tig;
                    float2 w = make_float2(cp[mt][nt][hf * 2], cp[mt][nt][hf * 2 + 1]);
                    *(float2*)&sSp[li * 132 + col] = w;
                }

        // ---- S_c = Qu @ K^T (64 x 64) ----
        float cc[2][2][4];
#pragma unroll
        for (int mt = 0; mt < 2; mt++)
#pragma unroll
            for (int nt = 0; nt < 2; nt++)
#pragma unroll
                for (int e = 0; e < 4; e++) cc[mt][nt][e] = 0.f;
#pragma unroll
        for (int kk = 0; kk < 64; kk += 8) {
            unsigned a[2][4], bf[2][2];
#pragma unroll
            for (int mt = 0; mt < 2; mt++) {
                const int m = wm + mt * 16 + gid;
                a[mt][0] = __float_as_uint(sQu[m * 68 + kk + tig]);
                a[mt][1] = __float_as_uint(sQu[(m + 8) * 68 + kk + tig]);
                a[mt][2] = __float_as_uint(sQu[m * 68 + kk + tig + 4]);
                a[mt][3] = __float_as_uint(sQu[(m + 8) * 68 + kk + tig + 4]);
            }
#pragma unroll
            for (int nt = 0; nt < 2; nt++) {
                const int n = wn + nt * 8 + gid;
                bf[nt][0] = f2tf32(Kb[n * 68 + kk + tig]);
                bf[nt][1] = f2tf32(Kb[n * 68 + kk + tig + 4]);
            }
#pragma unroll
            for (int mt = 0; mt < 2; mt++)
#pragma unroll
                for (int nt = 0; nt < 2; nt++)
                    MMA_TF32(cc[mt][nt], a[mt], bf[nt]);
        }
        __syncthreads();   // sSp visible

        // ---- combine: S = (S_c + gathered S_p) * scale, mask ----
#pragma unroll
        for (int mt = 0; mt < 2; mt++)
#pragma unroll
            for (int nt = 0; nt < 2; nt++)
#pragma unroll
                for (int hf = 0; hf < 2; hf++) {
                    const int li = wm + mt * 16 + gid + 8 * hf;
                    const int ljb = wn + nt * 8 + 2 * tig;
                    float2 w;
#pragma unroll
                    for (int e = 0; e < 2; e++) {
                        const int lj = ljb + e;
                        float val = (cc[mt][nt][hf * 2 + e]
                                     + sSp[li * 132 + lj + 63 - li]) * 0.125f;
                        const bool ok = (j0 + lj) <= (i0 + li + PREV);
                        (&w.x)[e] = ok ? val : -1e30f;
                    }
                    *(float2*)&sS[li * 68 + ljb] = w;
                }
        __syncthreads();

        // ---- online softmax: 4 threads per row ----
        {
            const int row = tid >> 2, seg = tid & 3;
            float* rp = sS + row * 68 + seg * 16;
            float4 xv[4];
            float mx = -1e30f;
#pragma unroll
            for (int t = 0; t < 4; t++) {
                xv[t] = *(const float4*)(rp + t * 4);
                mx = fmaxf(mx, fmaxf(fmaxf(xv[t].x, xv[t].y), fmaxf(xv[t].z, xv[t].w)));
            }
            mx = fmaxf(mx, __shfl_xor_sync(0xffffffffu, mx, 1));
            mx = fmaxf(mx, __shfl_xor_sync(0xffffffffu, mx, 2));
            const float mold = sM[row];
            const float mnew = fmaxf(mold, mx);
            float ssum = 0.f;
#pragma unroll
            for (int t = 0; t < 4; t++) {
                float e0 = __expf(xv[t].x - mnew);
                float e1 = __expf(xv[t].y - mnew);
                float e2 = __expf(xv[t].z - mnew);
                float e3 = __expf(xv[t].w - mnew);
                ssum += (e0 + e1) + (e2 + e3);
                float4 w;
                w.x = tf(e0); w.y = tf(e1); w.z = tf(e2); w.w = tf(e3);
                *(float4*)(rp + t * 4) = w;
            }
            ssum += __shfl_xor_sync(0xffffffffu, ssum, 1);
            ssum += __shfl_xor_sync(0xffffffffu, ssum, 2);
            if (seg == 0) {
                const float sc = __expf(mold - mnew);
                sM[row]  = mnew;
                sSc[row] = sc;
                sL[row]  = sL[row] * sc + ssum;
            }
        }
        __syncthreads();

        // ---- rescale O, then O += P @ V ----
#pragma unroll
        for (int mt = 0; mt < 2; mt++) {
            const float sc0 = sSc[wm + mt * 16 + gid];
            const float sc1 = sSc[wm + mt * 16 + gid + 8];
#pragma unroll
            for (int nt = 0; nt < 2; nt++) {
                o[mt][nt][0] *= sc0; o[mt][nt][1] *= sc0;
                o[mt][nt][2] *= sc1; o[mt][nt][3] *= sc1;
            }
        }
#pragma unroll
        for (int kk = 0; kk < 64; kk += 8) {
            unsigned a[2][4], bf[2][2];
#pragma unroll
            for (int mt = 0; mt < 2; mt++) {
                const int m = wm + mt * 16 + gid;
                a[mt][0] = __float_as_uint(sS[m * 68 + kk + tig]);
                a[mt][1] = __float_as_uint(sS[(m + 8) * 68 + kk + tig]);
                a[mt][2] = __float_as_uint(sS[m * 68 + kk + tig + 4]);
                a[mt][3] = __float_as_uint(sS[(m + 8) * 68 + kk + tig + 4]);
            }
#pragma unroll
            for (int nt = 0; nt < 2; nt++) {
                const int n = wn + nt * 8 + gid;
                bf[nt][0] = f2tf32(Vb[(kk + tig) * 72 + n]);
                bf[nt][1] = f2tf32(Vb[(kk + tig + 4) * 72 + n]);
            }
#pragma unroll
            for (int mt = 0; mt < 2; mt++)
#pragma unroll
                for (int nt = 0; nt < 2; nt++)
                    MMA_TF32(o[mt][nt], a[mt], bf[nt]);
        }
        __syncthreads();   // protect buffers before next-iter prefetch
    }

    // ---- write awv = O / l ----
#pragma unroll
    for (int mt = 0; mt < 2; mt++)
#pragma unroll
        for (int nt = 0; nt < 2; nt++)
#pragma unroll
            for (int hf = 0; hf < 2; hf++) {
                const int li = wm + mt * 16 + gid + 8 * hf;
                const int c  = wn + nt * 8 + 2 * tig;
                const float inv = 1.f / sL[li];
                float2 w = make_float2(o[mt][nt][hf * 2] * inv,
                                       o[mt][nt][hf * 2 + 1] * inv);
                *(float2*)&awv[((size_t)(i0 + li) * BSZ + b) * DIN + h * HD + c] = w;
            }
}

// ---------------- LayerNorm over last dim (1024), one block per row ------------
__global__ __launch_bounds__(256) void ln_kernel(
    const float* __restrict__ x, const float* __restrict__ gamma,
    const float* __restrict__ beta, float* __restrict__ out)
{
    const size_t row = blockIdx.x;
    const int tid = threadIdx.x;
    const float4 v = ((const float4*)(x + row * DIN))[tid];
    __shared__ float red[8];

    float s = v.x + v.y + v.z + v.w;
#pragma unroll
    for (int o = 16; o; o >>= 1) s += __shfl_xor_sync(0xffffffffu, s, o);
    if ((tid & 31) == 0) red[tid >> 5] = s;
    __syncthreads();
    s = red[0];
#pragma unroll
    for (int w = 1; w < 8; w++) s += red[w];
    const float mu = s * (1.0f / DIN);
    __syncthreads();

    const float d0 = v.x - mu, d1 = v.y - mu, d2 = v.z - mu, d3 = v.w - mu;
    float s2 = d0 * d0 + d1 * d1 + d2 * d2 + d3 * d3;
#pragma unroll
    for (int o = 16; o; o >>= 1) s2 += __shfl_xor_sync(0xffffffffu, s2, o);
    if ((tid & 31) == 0) red[tid >> 5] = s2;
    __syncthreads();
    s2 = red[0];
#pragma unroll
    for (int w = 1; w < 8; w++) s2 += red[w];
    const float inv = rsqrtf(s2 * (1.0f / DIN) + 1e-5f);

    const float4 g  = ((const float4*)gamma)[tid];
    const float4 bb = ((const float4*)beta)[tid];
    float4 o4;
    o4.x = d0 * inv * g.x + bb.x;
    o4.y = d1 * inv * g.y + bb.y;
    o4.z = d2 * inv * g.z + bb.z;
    o4.w = d3 * inv * g.w + bb.w;
    ((float4*)(out + row * DIN))[tid] = o4;
}

// ---------------- launch ---------------------------------------------------------
extern "C" void kernel_launch(void* const* d_in, const int* in_sizes, int n_in,
                              void* d_out, int out_size)
{
    const float* input_ = (const float*)d_in[0];
    const float* pos    = (const float*)d_in[1];
    const float* memory = (const float*)d_in[2];
    const float* u      = (const float*)d_in[3];
    const float* vvec   = (const float*)d_in[4];
    // d_in[5] = mask (analytic: j <= i + PREV)
    const float* W_kv   = (const float*)d_in[6];
    const float* W_q    = (const float*)d_in[7];
    const float* W_p    = (const float*)d_in[8];
    const float* W_out  = (const float*)d_in[9];
    const float* gamma  = (const float*)d_in[10];
    const float* beta   = (const float*)d_in[11];
    float* out = (float*)d_out;

    float *pq, *pk, *pv, *pp, *pawv, *pout;
    cudaGetSymbolAddress((void**)&pq,   g_q);
    cudaGetSymbolAddress((void**)&pk,   g_k);
    cudaGetSymbolAddress((void**)&pv,   g_v);
    cudaGetSymbolAddress((void**)&pp,   g_p);
    cudaGetSymbolAddress((void**)&pawv, g_awv);
    cudaGetSymbolAddress((void**)&pout, g_out);

    const int GEMM_SMEM = (2 * 128 * 36 + 2 * 32 * 136) * 4;      // 71680 B
    const int FA_SMEM   = (64*68*2 + 2*64*68 + 2*64*72 + 2*128*68
                           + 64*132 + 64*68 + 192) * 4;           // 228096 B
    cudaFuncSetAttribute(tcgemm,
                         cudaFuncAttributeMaxDynamicSharedMemorySize, GEMM_SMEM);
    cudaFuncSetAttribute(flash_attn,
                         cudaFuncAttributeMaxDynamicSharedMemorySize, FA_SMEM);

    // 1) kv = concat(memory, input_) @ W_kv  -> K | V split
    tcgemm<<<dim3(16, 64), 256, GEMM_SMEM>>>(
        memory, input_, PREV * BSZ, DIN, W_kv, 2 * DIN,
        pk, pv, DIN, DIN, nullptr, DIN);

    // 2) q = input_ @ W_q
    tcgemm<<<dim3(8, 32), 256, GEMM_SMEM>>>(
        input_, input_, 1 << 30, DIN, W_q, DIN,
        pq, nullptr, DIN, DIN, nullptr, DIN);

    // 3) p = pos_embs @ W_p
    tcgemm<<<dim3(8, 8), 256, GEMM_SMEM>>>(
        pos, pos, 1 << 30, DIN, W_p, DIN,
        pp, nullptr, DIN, DIN, nullptr, DIN);

    // 4) fused attention -> awv
    flash_attn<<<dim3(SEQ / 64, BSZ * NH), 256, FA_SMEM>>>(
        pq, pk, pv, pp, u, vvec, pawv);

    // 5) out_pre = input_ + awv @ W_out
    tcgemm<<<dim3(8, 32), 256, GEMM_SMEM>>>(
        pawv, pawv, 1 << 30, DIN, W_out, DIN,
        pout, nullptr, DIN, DIN, input_, DIN);

    // 6) LayerNorm -> d_out
    ln_kernel<<<SEQ * BSZ, 256>>>(pout, gamma, beta, out);
}

// round 6
// speedup vs baseline: 7.1225x; 1.6787x over previous
#include <cuda_runtime.h>
#include <cuda_fp16.h>
#include <math.h>

#define SEQ  512
#define PREV 512
#define TOT  1024
#define BSZ  8
#define DIN  1024
#define NH   16
#define HD   64

// ---------------- scratch (static device globals; no allocations) ----------------
__device__ __half g_in16 [SEQ * BSZ * DIN];
__device__ __half g_mem16[PREV * BSZ * DIN];
__device__ __half g_pos16[TOT * DIN];
__device__ __half g_wkv16[DIN * 2 * DIN];
__device__ __half g_wq16 [DIN * DIN];
__device__ __half g_wp16 [DIN * DIN];
__device__ __half g_wo16 [DIN * DIN];
__device__ __half g_kh [TOT * BSZ * DIN];
__device__ __half g_vh [TOT * BSZ * DIN];
__device__ __half g_ph [TOT * DIN];
__device__ __half g_qu [SEQ * BSZ * DIN];
__device__ __half g_qv [SEQ * BSZ * DIN];
__device__ __half g_awv[SEQ * BSZ * DIN];
__device__ float  g_out[SEQ * BSZ * DIN];

__device__ __forceinline__ unsigned smem_u32(const void* p) {
    return (unsigned)__cvta_generic_to_shared(p);
}
__device__ __forceinline__ void cp16(unsigned dst, const void* src) {
    asm volatile("cp.async.cg.shared.global [%0], [%1], 16;" :: "r"(dst), "l"(src));
}
#define CP_COMMIT() asm volatile("cp.async.commit_group;")
#define CP_WAIT1()  asm volatile("cp.async.wait_group 1;")

#define MMA_F16(c, a, b)                                                       \
    asm volatile(                                                              \
        "mma.sync.aligned.m16n8k16.row.col.f32.f16.f16.f32 "                   \
        "{%0,%1,%2,%3},{%4,%5,%6,%7},{%8,%9},{%0,%1,%2,%3};"                   \
        : "+f"(c[0]), "+f"(c[1]), "+f"(c[2]), "+f"(c[3])                       \
        : "r"(a[0]), "r"(a[1]), "r"(a[2]), "r"(a[3]), "r"(b[0]), "r"(b[1]))

__device__ __forceinline__ void ldmx4t(unsigned& r0, unsigned& r1,
                                       unsigned& r2, unsigned& r3, unsigned a) {
    asm volatile("ldmatrix.sync.aligned.m8n8.x4.trans.shared.b16 "
                 "{%0,%1,%2,%3}, [%4];"
                 : "=r"(r0), "=r"(r1), "=r"(r2), "=r"(r3) : "r"(a));
}

// ---------------- fp32 -> fp16 converter -----------------------------------------
__global__ void cvt_kernel(const float4* __restrict__ in,
                           __half2* __restrict__ out, int n4)
{
    int i = blockIdx.x * blockDim.x + threadIdx.x;
    if (i >= n4) return;
    float4 v = in[i];
    out[2 * i]     = __floats2half2_rn(v.x, v.y);
    out[2 * i + 1] = __floats2half2_rn(v.z, v.w);
}

// ============ fp16 GEMM, BK=64, cp.async double-buffered, 2 blocks/SM ============
// C = gather(A0 rows [0,M0) | A1) @ B  (B row-major [K][N] fp16).
// EPI 0: fp32 out (+resid). EPI 1: half split at col 1024 -> O0|O1.
// EPI 2: half qu=val+bu, qv=val+bv -> O0,O1. EPI 3: half plain -> O0.
extern __shared__ char dsm[];

template<int EPI>
__global__ __launch_bounds__(256, 2) void tcgemm_h(
    const __half* __restrict__ A0, const __half* __restrict__ A1, int M0, long lda,
    const __half* __restrict__ B, long ldb,
    void* __restrict__ O0, void* __restrict__ O1, long ldc,
    const float* __restrict__ resid,
    const float* __restrict__ bu, const float* __restrict__ bv, int K)
{
    // A: 128 x 64 half, row stride 144B. B: 64 x 128 half, row stride 272B.
    const int tid  = threadIdx.x;
    const int lane = tid & 31, wid = tid >> 5;
    const int gid  = lane >> 2, tig = lane & 3;
    const int warp_m = (wid & 3) * 32;
    const int warp_n = (wid >> 2) * 64;
    const int row0 = blockIdx.y * 128;
    const int col0 = blockIdx.x * 128;

    char* As = dsm;                 // 2 x 18432
    char* Bs = dsm + 2 * 18432;     // 2 x 17408

    float c[2][8][4];
#pragma unroll
    for (int mt = 0; mt < 2; mt++)
#pragma unroll
        for (int nt = 0; nt < 8; nt++)
#pragma unroll
            for (int q = 0; q < 4; q++) c[mt][nt][q] = 0.f;

    auto issue = [&](int k0, int buf) {
        unsigned ab = smem_u32(As + buf * 18432);
        unsigned bb = smem_u32(Bs + buf * 17408);
#pragma unroll
        for (int it = 0; it < 4; it++) {
            const int f = tid + it * 256;
            const int r = f >> 3, u = f & 7;
            const int gm = row0 + r;
            const __half* src = (gm < M0 ? A0 + (size_t)gm * lda
                                         : A1 + (size_t)(gm - M0) * lda) + k0 + u * 8;
            cp16(ab + r * 144 + u * 16, src);
        }
#pragma unroll
        for (int it = 0; it < 4; it++) {
            const int f = tid + it * 256;
            const int k = f >> 4, u = f & 15;
            cp16(bb + k * 272 + u * 16, B + (size_t)(k0 + k) * ldb + col0 + u * 8);
        }
    };

    issue(0, 0); CP_COMMIT();
    const int nk = K / 64;
    const int lrow = (lane & 7) + ((lane >> 3) & 1) * 8;
    const int lcol = ((lane >> 4) & 1) * 8;

    for (int kt = 0; kt < nk; kt++) {
        if (kt + 1 < nk) issue((kt + 1) * 64, (kt + 1) & 1);
        CP_COMMIT();
        CP_WAIT1();
        __syncthreads();

        const unsigned* Au = (const unsigned*)(As + (kt & 1) * 18432);
        const unsigned  bb = smem_u32(Bs + (kt & 1) * 17408);
#pragma unroll
        for (int kk = 0; kk < 64; kk += 16) {
            unsigned a[2][4];
#pragma unroll
            for (int mt = 0; mt < 2; mt++) {
                const int m = warp_m + mt * 16 + gid;
                a[mt][0] = Au[m * 36 + kk / 2 + tig];
                a[mt][1] = Au[(m + 8) * 36 + kk / 2 + tig];
                a[mt][2] = Au[m * 36 + kk / 2 + tig + 4];
                a[mt][3] = Au[(m + 8) * 36 + kk / 2 + tig + 4];
            }
#pragma unroll
            for (int p = 0; p < 4; p++) {
                unsigned r0, r1, r2, r3;
                ldmx4t(r0, r1, r2, r3,
                       bb + (kk + lrow) * 272 + (warp_n + p * 16 + lcol) * 2);
                unsigned b0[2] = {r0, r1}, b1[2] = {r2, r3};
#pragma unroll
                for (int mt = 0; mt < 2; mt++) {
                    MMA_F16(c[mt][2 * p],     a[mt], b0);
                    MMA_F16(c[mt][2 * p + 1], a[mt], b1);
                }
            }
        }
        __syncthreads();
    }

#pragma unroll
    for (int mt = 0; mt < 2; mt++) {
#pragma unroll
        for (int nt = 0; nt < 8; nt++) {
            const int cb = col0 + warp_n + nt * 8 + 2 * tig;
#pragma unroll
            for (int hf = 0; hf < 2; hf++) {
                const int r = row0 + warp_m + mt * 16 + gid + 8 * hf;
                float v0 = c[mt][nt][hf * 2], v1 = c[mt][nt][hf * 2 + 1];
                if (EPI == 0) {
                    if (resid) {
                        v0 += resid[(size_t)r * ldc + cb];
                        v1 += resid[(size_t)r * ldc + cb + 1];
                    }
                    ((float*)O0)[(size_t)r * ldc + cb]     = v0;
                    ((float*)O0)[(size_t)r * ldc + cb + 1] = v1;
                } else if (EPI == 1) {
                    __half2 h = __floats2half2_rn(v0, v1);
                    if (cb < DIN)
                        *(__half2*)((__half*)O0 + (size_t)r * DIN + cb) = h;
                    else
                        *(__half2*)((__half*)O1 + (size_t)r * DIN + cb - DIN) = h;
                } else if (EPI == 2) {
                    __half2 hu = __floats2half2_rn(v0 + bu[cb], v1 + bu[cb + 1]);
                    __half2 hv = __floats2half2_rn(v0 + bv[cb], v1 + bv[cb + 1]);
                    *(__half2*)((__half*)O0 + (size_t)r * ldc + cb) = hu;
                    *(__half2*)((__half*)O1 + (size_t)r * ldc + cb) = hv;
                } else {
                    *(__half2*)((__half*)O0 + (size_t)r * ldc + cb) =
                        __floats2half2_rn(v0, v1);
                }
            }
        }
    }
}

// ============ fused fp16 flash attention =========================================
// Block: one (b,h), 64 q-rows, 256 threads (2 m-warps x 4 n-warps).
// smem byte layout (total 137728):
//  sQu 0 (9216) | sQv 9216 | sK 18432 (2x9216) | sV 36864 (2x9216)
//  sP 55296 (2x18432) | sSp 92160 (64x132 f32) | sS 125952 (9216)
//  sRed 135168 (4x64 f32) | sRedS 136192 | sM 137216 | sL 137472
__global__ __launch_bounds__(256, 1) void flash_attn(
    const __half* __restrict__ qu, const __half* __restrict__ qv,
    const __half* __restrict__ kg, const __half* __restrict__ vg,
    const __half* __restrict__ pg, __half* __restrict__ awv)
{
    char* base = dsm;
    __half* sQu = (__half*)(base);
    __half* sQv = (__half*)(base + 9216);
    char*   sKb = base + 18432;
    char*   sVb = base + 36864;
    char*   sPb = base + 55296;
    float*  sSp = (float*)(base + 92160);
    __half* sS  = (__half*)(base + 125952);
    float*  sRed  = (float*)(base + 135168);
    float*  sRedS = (float*)(base + 136192);
    float*  sM  = (float*)(base + 137216);
    float*  sL  = (float*)(base + 137472);

    const int tid = threadIdx.x;
    const int lane = tid & 31, wid = tid >> 5;
    const int gid = lane >> 2, tig = lane & 3;
    const int i0 = (int)(gridDim.x - 1 - blockIdx.x) * 64;   // heavy tiles first
    const int bh = blockIdx.y;
    const int b = bh >> 4, h = bh & 15;

    const int wm   = (wid & 1) * 32;
    const int wgrp = wid >> 1;          // 0..3
    const int wn   = wgrp * 16;
    const int wn2  = wgrp * 32;
    const int lrow = (lane & 7) + ((lane >> 3) & 1) * 8;
    const int lcol = ((lane >> 4) & 1) * 8;

    const int nsteps = i0 / 64 + 9;

    auto issue_step = [&](int sn) {
        const int j0n = sn * 64;
        unsigned kd = smem_u32(sKb + (sn & 1) * 9216);
        unsigned vd = smem_u32(sVb + (sn & 1) * 9216);
        unsigned pd = smem_u32(sPb + (sn & 1) * 18432);
        const __half* kb = kg + ((size_t)j0n * BSZ + b) * DIN + h * HD;
        const __half* vb = vg + ((size_t)j0n * BSZ + b) * DIN + h * HD;
#pragma unroll
        for (int it = 0; it < 2; it++) {
            const int f = tid + it * 256;
            const int r = f >> 3, u = f & 7;
            cp16(kd + r * 144 + u * 16, kb + (size_t)r * BSZ * DIN + u * 8);
            cp16(vd + r * 144 + u * 16, vb + (size_t)r * BSZ * DIN + u * 8);
        }
        const int rbase = j0n - i0 + 448;
#pragma unroll
        for (int it = 0; it < 4; it++) {
            const int f = tid + it * 256;
            const int r = f >> 3, u = f & 7;
            int gr = rbase + r; if (gr > TOT - 1) gr = TOT - 1;
            cp16(pd + r * 144 + u * 16, pg + (size_t)gr * DIN + h * HD + u * 8);
        }
    };

    // prologue: Q tiles + step 0
    {
        unsigned qud = smem_u32(sQu), qvd = smem_u32(sQv);
        const __half* qub = qu + ((size_t)i0 * BSZ + b) * DIN + h * HD;
        const __half* qvb = qv + ((size_t)i0 * BSZ + b) * DIN + h * HD;
#pragma unroll
        for (int it = 0; it < 2; it++) {
            const int f = tid + it * 256;
            const int r = f >> 3, u = f & 7;
            cp16(qud + r * 144 + u * 16, qub + (size_t)r * BSZ * DIN + u * 8);
            cp16(qvd + r * 144 + u * 16, qvb + (size_t)r * BSZ * DIN + u * 8);
        }
        issue_step(0);
        CP_COMMIT();
    }
    if (tid < 64) { sM[tid] = -1e30f; sL[tid] = 0.f; }

    const unsigned* Quu = (const unsigned*)sQu;
    const unsigned* Qvu = (const unsigned*)sQv;
    unsigned* Su = (unsigned*)sS;

    float o[2][2][4];
#pragma unroll
    for (int mt = 0; mt < 2; mt++)
#pragma unroll
        for (int nt = 0; nt < 2; nt++)
#pragma unroll
            for (int e = 0; e < 4; e++) o[mt][nt][e] = 0.f;

    for (int s = 0; s < nsteps; s++) {
        const int j0 = s * 64;
        if (s + 1 < nsteps) issue_step(s + 1);
        CP_COMMIT();
        CP_WAIT1();
        __syncthreads();

        const unsigned* Ku = (const unsigned*)(sKb + (s & 1) * 9216);
        const unsigned  vB = smem_u32(sVb + (s & 1) * 9216);
        const unsigned* Pu = (const unsigned*)(sPb + (s & 1) * 18432);

        // ---- S_p = Qv @ P^T (64 x 128) ----
        float cp[2][4][4];
#pragma unroll
        for (int mt = 0; mt < 2; mt++)
#pragma unroll
            for (int nt = 0; nt < 4; nt++)
#pragma unroll
                for (int e = 0; e < 4; e++) cp[mt][nt][e] = 0.f;
#pragma unroll
        for (int kk = 0; kk < 64; kk += 16) {
            unsigned a[2][4], bf[4][2];
#pragma unroll
            for (int mt = 0; mt < 2; mt++) {
                const int m = wm + mt * 16 + gid;
                a[mt][0] = Qvu[m * 36 + kk / 2 + tig];
                a[mt][1] = Qvu[(m + 8) * 36 + kk / 2 + tig];
                a[mt][2] = Qvu[m * 36 + kk / 2 + tig + 4];
                a[mt][3] = Qvu[(m + 8) * 36 + kk / 2 + tig + 4];
            }
#pragma unroll
            for (int nt = 0; nt < 4; nt++) {
                const int n = wn2 + nt * 8 + gid;
                bf[nt][0] = Pu[n * 36 + kk / 2 + tig];
                bf[nt][1] = Pu[n * 36 + kk / 2 + tig + 4];
            }
#pragma unroll
            for (int mt = 0; mt < 2; mt++)
#pragma unroll
                for (int nt = 0; nt < 4; nt++)
                    MMA_F16(cp[mt][nt], a[mt], bf[nt]);
        }
#pragma unroll
        for (int mt = 0; mt < 2; mt++)
#pragma unroll
            for (int nt = 0; nt < 4; nt++)
#pragma unroll
                for (int hf = 0; hf < 2; hf++) {
                    const int li = wm + mt * 16 + gid + 8 * hf;
                    const int col = wn2 + nt * 8 + 2 * tig;
                    *(float2*)&sSp[li * 132 + col] =
                        make_float2(cp[mt][nt][hf * 2], cp[mt][nt][hf * 2 + 1]);
                }

        // ---- S_c = Qu @ K^T (64 x 64) ----
        float cc[2][2][4];
#pragma unroll
        for (int mt = 0; mt < 2; mt++)
#pragma unroll
            for (int nt = 0; nt < 2; nt++)
#pragma unroll
                for (int e = 0; e < 4; e++) cc[mt][nt][e] = 0.f;
#pragma unroll
        for (int kk = 0; kk < 64; kk += 16) {
            unsigned a[2][4], bf[2][2];
#pragma unroll
            for (int mt = 0; mt < 2; mt++) {
                const int m = wm + mt * 16 + gid;
                a[mt][0] = Quu[m * 36 + kk / 2 + tig];
                a[mt][1] = Quu[(m + 8) * 36 + kk / 2 + tig];
                a[mt][2] = Quu[m * 36 + kk / 2 + tig + 4];
                a[mt][3] = Quu[(m + 8) * 36 + kk / 2 + tig + 4];
            }
#pragma unroll
            for (int nt = 0; nt < 2; nt++) {
                const int n = wn + nt * 8 + gid;
                bf[nt][0] = Ku[n * 36 + kk / 2 + tig];
                bf[nt][1] = Ku[n * 36 + kk / 2 + tig + 4];
            }
#pragma unroll
            for (int mt = 0; mt < 2; mt++)
#pragma unroll
                for (int nt = 0; nt < 2; nt++)
                    MMA_F16(cc[mt][nt], a[mt], bf[nt]);
        }
        __syncthreads();   // sSp visible

        // ---- combine + mask + row-max partials (fragment-resident) ----
        float val[2][2][2][2];   // mt, nt, hf, e
        float cmax[2][2];        // per (mt,hf)
#pragma unroll
        for (int mt = 0; mt < 2; mt++)
#pragma unroll
            for (int hf = 0; hf < 2; hf++) {
                const int li = wm + mt * 16 + gid + 8 * hf;
                float mx = -1e30f;
#pragma unroll
                for (int nt = 0; nt < 2; nt++)
#pragma unroll
                    for (int e = 0; e < 2; e++) {
                        const int lj = wn + nt * 8 + 2 * tig + e;
                        float v = (cc[mt][nt][hf * 2 + e]
                                   + sSp[li * 132 + lj + 63 - li]) * 0.125f;
                        const bool ok = (j0 + lj) <= (i0 + li + PREV);
                        v = ok ? v : -1e30f;
                        val[mt][nt][hf][e] = v;
                        mx = fmaxf(mx, v);
                    }
                mx = fmaxf(mx, __shfl_xor_sync(0xffffffffu, mx, 1));
                mx = fmaxf(mx, __shfl_xor_sync(0xffffffffu, mx, 2));
                cmax[mt][hf] = mx;
                if (tig == 0) sRed[wgrp * 64 + li] = mx;
            }
        __syncthreads();

        // ---- exp + probs (fp16) + row-sum partials ----
        float scr[2][2];
#pragma unroll
        for (int mt = 0; mt < 2; mt++)
#pragma unroll
            for (int hf = 0; hf < 2; hf++) {
                const int li = wm + mt * 16 + gid + 8 * hf;
                const float mold = sM[li];
                float mnew = fmaxf(mold,
                    fmaxf(fmaxf(sRed[li], sRed[64 + li]),
                          fmaxf(sRed[128 + li], sRed[192 + li])));
                scr[mt][hf] = __expf(mold - mnew);
                float ssum = 0.f;
#pragma unroll
                for (int nt = 0; nt < 2; nt++) {
                    float e0 = __expf(val[mt][nt][hf][0] - mnew);
                    float e1 = __expf(val[mt][nt][hf][1] - mnew);
                    ssum += e0 + e1;
                    __half2 h = __floats2half2_rn(e0, e1);
                    Su[li * 36 + wn / 2 + nt * 4 + tig] = *(unsigned*)&h;
                }
                ssum += __shfl_xor_sync(0xffffffffu, ssum, 1);
                ssum += __shfl_xor_sync(0xffffffffu, ssum, 2);
                if (tig == 0) sRedS[wgrp * 64 + li] = ssum;
            }
        __syncthreads();

        // ---- bookkeeping (64 threads) overlapped with rescale + PV ----
        if (tid < 64) {
            const int row = tid;
            const float mold = sM[row];
            const float mnew = fmaxf(mold,
                fmaxf(fmaxf(sRed[row], sRed[64 + row]),
                      fmaxf(sRed[128 + row], sRed[192 + row])));
            const float ssum = sRedS[row] + sRedS[64 + row]
                             + sRedS[128 + row] + sRedS[192 + row];
            sM[row] = mnew;
            sL[row] = sL[row] * __expf(mold - mnew) + ssum;
        }

        // ---- O rescale + O += P @ V ----
#pragma unroll
        for (int mt = 0; mt < 2; mt++)
#pragma unroll
            for (int nt = 0; nt < 2; nt++) {
                o[mt][nt][0] *= scr[mt][0]; o[mt][nt][1] *= scr[mt][0];
                o[mt][nt][2] *= scr[mt][1]; o[mt][nt][3] *= scr[mt][1];
            }
#pragma unroll
        for (int kk = 0; kk < 64; kk += 16) {
            unsigned a[2][4];
#pragma unroll
            for (int mt = 0; mt < 2; mt++) {
                const int m = wm + mt * 16 + gid;
                a[mt][0] = Su[m * 36 + kk / 2 + tig];
                a[mt][1] = Su[(m + 8) * 36 + kk / 2 + tig];
                a[mt][2] = Su[m * 36 + kk / 2 + tig + 4];
                a[mt][3] = Su[(m + 8) * 36 + kk / 2 + tig + 4];
            }
            unsigned r0, r1, r2, r3;
            ldmx4t(r0, r1, r2, r3, vB + (kk + lrow) * 144 + (wn + lcol) * 2);
            unsigned b0[2] = {r0, r1}, b1[2] = {r2, r3};
#pragma unroll
            for (int mt = 0; mt < 2; mt++) {
                MMA_F16(o[mt][0], a[mt], b0);
                MMA_F16(o[mt][1], a[mt], b1);
            }
        }
        __syncthreads();   // buffers free for next prefetch
    }

    // ---- write awv = O / l (fp16) ----
#pragma unroll
    for (int mt = 0; mt < 2; mt++)
#pragma unroll
        for (int nt = 0; nt < 2; nt++)
#pragma unroll
            for (int hf = 0; hf < 2; hf++) {
                const int li = wm + mt * 16 + gid + 8 * hf;
                const int c  = wn + nt * 8 + 2 * tig;
                const float inv = 1.f / sL[li];
                __half2 w = __floats2half2_rn(o[mt][nt][hf * 2] * inv,
                                              o[mt][nt][hf * 2 + 1] * inv);
                *(__half2*)&awv[((size_t)(i0 + li) * BSZ + b) * DIN + h * HD + c] = w;
            }
}

// ---------------- LayerNorm over last dim (1024), one block per row ------------
__global__ __launch_bounds__(256) void ln_kernel(
    const float* __restrict__ x, const float* __restrict__ gamma,
    const float* __restrict__ beta, float* __restrict__ out)
{
    const size_t row = blockIdx.x;
    const int tid = threadIdx.x;
    const float4 v = ((const float4*)(x + row * DIN))[tid];
    __shared__ float red[8];

    float s = v.x + v.y + v.z + v.w;
#pragma unroll
    for (int o = 16; o; o >>= 1) s += __shfl_xor_sync(0xffffffffu, s, o);
    if ((tid & 31) == 0) red[tid >> 5] = s;
    __syncthreads();
    s = red[0];
#pragma unroll
    for (int w = 1; w < 8; w++) s += red[w];
    const float mu = s * (1.0f / DIN);
    __syncthreads();

    const float d0 = v.x - mu, d1 = v.y - mu, d2 = v.z - mu, d3 = v.w - mu;
    float s2 = d0 * d0 + d1 * d1 + d2 * d2 + d3 * d3;
#pragma unroll
    for (int o = 16; o; o >>= 1) s2 += __shfl_xor_sync(0xffffffffu, s2, o);
    if ((tid & 31) == 0) red[tid >> 5] = s2;
    __syncthreads();
    s2 = red[0];
#pragma unroll
    for (int w = 1; w < 8; w++) s2 += red[w];
    const float inv = rsqrtf(s2 * (1.0f / DIN) + 1e-5f);

    const float4 g  = ((const float4*)gamma)[tid];
    const float4 bb = ((const float4*)beta)[tid];
    float4 o4;
    o4.x = d0 * inv * g.x + bb.x;
    o4.y = d1 * inv * g.y + bb.y;
    o4.z = d2 * inv * g.z + bb.z;
    o4.w = d3 * inv * g.w + bb.w;
    ((float4*)(out + row * DIN))[tid] = o4;
}

// ---------------- launch ---------------------------------------------------------
extern "C" void kernel_launch(void* const* d_in, const int* in_sizes, int n_in,
                              void* d_out, int out_size)
{
    const float* input_ = (const float*)d_in[0];
    const float* pos    = (const float*)d_in[1];
    const float* memory = (const float*)d_in[2];
    const float* u      = (const float*)d_in[3];
    const float* vvec   = (const float*)d_in[4];
    // d_in[5] = mask (analytic: j <= i + PREV)
    const float* W_kv   = (const float*)d_in[6];
    const float* W_q    = (const float*)d_in[7];
    const float* W_p    = (const float*)d_in[8];
    const float* W_out  = (const float*)d_in[9];
    const float* gamma  = (const float*)d_in[10];
    const float* beta   = (const float*)d_in[11];
    float* out = (float*)d_out;

    __half *pin, *pmem, *ppos, *pwkv, *pwq, *pwp, *pwo;
    __half *pk, *pv, *pp, *pqu, *pqv, *pawv;
    float* pout;
    cudaGetSymbolAddress((void**)&pin,  g_in16);
    cudaGetSymbolAddress((void**)&pmem, g_mem16);
    cudaGetSymbolAddress((void**)&ppos, g_pos16);
    cudaGetSymbolAddress((void**)&pwkv, g_wkv16);
    cudaGetSymbolAddress((void**)&pwq,  g_wq16);
    cudaGetSymbolAddress((void**)&pwp,  g_wp16);
    cudaGetSymbolAddress((void**)&pwo,  g_wo16);
    cudaGetSymbolAddress((void**)&pk,   g_kh);
    cudaGetSymbolAddress((void**)&pv,   g_vh);
    cudaGetSymbolAddress((void**)&pp,   g_ph);
    cudaGetSymbolAddress((void**)&pqu,  g_qu);
    cudaGetSymbolAddress((void**)&pqv,  g_qv);
    cudaGetSymbolAddress((void**)&pawv, g_awv);
    cudaGetSymbolAddress((void**)&pout, g_out);

    const int GEMM_SMEM = 2 * 18432 + 2 * 17408;   // 71680
    const int FA_SMEM   = 137728;
    static bool attr_done = false;
    if (!attr_done) {
        cudaFuncSetAttribute(tcgemm_h<0>, cudaFuncAttributeMaxDynamicSharedMemorySize, GEMM_SMEM);
        cudaFuncSetAttribute(tcgemm_h<1>, cudaFuncAttributeMaxDynamicSharedMemorySize, GEMM_SMEM);
        cudaFuncSetAttribute(tcgemm_h<2>, cudaFuncAttributeMaxDynamicSharedMemorySize, GEMM_SMEM);
        cudaFuncSetAttribute(tcgemm_h<3>, cudaFuncAttributeMaxDynamicSharedMemorySize, GEMM_SMEM);
        cudaFuncSetAttribute(flash_attn,  cudaFuncAttributeMaxDynamicSharedMemorySize, FA_SMEM);
        attr_done = true;
    }

    // 0) fp32 -> fp16 conversions
    auto cvt = [&](const float* src, __half* dst, int n) {
        cvt_kernel<<<(n / 4 + 255) / 256, 256>>>((const float4*)src, (__half2*)dst, n / 4);
    };
    cvt(input_, pin,  SEQ * BSZ * DIN);
    cvt(memory, pmem, PREV * BSZ * DIN);
    cvt(pos,    ppos, TOT * DIN);
    cvt(W_kv,   pwkv, DIN * 2 * DIN);
    cvt(W_q,    pwq,  DIN * DIN);
    cvt(W_p,    pwp,  DIN * DIN);
    cvt(W_out,  pwo,  DIN * DIN);

    // 1) kv = concat(memory, input_) @ W_kv -> K | V (fp16)
    tcgemm_h<1><<<dim3(16, 64), 256, GEMM_SMEM>>>(
        pmem, pin, PREV * BSZ, DIN, pwkv, 2 * DIN,
        pk, pv, DIN, nullptr, nullptr, nullptr, DIN);

    // 2) qu = input_ @ W_q + u, qv = ... + v (fp16)
    tcgemm_h<2><<<dim3(8, 32), 256, GEMM_SMEM>>>(
        pin, pin, 1 << 30, DIN, pwq, DIN,
        pqu, pqv, DIN, nullptr, u, vvec, DIN);

    // 3) p = pos_embs @ W_p (fp16)
    tcgemm_h<3><<<dim3(8, 8), 256, GEMM_SMEM>>>(
        ppos, ppos, 1 << 30, DIN, pwp, DIN,
        pp, nullptr, DIN, nullptr, nullptr, nullptr, DIN);

    // 4) fused attention -> awv (fp16)
    flash_attn<<<dim3(SEQ / 64, BSZ * NH), 256, FA_SMEM>>>(
        pqu, pqv, pk, pv, pp, pawv);

    // 5) out_pre = input_ + awv @ W_out (fp32)
    tcgemm_h<0><<<dim3(8, 32), 256, GEMM_SMEM>>>(
        pawv, pawv, 1 << 30, DIN, pwo, DIN,
        pout, nullptr, DIN, input_, nullptr, nullptr, DIN);

    // 6) LayerNorm -> d_out
    ln_kernel<<<SEQ * BSZ, 256>>>(pout, gamma, beta, out);
}

// round 7
// speedup vs baseline: 8.1508x; 1.1444x over previous
#include <cuda_runtime.h>
#include <cuda_fp16.h>
#include <math.h>

#define SEQ  512
#define PREV 512
#define TOT  1024
#define BSZ  8
#define DIN  1024
#define NH   16
#define HD   64

// ---------------- scratch (static device globals; no allocations) ----------------
__device__ __half g_in16 [SEQ * BSZ * DIN];
__device__ __half g_mem16[PREV * BSZ * DIN];
__device__ __half g_pos16[TOT * DIN];
__device__ __half g_wkv16[DIN * 2 * DIN];
__device__ __half g_wq16 [DIN * DIN];
__device__ __half g_wp16 [DIN * DIN];
__device__ __half g_wo16 [DIN * DIN];
__device__ __half g_kh [TOT * BSZ * DIN];
__device__ __half g_vh [TOT * BSZ * DIN];
__device__ __half g_ph [TOT * DIN];
__device__ __half g_qu [SEQ * BSZ * DIN];
__device__ __half g_qv [SEQ * BSZ * DIN];
__device__ __half g_awv[SEQ * BSZ * DIN];
__device__ float  g_out[SEQ * BSZ * DIN];

__device__ __forceinline__ unsigned smem_u32(const void* p) {
    return (unsigned)__cvta_generic_to_shared(p);
}
__device__ __forceinline__ void cp16(unsigned dst, const void* src) {
    asm volatile("cp.async.cg.shared.global [%0], [%1], 16;" :: "r"(dst), "l"(src));
}
#define CP_COMMIT() asm volatile("cp.async.commit_group;")
#define CP_WAIT1()  asm volatile("cp.async.wait_group 1;")

#define MMA_F16(c, a, b)                                                       \
    asm volatile(                                                              \
        "mma.sync.aligned.m16n8k16.row.col.f32.f16.f16.f32 "                   \
        "{%0,%1,%2,%3},{%4,%5,%6,%7},{%8,%9},{%0,%1,%2,%3};"                   \
        : "+f"(c[0]), "+f"(c[1]), "+f"(c[2]), "+f"(c[3])                       \
        : "r"(a[0]), "r"(a[1]), "r"(a[2]), "r"(a[3]), "r"(b[0]), "r"(b[1]))

__device__ __forceinline__ void ldmx4t(unsigned& r0, unsigned& r1,
                                       unsigned& r2, unsigned& r3, unsigned a) {
    asm volatile("ldmatrix.sync.aligned.m8n8.x4.trans.shared.b16 "
                 "{%0,%1,%2,%3}, [%4];"
                 : "=r"(r0), "=r"(r1), "=r"(r2), "=r"(r3) : "r"(a));
}

// ---------------- fp32 -> fp16 converter (single segmented launch) --------------
struct CvtSegs {
    const float4* src[7];
    __half2*      dst[7];
    int           n4[7];
};

__global__ void cvt_all(CvtSegs s)
{
    int i = blockIdx.x * blockDim.x + threadIdx.x;
#pragma unroll
    for (int k = 0; k < 7; k++) {
        if (i < s.n4[k]) {
            float4 v = s.src[k][i];
            s.dst[k][2 * i]     = __floats2half2_rn(v.x, v.y);
            s.dst[k][2 * i + 1] = __floats2half2_rn(v.z, v.w);
            return;
        }
        i -= s.n4[k];
    }
}

// ============ fp16 GEMM, BK=64, cp.async double-buffered, 2 blocks/SM ============
// C = gather(A0 rows [0,M0) | A1) @ B  (B row-major [K][N] fp16).
// EPI 0: fp32 out (+resid). EPI 1: half split at col 1024 -> O0|O1.
// EPI 2: half qu=val+bu, qv=val+bv -> O0,O1. EPI 3: half plain -> O0.
extern __shared__ char dsm[];

template<int EPI>
__global__ __launch_bounds__(256, 2) void tcgemm_h(
    const __half* __restrict__ A0, const __half* __restrict__ A1, int M0, long lda,
    const __half* __restrict__ B, long ldb,
    void* __restrict__ O0, void* __restrict__ O1, long ldc,
    const float* __restrict__ resid,
    const float* __restrict__ bu, const float* __restrict__ bv, int K)
{
    const int tid  = threadIdx.x;
    const int lane = tid & 31, wid = tid >> 5;
    const int gid  = lane >> 2, tig = lane & 3;
    const int warp_m = (wid & 3) * 32;
    const int warp_n = (wid >> 2) * 64;
    const int row0 = blockIdx.y * 128;
    const int col0 = blockIdx.x * 128;

    char* As = dsm;                 // 2 x 18432
    char* Bs = dsm + 2 * 18432;     // 2 x 17408

    float c[2][8][4];
#pragma unroll
    for (int mt = 0; mt < 2; mt++)
#pragma unroll
        for (int nt = 0; nt < 8; nt++)
#pragma unroll
            for (int q = 0; q < 4; q++) c[mt][nt][q] = 0.f;

    auto issue = [&](int k0, int buf) {
        unsigned ab = smem_u32(As + buf * 18432);
        unsigned bb = smem_u32(Bs + buf * 17408);
#pragma unroll
        for (int it = 0; it < 4; it++) {
            const int f = tid + it * 256;
            const int r = f >> 3, u = f & 7;
            const int gm = row0 + r;
            const __half* src = (gm < M0 ? A0 + (size_t)gm * lda
                                         : A1 + (size_t)(gm - M0) * lda) + k0 + u * 8;
            cp16(ab + r * 144 + u * 16, src);
        }
#pragma unroll
        for (int it = 0; it < 4; it++) {
            const int f = tid + it * 256;
            const int k = f >> 4, u = f & 15;
            cp16(bb + k * 272 + u * 16, B + (size_t)(k0 + k) * ldb + col0 + u * 8);
        }
    };

    issue(0, 0); CP_COMMIT();
    const int nk = K / 64;
    const int lrow = (lane & 7) + ((lane >> 3) & 1) * 8;
    const int lcol = ((lane >> 4) & 1) * 8;

    for (int kt = 0; kt < nk; kt++) {
        if (kt + 1 < nk) issue((kt + 1) * 64, (kt + 1) & 1);
        CP_COMMIT();
        CP_WAIT1();
        __syncthreads();

        const unsigned* Au = (const unsigned*)(As + (kt & 1) * 18432);
        const unsigned  bb = smem_u32(Bs + (kt & 1) * 17408);
#pragma unroll
        for (int kk = 0; kk < 64; kk += 16) {
            unsigned a[2][4];
#pragma unroll
            for (int mt = 0; mt < 2; mt++) {
                const int m = warp_m + mt * 16 + gid;
                a[mt][0] = Au[m * 36 + kk / 2 + tig];
                a[mt][1] = Au[(m + 8) * 36 + kk / 2 + tig];
                a[mt][2] = Au[m * 36 + kk / 2 + tig + 4];
                a[mt][3] = Au[(m + 8) * 36 + kk / 2 + tig + 4];
            }
#pragma unroll
            for (int p = 0; p < 4; p++) {
                unsigned r0, r1, r2, r3;
                ldmx4t(r0, r1, r2, r3,
                       bb + (kk + lrow) * 272 + (warp_n + p * 16 + lcol) * 2);
                unsigned b0[2] = {r0, r1}, b1[2] = {r2, r3};
#pragma unroll
                for (int mt = 0; mt < 2; mt++) {
                    MMA_F16(c[mt][2 * p],     a[mt], b0);
                    MMA_F16(c[mt][2 * p + 1], a[mt], b1);
                }
            }
        }
        __syncthreads();
    }

#pragma unroll
    for (int mt = 0; mt < 2; mt++) {
#pragma unroll
        for (int nt = 0; nt < 8; nt++) {
            const int cb = col0 + warp_n + nt * 8 + 2 * tig;
#pragma unroll
            for (int hf = 0; hf < 2; hf++) {
                const int r = row0 + warp_m + mt * 16 + gid + 8 * hf;
                float v0 = c[mt][nt][hf * 2], v1 = c[mt][nt][hf * 2 + 1];
                if (EPI == 0) {
                    if (resid) {
                        v0 += resid[(size_t)r * ldc + cb];
                        v1 += resid[(size_t)r * ldc + cb + 1];
                    }
                    ((float*)O0)[(size_t)r * ldc + cb]     = v0;
                    ((float*)O0)[(size_t)r * ldc + cb + 1] = v1;
                } else if (EPI == 1) {
                    __half2 h = __floats2half2_rn(v0, v1);
                    if (cb < DIN)
                        *(__half2*)((__half*)O0 + (size_t)r * DIN + cb) = h;
                    else
                        *(__half2*)((__half*)O1 + (size_t)r * DIN + cb - DIN) = h;
                } else if (EPI == 2) {
                    __half2 hu = __floats2half2_rn(v0 + bu[cb], v1 + bu[cb + 1]);
                    __half2 hv = __floats2half2_rn(v0 + bv[cb], v1 + bv[cb + 1]);
                    *(__half2*)((__half*)O0 + (size_t)r * ldc + cb) = hu;
                    *(__half2*)((__half*)O1 + (size_t)r * ldc + cb) = hv;
                } else {
                    *(__half2*)((__half*)O0 + (size_t)r * ldc + cb) =
                        __floats2half2_rn(v0, v1);
                }
            }
        }
    }
}

// ============ fused fp16 flash attention, 2 blocks/SM ============================
// Block: one (b,h), 64 q-rows, 256 threads (2 m-warps x 4 n-warps).
// smem byte layout (total 111616):
//  sQu 0 (9216) | sQv 9216 | sK 18432 (2x9216) | sV 36864 (2x9216)
//  sP 55296 (2x18432) | sSp 92160 (64x132 half = 16896; sS 9216 ALIASED here)
//  sRed 109056 | sRedS 110080 | sM 111104 | sL 111360
__global__ __launch_bounds__(256, 2) void flash_attn(
    const __half* __restrict__ qu, const __half* __restrict__ qv,
    const __half* __restrict__ kg, const __half* __restrict__ vg,
    const __half* __restrict__ pg, __half* __restrict__ awv)
{
    char* base = dsm;
    __half* sQu = (__half*)(base);
    __half* sQv = (__half*)(base + 9216);
    char*   sKb = base + 18432;
    char*   sVb = base + 36864;
    char*   sPb = base + 55296;
    __half* sSp = (__half*)(base + 92160);          // fp16 pos-score stage
    unsigned* Su = (unsigned*)(base + 92160);       // probs, ALIASES sSp (time-disjoint)
    float*  sRed  = (float*)(base + 109056);
    float*  sRedS = (float*)(base + 110080);
    float*  sM  = (float*)(base + 111104);
    float*  sL  = (float*)(base + 111360);

    const int tid = threadIdx.x;
    const int lane = tid & 31, wid = tid >> 5;
    const int gid = lane >> 2, tig = lane & 3;
    const int i0 = (int)(gridDim.x - 1 - blockIdx.x) * 64;   // heavy tiles first
    const int bh = blockIdx.y;
    const int b = bh >> 4, h = bh & 15;

    const int wm   = (wid & 1) * 32;
    const int wgrp = wid >> 1;          // 0..3
    const int wn   = wgrp * 16;
    const int wn2  = wgrp * 32;
    const int lrow = (lane & 7) + ((lane >> 3) & 1) * 8;
    const int lcol = ((lane >> 4) & 1) * 8;

    const int nsteps = i0 / 64 + 9;

    auto issue_step = [&](int sn) {
        const int j0n = sn * 64;
        unsigned kd = smem_u32(sKb + (sn & 1) * 9216);
        unsigned vd = smem_u32(sVb + (sn & 1) * 9216);
        unsigned pd = smem_u32(sPb + (sn & 1) * 18432);
        const __half* kb = kg + ((size_t)j0n * BSZ + b) * DIN + h * HD;
        const __half* vb = vg + ((size_t)j0n * BSZ + b) * DIN + h * HD;
#pragma unroll
        for (int it = 0; it < 2; it++) {
            const int f = tid + it * 256;
            const int r = f >> 3, u = f & 7;
            cp16(kd + r * 144 + u * 16, kb + (size_t)r * BSZ * DIN + u * 8);
            cp16(vd + r * 144 + u * 16, vb + (size_t)r * BSZ * DIN + u * 8);
        }
        const int rbase = j0n - i0 + 448;
#pragma unroll
        for (int it = 0; it < 4; it++) {
            const int f = tid + it * 256;
            const int r = f >> 3, u = f & 7;
            int gr = rbase + r; if (gr > TOT - 1) gr = TOT - 1;
            cp16(pd + r * 144 + u * 16, pg + (size_t)gr * DIN + h * HD + u * 8);
        }
    };

    // prologue: Q tiles + step 0
    {
        unsigned qud = smem_u32(sQu), qvd = smem_u32(sQv);
        const __half* qub = qu + ((size_t)i0 * BSZ + b) * DIN + h * HD;
        const __half* qvb = qv + ((size_t)i0 * BSZ + b) * DIN + h * HD;
#pragma unroll
        for (int it = 0; it < 2; it++) {
            const int f = tid + it * 256;
            const int r = f >> 3, u = f & 7;
            cp16(qud + r * 144 + u * 16, qub + (size_t)r * BSZ * DIN + u * 8);
            cp16(qvd + r * 144 + u * 16, qvb + (size_t)r * BSZ * DIN + u * 8);
        }
        issue_step(0);
        CP_COMMIT();
    }
    if (tid < 64) { sM[tid] = -1e30f; sL[tid] = 0.f; }

    const unsigned* Quu = (const unsigned*)sQu;
    const unsigned* Qvu = (const unsigned*)sQv;

    float o[2][2][4];
#pragma unroll
    for (int mt = 0; mt < 2; mt++)
#pragma unroll
        for (int nt = 0; nt < 2; nt++)
#pragma unroll
            for (int e = 0; e < 4; e++) o[mt][nt][e] = 0.f;

    for (int s = 0; s < nsteps; s++) {
        const int j0 = s * 64;
        if (s + 1 < nsteps) issue_step(s + 1);
        CP_COMMIT();
        CP_WAIT1();
        __syncthreads();

        const unsigned* Ku = (const unsigned*)(sKb + (s & 1) * 9216);
        const unsigned  vB = smem_u32(sVb + (s & 1) * 9216);
        const unsigned* Pu = (const unsigned*)(sPb + (s & 1) * 18432);

        // ---- S_p = Qv @ P^T (64 x 128) ----
        float cp[2][4][4];
#pragma unroll
        for (int mt = 0; mt < 2; mt++)
#pragma unroll
            for (int nt = 0; nt < 4; nt++)
#pragma unroll
                for (int e = 0; e < 4; e++) cp[mt][nt][e] = 0.f;
#pragma unroll
        for (int kk = 0; kk < 64; kk += 16) {
            unsigned a[2][4], bf[4][2];
#pragma unroll
            for (int mt = 0; mt < 2; mt++) {
                const int m = wm + mt * 16 + gid;
                a[mt][0] = Qvu[m * 36 + kk / 2 + tig];
                a[mt][1] = Qvu[(m + 8) * 36 + kk / 2 + tig];
                a[mt][2] = Qvu[m * 36 + kk / 2 + tig + 4];
                a[mt][3] = Qvu[(m + 8) * 36 + kk / 2 + tig + 4];
            }
#pragma unroll
            for (int nt = 0; nt < 4; nt++) {
                const int n = wn2 + nt * 8 + gid;
                bf[nt][0] = Pu[n * 36 + kk / 2 + tig];
                bf[nt][1] = Pu[n * 36 + kk / 2 + tig + 4];
            }
#pragma unroll
            for (int mt = 0; mt < 2; mt++)
#pragma unroll
                for (int nt = 0; nt < 4; nt++)
                    MMA_F16(cp[mt][nt], a[mt], bf[nt]);
        }
#pragma unroll
        for (int mt = 0; mt < 2; mt++)
#pragma unroll
            for (int nt = 0; nt < 4; nt++)
#pragma unroll
                for (int hf = 0; hf < 2; hf++) {
                    const int li = wm + mt * 16 + gid + 8 * hf;
                    const int col = wn2 + nt * 8 + 2 * tig;
                    *(__half2*)&sSp[li * 132 + col] =
                        __floats2half2_rn(cp[mt][nt][hf * 2], cp[mt][nt][hf * 2 + 1]);
                }

        // ---- S_c = Qu @ K^T (64 x 64) ----
        float cc[2][2][4];
#pragma unroll
        for (int mt = 0; mt < 2; mt++)
#pragma unroll
            for (int nt = 0; nt < 2; nt++)
#pragma unroll
                for (int e = 0; e < 4; e++) cc[mt][nt][e] = 0.f;
#pragma unroll
        for (int kk = 0; kk < 64; kk += 16) {
            unsigned a[2][4], bf[2][2];
#pragma unroll
            for (int mt = 0; mt < 2; mt++) {
                const int m = wm + mt * 16 + gid;
                a[mt][0] = Quu[m * 36 + kk / 2 + tig];
                a[mt][1] = Quu[(m + 8) * 36 + kk / 2 + tig];
                a[mt][2] = Quu[m * 36 + kk / 2 + tig + 4];
                a[mt][3] = Quu[(m + 8) * 36 + kk / 2 + tig + 4];
            }
#pragma unroll
            for (int nt = 0; nt < 2; nt++) {
                const int n = wn + nt * 8 + gid;
                bf[nt][0] = Ku[n * 36 + kk / 2 + tig];
                bf[nt][1] = Ku[n * 36 + kk / 2 + tig + 4];
            }
#pragma unroll
            for (int mt = 0; mt < 2; mt++)
#pragma unroll
                for (int nt = 0; nt < 2; nt++)
                    MMA_F16(cc[mt][nt], a[mt], bf[nt]);
        }
        __syncthreads();   // sSp visible to all warps

        // ---- combine + mask + row-max partials (fragment-resident) ----
        float val[2][2][2][2];   // mt, nt, hf, e
#pragma unroll
        for (int mt = 0; mt < 2; mt++)
#pragma unroll
            for (int hf = 0; hf < 2; hf++) {
                const int li = wm + mt * 16 + gid + 8 * hf;
                float mx = -1e30f;
#pragma unroll
                for (int nt = 0; nt < 2; nt++)
#pragma unroll
                    for (int e = 0; e < 2; e++) {
                        const int lj = wn + nt * 8 + 2 * tig + e;
                        float v = (cc[mt][nt][hf * 2 + e]
                                   + __half2float(sSp[li * 132 + lj + 63 - li])) * 0.125f;
                        const bool ok = (j0 + lj) <= (i0 + li + PREV);
                        v = ok ? v : -1e30f;
                        val[mt][nt][hf][e] = v;
                        mx = fmaxf(mx, v);
                    }
                mx = fmaxf(mx, __shfl_xor_sync(0xffffffffu, mx, 1));
                mx = fmaxf(mx, __shfl_xor_sync(0xffffffffu, mx, 2));
                if (tig == 0) sRed[wgrp * 64 + li] = mx;
            }
        __syncthreads();   // sSp fully consumed; Su writes may begin

        // ---- exp + probs (fp16, into Su alias) + row-sum partials ----
        float scr[2][2];
#pragma unroll
        for (int mt = 0; mt < 2; mt++)
#pragma unroll
            for (int hf = 0; hf < 2; hf++) {
                const int li = wm + mt * 16 + gid + 8 * hf;
                const float mold = sM[li];
                float mnew = fmaxf(mold,
                    fmaxf(fmaxf(sRed[li], sRed[64 + li]),
                          fmaxf(sRed[128 + li], sRed[192 + li])));
                scr[mt][hf] = __expf(mold - mnew);
                float ssum = 0.f;
#pragma unroll
                for (int nt = 0; nt < 2; nt++) {
                    float e0 = __expf(val[mt][nt][hf][0] - mnew);
                    float e1 = __expf(val[mt][nt][hf][1] - mnew);
                    ssum += e0 + e1;
                    __half2 hh = __floats2half2_rn(e0, e1);
                    Su[li * 36 + wn / 2 + nt * 4 + tig] = *(unsigned*)&hh;
                }
                ssum += __shfl_xor_sync(0xffffffffu, ssum, 1);
                ssum += __shfl_xor_sync(0xffffffffu, ssum, 2);
                if (tig == 0) sRedS[wgrp * 64 + li] = ssum;
            }
        __syncthreads();

        // ---- bookkeeping (64 threads) ----
        if (tid < 64) {
            const int row = tid;
            const float mold = sM[row];
            const float mnew = fmaxf(mold,
                fmaxf(fmaxf(sRed[row], sRed[64 + row]),
                      fmaxf(sRed[128 + row], sRed[192 + row])));
            const float ssum = sRedS[row] + sRedS[64 + row]
                             + sRedS[128 + row] + sRedS[192 + row];
            sM[row] = mnew;
            sL[row] = sL[row] * __expf(mold - mnew) + ssum;
        }

        // ---- O rescale + O += P @ V ----
#pragma unroll
        for (int mt = 0; mt < 2; mt++)
#pragma unroll
            for (int nt = 0; nt < 2; nt++) {
                o[mt][nt][0] *= scr[mt][0]; o[mt][nt][1] *= scr[mt][0];
                o[mt][nt][2] *= scr[mt][1]; o[mt][nt][3] *= scr[mt][1];
            }
#pragma unroll
        for (int kk = 0; kk < 64; kk += 16) {
            unsigned a[2][4];
#pragma unroll
            for (int mt = 0; mt < 2; mt++) {
                const int m = wm + mt * 16 + gid;
                a[mt][0] = Su[m * 36 + kk / 2 + tig];
                a[mt][1] = Su[(m + 8) * 36 + kk / 2 + tig];
                a[mt][2] = Su[m * 36 + kk / 2 + tig + 4];
                a[mt][3] = Su[(m + 8) * 36 + kk / 2 + tig + 4];
            }
            unsigned r0, r1, r2, r3;
            ldmx4t(r0, r1, r2, r3, vB + (kk + lrow) * 144 + (wn + lcol) * 2);
            unsigned b0[2] = {r0, r1}, b1[2] = {r2, r3};
#pragma unroll
            for (int mt = 0; mt < 2; mt++) {
                MMA_F16(o[mt][0], a[mt], b0);
                MMA_F16(o[mt][1], a[mt], b1);
            }
        }
        __syncthreads();   // buffers (incl. Su/sSp) free for next step
    }

    // ---- write awv = O / l (fp16) ----
#pragma unroll
    for (int mt = 0; mt < 2; mt++)
#pragma unroll
        for (int nt = 0; nt < 2; nt++)
#pragma unroll
            for (int hf = 0; hf < 2; hf++) {
                const int li = wm + mt * 16 + gid + 8 * hf;
                const int c  = wn + nt * 8 + 2 * tig;
                const float inv = 1.f / sL[li];
                __half2 w = __floats2half2_rn(o[mt][nt][hf * 2] * inv,
                                              o[mt][nt][hf * 2 + 1] * inv);
                *(__half2*)&awv[((size_t)(i0 + li) * BSZ + b) * DIN + h * HD + c] = w;
            }
}

// ---------------- LayerNorm over last dim (1024), one block per row ------------
__global__ __launch_bounds__(256) void ln_kernel(
    const float* __restrict__ x, const float* __restrict__ gamma,
    const float* __restrict__ beta, float* __restrict__ out)
{
    const size_t row = blockIdx.x;
    const int tid = threadIdx.x;
    const float4 v = ((const float4*)(x + row * DIN))[tid];
    __shared__ float red[8];

    float s = v.x + v.y + v.z + v.w;
#pragma unroll
    for (int o = 16; o; o >>= 1) s += __shfl_xor_sync(0xffffffffu, s, o);
    if ((tid & 31) == 0) red[tid >> 5] = s;
    __syncthreads();
    s = red[0];
#pragma unroll
    for (int w = 1; w < 8; w++) s += red[w];
    const float mu = s * (1.0f / DIN);
    __syncthreads();

    const float d0 = v.x - mu, d1 = v.y - mu, d2 = v.z - mu, d3 = v.w - mu;
    float s2 = d0 * d0 + d1 * d1 + d2 * d2 + d3 * d3;
#pragma unroll
    for (int o = 16; o; o >>= 1) s2 += __shfl_xor_sync(0xffffffffu, s2, o);
    if ((tid & 31) == 0) red[tid >> 5] = s2;
    __syncthreads();
    s2 = red[0];
#pragma unroll
    for (int w = 1; w < 8; w++) s2 += red[w];
    const float inv = rsqrtf(s2 * (1.0f / DIN) + 1e-5f);

    const float4 g  = ((const float4*)gamma)[tid];
    const float4 bb = ((const float4*)beta)[tid];
    float4 o4;
    o4.x = d0 * inv * g.x + bb.x;
    o4.y = d1 * inv * g.y + bb.y;
    o4.z = d2 * inv * g.z + bb.z;
    o4.w = d3 * inv * g.w + bb.w;
    ((float4*)(out + row * DIN))[tid] = o4;
}

// ---------------- launch ---------------------------------------------------------
extern "C" void kernel_launch(void* const* d_in, const int* in_sizes, int n_in,
                              void* d_out, int out_size)
{
    const float* input_ = (const float*)d_in[0];
    const float* pos    = (const float*)d_in[1];
    const float* memory = (const float*)d_in[2];
    const float* u      = (const float*)d_in[3];
    const float* vvec   = (const float*)d_in[4];
    // d_in[5] = mask (analytic: j <= i + PREV)
    const float* W_kv   = (const float*)d_in[6];
    const float* W_q    = (const float*)d_in[7];
    const float* W_p    = (const float*)d_in[8];
    const float* W_out  = (const float*)d_in[9];
    const float* gamma  = (const float*)d_in[10];
    const float* beta   = (const float*)d_in[11];
    float* out = (float*)d_out;

    __half *pin, *pmem, *ppos, *pwkv, *pwq, *pwp, *pwo;
    __half *pk, *pv, *pp, *pqu, *pqv, *pawv;
    float* pout;
    cudaGetSymbolAddress((void**)&pin,  g_in16);
    cudaGetSymbolAddress((void**)&pmem, g_mem16);
    cudaGetSymbolAddress((void**)&ppos, g_pos16);
    cudaGetSymbolAddress((void**)&pwkv, g_wkv16);
    cudaGetSymbolAddress((void**)&pwq,  g_wq16);
    cudaGetSymbolAddress((void**)&pwp,  g_wp16);
    cudaGetSymbolAddress((void**)&pwo,  g_wo16);
    cudaGetSymbolAddress((void**)&pk,   g_kh);
    cudaGetSymbolAddress((void**)&pv,   g_vh);
    cudaGetSymbolAddress((void**)&pp,   g_ph);
    cudaGetSymbolAddress((void**)&pqu,  g_qu);
    cudaGetSymbolAddress((void**)&pqv,  g_qv);
    cudaGetSymbolAddress((void**)&pawv, g_awv);
    cudaGetSymbolAddress((void**)&pout, g_out);

    const int GEMM_SMEM = 2 * 18432 + 2 * 17408;   // 71680
    const int FA_SMEM   = 111616;
    cudaFuncSetAttribute(tcgemm_h<0>, cudaFuncAttributeMaxDynamicSharedMemorySize, GEMM_SMEM);
    cudaFuncSetAttribute(tcgemm_h<1>, cudaFuncAttributeMaxDynamicSharedMemorySize, GEMM_SMEM);
    cudaFuncSetAttribute(tcgemm_h<2>, cudaFuncAttributeMaxDynamicSharedMemorySize, GEMM_SMEM);
    cudaFuncSetAttribute(tcgemm_h<3>, cudaFuncAttributeMaxDynamicSharedMemorySize, GEMM_SMEM);
    cudaFuncSetAttribute(flash_attn,  cudaFuncAttributeMaxDynamicSharedMemorySize, FA_SMEM);

    // 0) fp32 -> fp16 conversions, single launch
    CvtSegs segs;
    segs.src[0] = (const float4*)input_; segs.dst[0] = (__half2*)pin;  segs.n4[0] = SEQ * BSZ * DIN / 4;
    segs.src[1] = (const float4*)memory; segs.dst[1] = (__half2*)pmem; segs.n4[1] = PREV * BSZ * DIN / 4;
    segs.src[2] = (const float4*)pos;    segs.dst[2] = (__half2*)ppos; segs.n4[2] = TOT * DIN / 4;
    segs.src[3] = (const float4*)W_kv;   segs.dst[3] = (__half2*)pwkv; segs.n4[3] = DIN * 2 * DIN / 4;
    segs.src[4] = (const float4*)W_q;    segs.dst[4] = (__half2*)pwq;  segs.n4[4] = DIN * DIN / 4;
    segs.src[5] = (const float4*)W_p;    segs.dst[5] = (__half2*)pwp;  segs.n4[5] = DIN * DIN / 4;
    segs.src[6] = (const float4*)W_out;  segs.dst[6] = (__half2*)pwo;  segs.n4[6] = DIN * DIN / 4;
    int total4 = 0;
    for (int k = 0; k < 7; k++) total4 += segs.n4[k];
    cvt_all<<<(total4 + 255) / 256, 256>>>(segs);

    // 1) kv = concat(memory, input_) @ W_kv -> K | V (fp16)
    tcgemm_h<1><<<dim3(16, 64), 256, GEMM_SMEM>>>(
        pmem, pin, PREV * BSZ, DIN, pwkv, 2 * DIN,
        pk, pv, DIN, nullptr, nullptr, nullptr, DIN);

    // 2) qu = input_ @ W_q + u, qv = ... + v (fp16)
    tcgemm_h<2><<<dim3(8, 32), 256, GEMM_SMEM>>>(
        pin, pin, 1 << 30, DIN, pwq, DIN,
        pqu, pqv, DIN, nullptr, u, vvec, DIN);

    // 3) p = pos_embs @ W_p (fp16)
    tcgemm_h<3><<<dim3(8, 8), 256, GEMM_SMEM>>>(
        ppos, ppos, 1 << 30, DIN, pwp, DIN,
        pp, nullptr, DIN, nullptr, nullptr, nullptr, DIN);

    // 4) fused attention -> awv (fp16)
    flash_attn<<<dim3(SEQ / 64, BSZ * NH), 256, FA_SMEM>>>(
        pqu, pqv, pk, pv, pp, pawv);

    // 5) out_pre = input_ + awv @ W_out (fp32)
    tcgemm_h<0><<<dim3(8, 32), 256, GEMM_SMEM>>>(
        pawv, pawv, 1 << 30, DIN, pwo, DIN,
        pout, nullptr, DIN, input_, nullptr, nullptr, DIN);

    // 6) LayerNorm -> d_out
    ln_kernel<<<SEQ * BSZ, 256>>>(pout, gamma, beta, out);
}

// round 9
// speedup vs baseline: 9.8576x; 1.2094x over previous
#include <cuda_runtime.h>
#include <cuda_fp16.h>
#include <math.h>

#define SEQ  512
#define PREV 512
#define TOT  1024
#define BSZ  8
#define DIN  1024
#define NH   16
#define HD   64

// ---------------- scratch (static device globals; no allocations) ----------------
__device__ __half g_in16 [SEQ * BSZ * DIN];
__device__ __half g_mem16[PREV * BSZ * DIN];
__device__ __half g_pos16[TOT * DIN];
__device__ __half g_wkv16[DIN * 2 * DIN];
__device__ __half g_wq16 [DIN * DIN];
__device__ __half g_wp16 [DIN * DIN];
__device__ __half g_wo16 [DIN * DIN];
__device__ __half g_kh [TOT * BSZ * DIN];
__device__ __half g_vh [TOT * BSZ * DIN];
__device__ __half g_ph [TOT * DIN];
__device__ __half g_qu [SEQ * BSZ * DIN];
__device__ __half g_qv [SEQ * BSZ * DIN];
__device__ __half g_awv[SEQ * BSZ * DIN];
__device__ float  g_out[SEQ * BSZ * DIN];

__device__ __forceinline__ unsigned smem_u32(const void* p) {
    return (unsigned)__cvta_generic_to_shared(p);
}
__device__ __forceinline__ void cp16(unsigned dst, const void* src) {
    asm volatile("cp.async.cg.shared.global [%0], [%1], 16;" :: "r"(dst), "l"(src));
}
#define CP_COMMIT() asm volatile("cp.async.commit_group;")
#define CP_WAIT1()  asm volatile("cp.async.wait_group 1;")

#define MMA_F16(c, a, b)                                                       \
    asm volatile(                                                              \
        "mma.sync.aligned.m16n8k16.row.col.f32.f16.f16.f32 "                   \
        "{%0,%1,%2,%3},{%4,%5,%6,%7},{%8,%9},{%0,%1,%2,%3};"                   \
        : "+f"(c[0]), "+f"(c[1]), "+f"(c[2]), "+f"(c[3])                       \
        : "r"(a[0]), "r"(a[1]), "r"(a[2]), "r"(a[3]), "r"(b[0]), "r"(b[1]))

__device__ __forceinline__ void ldmx4t(unsigned& r0, unsigned& r1,
                                       unsigned& r2, unsigned& r3, unsigned a) {
    asm volatile("ldmatrix.sync.aligned.m8n8.x4.trans.shared.b16 "
                 "{%0,%1,%2,%3}, [%4];"
                 : "=r"(r0), "=r"(r1), "=r"(r2), "=r"(r3) : "r"(a));
}

// ---------------- fp32 -> fp16 converter (single segmented launch) --------------
struct CvtSegs {
    const float4* src[7];
    __half2*      dst[7];
    int           n4[7];
};

__global__ void cvt_all(CvtSegs s)
{
    int i = blockIdx.x * blockDim.x + threadIdx.x;
#pragma unroll
    for (int k = 0; k < 7; k++) {
        if (i < s.n4[k]) {
            float4 v = s.src[k][i];
            s.dst[k][2 * i]     = __floats2half2_rn(v.x, v.y);
            s.dst[k][2 * i + 1] = __floats2half2_rn(v.z, v.w);
            return;
        }
        i -= s.n4[k];
    }
}

extern __shared__ char dsm[];

// ============ mega projection GEMM: kv + q + p in ONE launch =====================
// blockIdx.x < 1024 : kv  (M=8192 gather(mem|in), N=2048, split -> kh|vh)
// 1024..1279        : q   (M=4096 in,            N=1024, dual bias -> qu,qv)
// 1280..1343        : p   (M=1024 pos,           N=1024, plain -> ph)
__global__ __launch_bounds__(256, 2) void proj_mega(
    const __half* __restrict__ in16, const __half* __restrict__ mem16,
    const __half* __restrict__ pos16,
    const __half* __restrict__ wkv, const __half* __restrict__ wq,
    const __half* __restrict__ wp,
    __half* __restrict__ kh, __half* __restrict__ vh,
    __half* __restrict__ quo, __half* __restrict__ qvo,
    __half* __restrict__ ph,
    const float* __restrict__ ubias, const float* __restrict__ vbias)
{
    const int bx = blockIdx.x;
    const __half *A0, *A1, *B;
    int M0, row0, col0, epi;
    long ldb;
    if (bx < 1024) {
        row0 = (bx >> 4) * 128; col0 = (bx & 15) * 128;
        A0 = mem16; A1 = in16; M0 = PREV * BSZ; B = wkv; ldb = 2 * DIN; epi = 1;
    } else if (bx < 1280) {
        const int t = bx - 1024;
        row0 = (t >> 3) * 128; col0 = (t & 7) * 128;
        A0 = in16; A1 = in16; M0 = 1 << 30; B = wq; ldb = DIN; epi = 2;
    } else {
        const int t = bx - 1280;
        row0 = (t >> 3) * 128; col0 = (t & 7) * 128;
        A0 = pos16; A1 = pos16; M0 = 1 << 30; B = wp; ldb = DIN; epi = 3;
    }

    const int tid  = threadIdx.x;
    const int lane = tid & 31, wid = tid >> 5;
    const int gid  = lane >> 2, tig = lane & 3;
    const int warp_m = (wid & 3) * 32;
    const int warp_n = (wid >> 2) * 64;

    char* As = dsm;                 // 2 x 18432
    char* Bs = dsm + 2 * 18432;     // 2 x 17408

    float c[2][8][4];
#pragma unroll
    for (int mt = 0; mt < 2; mt++)
#pragma unroll
        for (int nt = 0; nt < 8; nt++)
#pragma unroll
            for (int q = 0; q < 4; q++) c[mt][nt][q] = 0.f;

    auto issue = [&](int k0, int buf) {
        unsigned ab = smem_u32(As + buf * 18432);
        unsigned bb = smem_u32(Bs + buf * 17408);
#pragma unroll
        for (int it = 0; it < 4; it++) {
            const int f = tid + it * 256;
            const int r = f >> 3, u = f & 7;
            const int gm = row0 + r;
            const __half* src = (gm < M0 ? A0 + (size_t)gm * DIN
                                         : A1 + (size_t)(gm - M0) * DIN) + k0 + u * 8;
            cp16(ab + r * 144 + u * 16, src);
        }
#pragma unroll
        for (int it = 0; it < 4; it++) {
            const int f = tid + it * 256;
            const int k = f >> 4, u = f & 15;
            cp16(bb + k * 272 + u * 16, B + (size_t)(k0 + k) * ldb + col0 + u * 8);
        }
    };

    issue(0, 0); CP_COMMIT();
    const int lrow = (lane & 7) + ((lane >> 3) & 1) * 8;
    const int lcol = ((lane >> 4) & 1) * 8;

    for (int kt = 0; kt < 16; kt++) {
        if (kt + 1 < 16) issue((kt + 1) * 64, (kt + 1) & 1);
        CP_COMMIT();
        CP_WAIT1();
        __syncthreads();

        const unsigned* Au = (const unsigned*)(As + (kt & 1) * 18432);
        const unsigned  bb = smem_u32(Bs + (kt & 1) * 17408);
#pragma unroll
        for (int kk = 0; kk < 64; kk += 16) {
            unsigned a[2][4];
#pragma unroll
            for (int mt = 0; mt < 2; mt++) {
                const int m = warp_m + mt * 16 + gid;
                a[mt][0] = Au[m * 36 + kk / 2 + tig];
                a[mt][1] = Au[(m + 8) * 36 + kk / 2 + tig];
                a[mt][2] = Au[m * 36 + kk / 2 + tig + 4];
                a[mt][3] = Au[(m + 8) * 36 + kk / 2 + tig + 4];
            }
#pragma unroll
            for (int p = 0; p < 4; p++) {
                unsigned r0, r1, r2, r3;
                ldmx4t(r0, r1, r2, r3,
                       bb + (kk + lrow) * 272 + (warp_n + p * 16 + lcol) * 2);
                unsigned b0[2] = {r0, r1}, b1[2] = {r2, r3};
#pragma unroll
                for (int mt = 0; mt < 2; mt++) {
                    MMA_F16(c[mt][2 * p],     a[mt], b0);
                    MMA_F16(c[mt][2 * p + 1], a[mt], b1);
                }
            }
        }
        __syncthreads();
    }

#pragma unroll
    for (int mt = 0; mt < 2; mt++) {
#pragma unroll
        for (int nt = 0; nt < 8; nt++) {
            const int cb = col0 + warp_n + nt * 8 + 2 * tig;
#pragma unroll
            for (int hf = 0; hf < 2; hf++) {
                const int r = row0 + warp_m + mt * 16 + gid + 8 * hf;
                float v0 = c[mt][nt][hf * 2], v1 = c[mt][nt][hf * 2 + 1];
                if (epi == 1) {
                    __half2 h = __floats2half2_rn(v0, v1);
                    if (cb < DIN)
                        *(__half2*)(kh + (size_t)r * DIN + cb) = h;
                    else
                        *(__half2*)(vh + (size_t)r * DIN + cb - DIN) = h;
                } else if (epi == 2) {
                    *(__half2*)(quo + (size_t)r * DIN + cb) =
                        __floats2half2_rn(v0 + ubias[cb], v1 + ubias[cb + 1]);
                    *(__half2*)(qvo + (size_t)r * DIN + cb) =
                        __floats2half2_rn(v0 + vbias[cb], v1 + vbias[cb + 1]);
                } else {
                    *(__half2*)(ph + (size_t)r * DIN + cb) =
                        __floats2half2_rn(v0, v1);
                }
            }
        }
    }
}

// ============ output projection GEMM (fp32 out + residual) =======================
__global__ __launch_bounds__(256, 2) void out_gemm(
    const __half* __restrict__ A, const __half* __restrict__ B,
    float* __restrict__ O, const float* __restrict__ resid)
{
    const int tid  = threadIdx.x;
    const int lane = tid & 31, wid = tid >> 5;
    const int gid  = lane >> 2, tig = lane & 3;
    const int warp_m = (wid & 3) * 32;
    const int warp_n = (wid >> 2) * 64;
    const int row0 = blockIdx.y * 128;
    const int col0 = blockIdx.x * 128;

    char* As = dsm;
    char* Bs = dsm + 2 * 18432;

    float c[2][8][4];
#pragma unroll
    for (int mt = 0; mt < 2; mt++)
#pragma unroll
        for (int nt = 0; nt < 8; nt++)
#pragma unroll
            for (int q = 0; q < 4; q++) c[mt][nt][q] = 0.f;

    auto issue = [&](int k0, int buf) {
        unsigned ab = smem_u32(As + buf * 18432);
        unsigned bb = smem_u32(Bs + buf * 17408);
#pragma unroll
        for (int it = 0; it < 4; it++) {
            const int f = tid + it * 256;
            const int r = f >> 3, u = f & 7;
            cp16(ab + r * 144 + u * 16, A + (size_t)(row0 + r) * DIN + k0 + u * 8);
        }
#pragma unroll
        for (int it = 0; it < 4; it++) {
            const int f = tid + it * 256;
            const int k = f >> 4, u = f & 15;
            cp16(bb + k * 272 + u * 16, B + (size_t)(k0 + k) * DIN + col0 + u * 8);
        }
    };

    issue(0, 0); CP_COMMIT();
    const int lrow = (lane & 7) + ((lane >> 3) & 1) * 8;
    const int lcol = ((lane >> 4) & 1) * 8;

    for (int kt = 0; kt < 16; kt++) {
        if (kt + 1 < 16) issue((kt + 1) * 64, (kt + 1) & 1);
        CP_COMMIT();
        CP_WAIT1();
        __syncthreads();

        const unsigned* Au = (const unsigned*)(As + (kt & 1) * 18432);
        const unsigned  bb = smem_u32(Bs + (kt & 1) * 17408);
#pragma unroll
        for (int kk = 0; kk < 64; kk += 16) {
            unsigned a[2][4];
#pragma unroll
            for (int mt = 0; mt < 2; mt++) {
                const int m = warp_m + mt * 16 + gid;
                a[mt][0] = Au[m * 36 + kk / 2 + tig];
                a[mt][1] = Au[(m + 8) * 36 + kk / 2 + tig];
                a[mt][2] = Au[m * 36 + kk / 2 + tig + 4];
                a[mt][3] = Au[(m + 8) * 36 + kk / 2 + tig + 4];
            }
#pragma unroll
            for (int p = 0; p < 4; p++) {
                unsigned r0, r1, r2, r3;
                ldmx4t(r0, r1, r2, r3,
                       bb + (kk + lrow) * 272 + (warp_n + p * 16 + lcol) * 2);
                unsigned b0[2] = {r0, r1}, b1[2] = {r2, r3};
#pragma unroll
                for (int mt = 0; mt < 2; mt++) {
                    MMA_F16(c[mt][2 * p],     a[mt], b0);
                    MMA_F16(c[mt][2 * p + 1], a[mt], b1);
                }
            }
        }
        __syncthreads();
    }

#pragma unroll
    for (int mt = 0; mt < 2; mt++)
#pragma unroll
        for (int nt = 0; nt < 8; nt++) {
            const int cb = col0 + warp_n + nt * 8 + 2 * tig;
#pragma unroll
            for (int hf = 0; hf < 2; hf++) {
                const int r = row0 + warp_m + mt * 16 + gid + 8 * hf;
                O[(size_t)r * DIN + cb]     = c[mt][nt][hf * 2]     + resid[(size_t)r * DIN + cb];
                O[(size_t)r * DIN + cb + 1] = c[mt][nt][hf * 2 + 1] + resid[(size_t)r * DIN + cb + 1];
            }
        }
}

// ============ fused flash attention, FA2 layout (m-split warps) ==================
// Block: one (b,h), 128 q-rows, 8 warps each owning 16 full rows.
// smem (96256 B): sK 2x9216 @0 | sV 2x9216 @18432 | P ring 256x144 @36864
//                 sSp 8 x (16 x 88 half) @73728
__global__ __launch_bounds__(256, 2) void flash_attn(
    const __half* __restrict__ qug, const __half* __restrict__ qvg,
    const __half* __restrict__ kg,  const __half* __restrict__ vg,
    const __half* __restrict__ pg,  __half* __restrict__ awv)
{
    char* base = dsm;
    char* sKb = base;
    char* sVb = base + 18432;
    char* sPr = base + 36864;
    const unsigned* Pring = (const unsigned*)sPr;

    const int tid = threadIdx.x;
    const int lane = tid & 31, wid = tid >> 5;
    const int gid = lane >> 2, tig = lane & 3;
    const int i0 = (3 - (int)blockIdx.x) * 128;     // heavy tiles first
    const int bh = blockIdx.y;
    const int b = bh >> 4, h = bh & 15;
    const int lrow = (lane & 7) + ((lane >> 3) & 1) * 8;
    const int lcol = ((lane >> 4) & 1) * 8;
    const int rb0 = 384 - i0;                       // P window base at step 0
    const int nsteps = i0 / 64 + 10;

    __half* sSpW = (__half*)(base + 73728 + wid * 2816);   // 16 x 88 halves

    // ---- prologue: issue step-0 group (P rows rb0..rb0+191, K/V j0=0) ----
    {
#pragma unroll
        for (int it = 0; it < 6; it++) {
            const int f = tid + it * 256;
            const int rl = f >> 3, u = f & 7;
            const int r = rb0 + rl;
            const int slot = r & 255;
            const int src = min(r, TOT - 1);
            cp16(smem_u32(sPr + slot * 144 + u * 16),
                 pg + (size_t)src * DIN + h * HD + u * 8);
        }
        const __half* kb = kg + (size_t)b * DIN + h * HD;
        const __half* vb = vg + (size_t)b * DIN + h * HD;
#pragma unroll
        for (int it = 0; it < 2; it++) {
            const int f = tid + it * 256;
            const int r = f >> 3, u = f & 7;
            cp16(smem_u32(sKb + r * 144 + u * 16), kb + (size_t)r * BSZ * DIN + u * 8);
            cp16(smem_u32(sVb + r * 144 + u * 16), vb + (size_t)r * BSZ * DIN + u * 8);
        }
        CP_COMMIT();
    }

    // ---- Q fragments: load from global into registers (held all kernel) ----
    unsigned qu_f[4][4], qv_f[4][4];
    {
        const int r0 = i0 + wid * 16 + gid;
        const __half* a0 = qug + ((size_t)r0 * BSZ + b) * DIN + h * HD;
        const __half* a8 = a0 + (size_t)8 * BSZ * DIN;
        const __half* v0 = qvg + ((size_t)r0 * BSZ + b) * DIN + h * HD;
        const __half* v8 = v0 + (size_t)8 * BSZ * DIN;
#pragma unroll
        for (int kc = 0; kc < 4; kc++) {
            qu_f[kc][0] = *(const unsigned*)(a0 + kc * 16 + 2 * tig);
            qu_f[kc][1] = *(const unsigned*)(a8 + kc * 16 + 2 * tig);
            qu_f[kc][2] = *(const unsigned*)(a0 + kc * 16 + 8 + 2 * tig);
            qu_f[kc][3] = *(const unsigned*)(a8 + kc * 16 + 8 + 2 * tig);
            qv_f[kc][0] = *(const unsigned*)(v0 + kc * 16 + 2 * tig);
            qv_f[kc][1] = *(const unsigned*)(v8 + kc * 16 + 2 * tig);
            qv_f[kc][2] = *(const unsigned*)(v0 + kc * 16 + 8 + 2 * tig);
            qv_f[kc][3] = *(const unsigned*)(v8 + kc * 16 + 8 + 2 * tig);
        }
    }

    float o[8][4];
#pragma unroll
    for (int nt = 0; nt < 8; nt++)
#pragma unroll
        for (int e = 0; e < 4; e++) o[nt][e] = 0.f;
    float l0 = 0.f, l1 = 0.f;

    for (int s = 0; s < nsteps; s++) {
        const int j0 = s * 64;
        if (s + 1 < nsteps) {
            const int buf = (s + 1) & 1;
            const __half* kb = kg + ((size_t)(j0 + 64) * BSZ + b) * DIN + h * HD;
            const __half* vb = vg + ((size_t)(j0 + 64) * BSZ + b) * DIN + h * HD;
            const unsigned kd = smem_u32(sKb + buf * 9216);
            const unsigned vd = smem_u32(sVb + buf * 9216);
#pragma unroll
            for (int it = 0; it < 2; it++) {
                const int f = tid + it * 256;
                const int r = f >> 3, u = f & 7;
                cp16(kd + r * 144 + u * 16, kb + (size_t)r * BSZ * DIN + u * 8);
                cp16(vd + r * 144 + u * 16, vb + (size_t)r * BSZ * DIN + u * 8);
            }
            const int wb = rb0 + 64 * (s + 1) + 128;   // new 64 P rows for window s+1
#pragma unroll
            for (int it = 0; it < 2; it++) {
                const int f = tid + it * 256;
                const int rl = f >> 3, u = f & 7;
                const int r = wb + rl;
                const int slot = r & 255;
                const int src = min(r, TOT - 1);
                cp16(smem_u32(sPr + slot * 144 + u * 16),
                     pg + (size_t)src * DIN + h * HD + u * 8);
            }
        }
        CP_COMMIT();
        CP_WAIT1();
        __syncthreads();

        const int di = i0 + 16 * wid + 512 - j0;       // mask: lj <= di + li
        if (di + 15 >= 0) {                            // warp has unmasked work
            const unsigned* Ku = (const unsigned*)(sKb + (s & 1) * 9216);
            const unsigned  vB = smem_u32(sVb + (s & 1) * 9216);

            // ---- S_p = Qv_warp(16x64) @ P_slice(80x64)^T, staged in 2 halves ----
            const int rsg = j0 + 496 - i0 - 16 * wid + gid;   // ring row for this gid
#pragma unroll
            for (int half = 0; half < 2; half++) {
                float cp5[5][4];
#pragma unroll
                for (int nt = 0; nt < 5; nt++)
#pragma unroll
                    for (int e = 0; e < 4; e++) cp5[nt][e] = 0.f;
#pragma unroll
                for (int kc = 0; kc < 4; kc++) {
#pragma unroll
                    for (int nt = 0; nt < 5; nt++) {
                        const int slot = (rsg + half * 40 + nt * 8) & 255;
                        unsigned bf[2];
                        bf[0] = Pring[slot * 36 + kc * 8 + tig];
                        bf[1] = Pring[slot * 36 + kc * 8 + tig + 4];
                        MMA_F16(cp5[nt], qv_f[kc], bf);
                    }
                }
#pragma unroll
                for (int nt = 0; nt < 5; nt++) {
                    const int cn = (half * 5 + nt) * 8 + 2 * tig;
                    *(__half2*)&sSpW[gid * 88 + cn] =
                        __floats2half2_rn(cp5[nt][0], cp5[nt][1]);
                    *(__half2*)&sSpW[(gid + 8) * 88 + cn] =
                        __floats2half2_rn(cp5[nt][2], cp5[nt][3]);
                }
            }
            __syncwarp();

            // ---- S_c = Qu_warp(16x64) @ K^T(64x64) ----
            float cc[8][4];
#pragma unroll
            for (int nt = 0; nt < 8; nt++)
#pragma unroll
                for (int e = 0; e < 4; e++) cc[nt][e] = 0.f;
#pragma unroll
            for (int kc = 0; kc < 4; kc++)
#pragma unroll
                for (int nt = 0; nt < 8; nt++) {
                    unsigned bf[2];
                    bf[0] = Ku[(nt * 8 + gid) * 36 + kc * 8 + tig];
                    bf[1] = Ku[(nt * 8 + gid) * 36 + kc * 8 + tig + 4];
                    MMA_F16(cc[nt], qu_f[kc], bf);
                }

            // ---- combine + mask + exp (no-max) + pack; accumulate row sums ----
            unsigned pa[4][4];
            float ls0 = 0.f, ls1 = 0.f;
#pragma unroll
            for (int nt = 0; nt < 8; nt++) {
                const int lj = nt * 8 + 2 * tig;
                const int liA = gid, liB = gid + 8;
                float spA0 = __half2float(sSpW[liA * 88 + lj + 15 - liA]);
                float spA1 = __half2float(sSpW[liA * 88 + lj + 16 - liA]);
                float spB0 = __half2float(sSpW[liB * 88 + lj + 15 - liB]);
                float spB1 = __half2float(sSpW[liB * 88 + lj + 16 - liB]);
                float eA0 = (lj     <= di + liA) ? __expf((cc[nt][0] + spA0) * 0.125f) : 0.f;
                float eA1 = (lj + 1 <= di + liA) ? __expf((cc[nt][1] + spA1) * 0.125f) : 0.f;
                float eB0 = (lj     <= di + liB) ? __expf((cc[nt][2] + spB0) * 0.125f) : 0.f;
                float eB1 = (lj + 1 <= di + liB) ? __expf((cc[nt][3] + spB1) * 0.125f) : 0.f;
                ls0 += eA0 + eA1;
                ls1 += eB0 + eB1;
                __half2 hA = __floats2half2_rn(eA0, eA1);
                __half2 hB = __floats2half2_rn(eB0, eB1);
                pa[nt >> 1][(nt & 1) * 2]     = *(unsigned*)&hA;
                pa[nt >> 1][(nt & 1) * 2 + 1] = *(unsigned*)&hB;
            }
            ls0 += __shfl_xor_sync(0xffffffffu, ls0, 1);
            ls0 += __shfl_xor_sync(0xffffffffu, ls0, 2);
            ls1 += __shfl_xor_sync(0xffffffffu, ls1, 1);
            ls1 += __shfl_xor_sync(0xffffffffu, ls1, 2);
            l0 += ls0; l1 += ls1;

            // ---- O += P @ V (probs already in A-fragment registers) ----
#pragma unroll
            for (int kc = 0; kc < 4; kc++) {
#pragma unroll
                for (int np = 0; np < 4; np++) {
                    unsigned r0, r1, r2, r3;
                    ldmx4t(r0, r1, r2, r3,
                           vB + (kc * 16 + lrow) * 144 + (np * 16 + lcol) * 2);
                    unsigned b0[2] = {r0, r1}, b1[2] = {r2, r3};
                    MMA_F16(o[2 * np],     pa[kc], b0);
                    MMA_F16(o[2 * np + 1], pa[kc], b1);
                }
            }
        }
        __syncthreads();   // buffers + ring + sSp free for next step
    }

    // ---- write awv = O / l (fp16) ----
    const float inv0 = 1.f / l0, inv1 = 1.f / l1;
    const int r0 = i0 + wid * 16 + gid;
#pragma unroll
    for (int nt = 0; nt < 8; nt++) {
        const int c = nt * 8 + 2 * tig;
        *(__half2*)&awv[((size_t)r0 * BSZ + b) * DIN + h * HD + c] =
            __floats2half2_rn(o[nt][0] * inv0, o[nt][1] * inv0);
        *(__half2*)&awv[((size_t)(r0 + 8) * BSZ + b) * DIN + h * HD + c] =
            __floats2half2_rn(o[nt][2] * inv1, o[nt][3] * inv1);
    }
}

// ---------------- LayerNorm over last dim (1024), one block per row ------------
__global__ __launch_bounds__(256) void ln_kernel(
    const float* __restrict__ x, const float* __restrict__ gamma,
    const float* __restrict__ beta, float* __restrict__ out)
{
    const size_t row = blockIdx.x;
    const int tid = threadIdx.x;
    const float4 v = ((const float4*)(x + row * DIN))[tid];
    __shared__ float red[8];

    float s = v.x + v.y + v.z + v.w;
#pragma unroll
    for (int o = 16; o; o >>= 1) s += __shfl_xor_sync(0xffffffffu, s, o);
    if ((tid & 31) == 0) red[tid >> 5] = s;
    __syncthreads();
    s = red[0];
#pragma unroll
    for (int w = 1; w < 8; w++) s += red[w];
    const float mu = s * (1.0f / DIN);
    __syncthreads();

    const float d0 = v.x - mu, d1 = v.y - mu, d2 = v.z - mu, d3 = v.w - mu;
    float s2 = d0 * d0 + d1 * d1 + d2 * d2 + d3 * d3;
#pragma unroll
    for (int o = 16; o; o >>= 1) s2 += __shfl_xor_sync(0xffffffffu, s2, o);
    if ((tid & 31) == 0) red[tid >> 5] = s2;
    __syncthreads();
    s2 = red[0];
#pragma unroll
    for (int w = 1; w < 8; w++) s2 += red[w];
    const float inv = rsqrtf(s2 * (1.0f / DIN) + 1e-5f);

    const float4 g  = ((const float4*)gamma)[tid];
    const float4 bb = ((const float4*)beta)[tid];
    float4 o4;
    o4.x = d0 * inv * g.x + bb.x;
    o4.y = d1 * inv * g.y + bb.y;
    o4.z = d2 * inv * g.z + bb.z;
    o4.w = d3 * inv * g.w + bb.w;
    ((float4*)(out + row * DIN))[tid] = o4;
}

// ---------------- launch ---------------------------------------------------------
extern "C" void kernel_launch(void* const* d_in, const int* in_sizes, int n_in,
                              void* d_out, int out_size)
{
    const float* input_ = (const float*)d_in[0];
    const float* pos    = (const float*)d_in[1];
    const float* memory = (const float*)d_in[2];
    const float* u      = (const float*)d_in[3];
    const float* vvec   = (const float*)d_in[4];
    // d_in[5] = mask (analytic: j <= i + PREV)
    const float* W_kv   = (const float*)d_in[6];
    const float* W_q    = (const float*)d_in[7];
    const float* W_p    = (const float*)d_in[8];
    const float* W_out  = (const float*)d_in[9];
    const float* gamma  = (const float*)d_in[10];
    const float* beta   = (const float*)d_in[11];
    float* out = (float*)d_out;

    __half *pin, *pmem, *ppos, *pwkv, *pwq, *pwp, *pwo;
    __half *pk, *pv, *pp, *pqu, *pqv, *pawv;
    float* pout;
    cudaGetSymbolAddress((void**)&pin,  g_in16);
    cudaGetSymbolAddress((void**)&pmem, g_mem16);
    cudaGetSymbolAddress((void**)&ppos, g_pos16);
    cudaGetSymbolAddress((void**)&pwkv, g_wkv16);
    cudaGetSymbolAddress((void**)&pwq,  g_wq16);
    cudaGetSymbolAddress((void**)&pwp,  g_wp16);
    cudaGetSymbolAddress((void**)&pwo,  g_wo16);
    cudaGetSymbolAddress((void**)&pk,   g_kh);
    cudaGetSymbolAddress((void**)&pv,   g_vh);
    cudaGetSymbolAddress((void**)&pp,   g_ph);
    cudaGetSymbolAddress((void**)&pqu,  g_qu);
    cudaGetSymbolAddress((void**)&pqv,  g_qv);
    cudaGetSymbolAddress((void**)&pawv, g_awv);
    cudaGetSymbolAddress((void**)&pout, g_out);

    const int GEMM_SMEM = 2 * 18432 + 2 * 17408;   // 71680
    const int FA_SMEM   = 96256;
    cudaFuncSetAttribute(proj_mega, cudaFuncAttributeMaxDynamicSharedMemorySize, GEMM_SMEM);
    cudaFuncSetAttribute(out_gemm,  cudaFuncAttributeMaxDynamicSharedMemorySize, GEMM_SMEM);
    cudaFuncSetAttribute(flash_attn, cudaFuncAttributeMaxDynamicSharedMemorySize, FA_SMEM);

    // 0) fp32 -> fp16 conversions, single launch
    CvtSegs segs;
    segs.src[0] = (const float4*)input_; segs.dst[0] = (__half2*)pin;  segs.n4[0] = SEQ * BSZ * DIN / 4;
    segs.src[1] = (const float4*)memory; segs.dst[1] = (__half2*)pmem; segs.n4[1] = PREV * BSZ * DIN / 4;
    segs.src[2] = (const float4*)pos;    segs.dst[2] = (__half2*)ppos; segs.n4[2] = TOT * DIN / 4;
    segs.src[3] = (const float4*)W_kv;   segs.dst[3] = (__half2*)pwkv; segs.n4[3] = DIN * 2 * DIN / 4;
    segs.src[4] = (const float4*)W_q;    segs.dst[4] = (__half2*)pwq;  segs.n4[4] = DIN * DIN / 4;
    segs.src[5] = (const float4*)W_p;    segs.dst[5] = (__half2*)pwp;  segs.n4[5] = DIN * DIN / 4;
    segs.src[6] = (const float4*)W_out;  segs.dst[6] = (__half2*)pwo;  segs.n4[6] = DIN * DIN / 4;
    int total4 = 0;
    for (int k = 0; k < 7; k++) total4 += segs.n4[k];
    cvt_all<<<(total4 + 255) / 256, 256>>>(segs);

    // 1) all projections (kv | q | p) in one launch
    proj_mega<<<1344, 256, GEMM_SMEM>>>(
        pin, pmem, ppos, pwkv, pwq, pwp,
        pk, pv, pqu, pqv, pp, u, vvec);

    // 2) fused attention -> awv (fp16)
    flash_attn<<<dim3(4, BSZ * NH), 256, FA_SMEM>>>(
        pqu, pqv, pk, pv, pp, pawv);

    // 3) out_pre = input_ + awv @ W_out (fp32)
    out_gemm<<<dim3(8, 32), 256, GEMM_SMEM>>>(pawv, pwo, pout, input_);

    // 4) LayerNorm -> d_out
    ln_kernel<<<SEQ * BSZ, 256>>>(pout, gamma, beta, out);
}

// round 11
// speedup vs baseline: 10.5249x; 1.0677x over previous
#include <cuda_runtime.h>
#include <cuda_fp16.h>
#include <math.h>

#define SEQ  512
#define PREV 512
#define TOT  1024
#define BSZ  8
#define DIN  1024
#define NH   16
#define HD   64

// ---------------- scratch (static device globals; no allocations) ----------------
__device__ __half g_in16 [SEQ * BSZ * DIN];
__device__ __half g_mem16[PREV * BSZ * DIN];
__device__ __half g_pos16[TOT * DIN];
__device__ __half g_wkv16[DIN * 2 * DIN];
__device__ __half g_wq16 [DIN * DIN];
__device__ __half g_wp16 [DIN * DIN];
__device__ __half g_wo16 [DIN * DIN];
__device__ __half g_kh [TOT * BSZ * DIN];
__device__ __half g_vh [TOT * BSZ * DIN];
__device__ __half g_ph [TOT * DIN];
__device__ __half g_qu [SEQ * BSZ * DIN];
__device__ __half g_qv [SEQ * BSZ * DIN];
__device__ __half g_awv[SEQ * BSZ * DIN];
__device__ float  g_out[SEQ * BSZ * DIN];

__device__ __forceinline__ unsigned smem_u32(const void* p) {
    return (unsigned)__cvta_generic_to_shared(p);
}
__device__ __forceinline__ void cp16(unsigned dst, const void* src) {
    asm volatile("cp.async.cg.shared.global [%0], [%1], 16;" :: "r"(dst), "l"(src));
}
#define CP_COMMIT() asm volatile("cp.async.commit_group;")
#define CP_WAIT1()  asm volatile("cp.async.wait_group 1;")
#define CP_WAIT2()  asm volatile("cp.async.wait_group 2;")

#define MMA_F16(c, a, b)                                                       \
    asm volatile(                                                              \
        "mma.sync.aligned.m16n8k16.row.col.f32.f16.f16.f32 "                   \
        "{%0,%1,%2,%3},{%4,%5,%6,%7},{%8,%9},{%0,%1,%2,%3};"                   \
        : "+f"(c[0]), "+f"(c[1]), "+f"(c[2]), "+f"(c[3])                       \
        : "r"(a[0]), "r"(a[1]), "r"(a[2]), "r"(a[3]), "r"(b[0]), "r"(b[1]))

__device__ __forceinline__ void ldmx4t(unsigned& r0, unsigned& r1,
                                       unsigned& r2, unsigned& r3, unsigned a) {
    asm volatile("ldmatrix.sync.aligned.m8n8.x4.trans.shared.b16 "
                 "{%0,%1,%2,%3}, [%4];"
                 : "=r"(r0), "=r"(r1), "=r"(r2), "=r"(r3) : "r"(a));
}
__device__ __forceinline__ void ldmx4(unsigned& r0, unsigned& r1,
                                      unsigned& r2, unsigned& r3, unsigned a) {
    asm volatile("ldmatrix.sync.aligned.m8n8.x4.shared.b16 "
                 "{%0,%1,%2,%3}, [%4];"
                 : "=r"(r0), "=r"(r1), "=r"(r2), "=r"(r3) : "r"(a));
}

// ---------------- fp32 -> fp16 converter (single segmented launch) --------------
struct CvtSegs {
    const float4* src[7];
    __half2*      dst[7];
    int           n4[7];
};

__global__ void cvt_all(CvtSegs s)
{
    int i = blockIdx.x * blockDim.x + threadIdx.x;
#pragma unroll
    for (int k = 0; k < 7; k++) {
        if (i < s.n4[k]) {
            float4 v = s.src[k][i];
            s.dst[k][2 * i]     = __floats2half2_rn(v.x, v.y);
            s.dst[k][2 * i + 1] = __floats2half2_rn(v.z, v.w);
            return;
        }
        i -= s.n4[k];
    }
}

extern __shared__ char dsm[];

// A stage: 128 rows x 80 B (stride 80 = 16-aligned, ldmatrix conflict-free).
// B stage: 32 rows x 272 B.
#define AST 80
#define A_STAGE (128 * AST)    // 10240
#define B_STAGE (32 * 272)     // 8704

// ============ mega projection GEMM: kv + q + p in ONE launch =====================
// 4-stage cp.async pipeline, BK=32, one barrier per k-iter, A via ldmatrix.x4.
// blockIdx.x < 1024 : kv  (M=8192 gather(mem|in), N=2048, split -> kh|vh)
// 1024..1279        : q   (M=4096 in,            N=1024, dual bias -> qu,qv)
// 1280..1343        : p   (M=1024 pos,           N=1024, plain -> ph)
__global__ __launch_bounds__(256, 2) void proj_mega(
    const __half* __restrict__ in16, const __half* __restrict__ mem16,
    const __half* __restrict__ pos16,
    const __half* __restrict__ wkv, const __half* __restrict__ wq,
    const __half* __restrict__ wp,
    __half* __restrict__ kh, __half* __restrict__ vh,
    __half* __restrict__ quo, __half* __restrict__ qvo,
    __half* __restrict__ ph,
    const float* __restrict__ ubias, const float* __restrict__ vbias)
{
    const int bx = blockIdx.x;
    const __half *A0, *A1, *B;
    int M0, row0, col0, epi;
    long ldb;
    if (bx < 1024) {
        row0 = (bx >> 4) * 128; col0 = (bx & 15) * 128;
        A0 = mem16; A1 = in16; M0 = PREV * BSZ; B = wkv; ldb = 2 * DIN; epi = 1;
    } else if (bx < 1280) {
        const int t = bx - 1024;
        row0 = (t >> 3) * 128; col0 = (t & 7) * 128;
        A0 = in16; A1 = in16; M0 = 1 << 30; B = wq; ldb = DIN; epi = 2;
    } else {
        const int t = bx - 1280;
        row0 = (t >> 3) * 128; col0 = (t & 7) * 128;
        A0 = pos16; A1 = pos16; M0 = 1 << 30; B = wp; ldb = DIN; epi = 3;
    }

    const int tid  = threadIdx.x;
    const int lane = tid & 31, wid = tid >> 5;
    const int gid  = lane >> 2, tig = lane & 3;
    const int warp_m = (wid & 3) * 32;
    const int warp_n = (wid >> 2) * 64;

    char* As = dsm;                   // 4 x A_STAGE
    char* Bs = dsm + 4 * A_STAGE;     // 4 x B_STAGE

    float c[2][8][4];
#pragma unroll
    for (int mt = 0; mt < 2; mt++)
#pragma unroll
        for (int nt = 0; nt < 8; nt++)
#pragma unroll
            for (int q = 0; q < 4; q++) c[mt][nt][q] = 0.f;

    auto issue = [&](int k0, int buf) {
        unsigned ab = smem_u32(As + buf * A_STAGE);
        unsigned bb = smem_u32(Bs + buf * B_STAGE);
#pragma unroll
        for (int it = 0; it < 2; it++) {
            const int f = tid + it * 256;
            const int r = f >> 2, u = f & 3;
            const int gm = row0 + r;
            const __half* src = (gm < M0 ? A0 + (size_t)gm * DIN
                                         : A1 + (size_t)(gm - M0) * DIN) + k0 + u * 8;
            cp16(ab + r * AST + u * 16, src);
        }
#pragma unroll
        for (int it = 0; it < 2; it++) {
            const int f = tid + it * 256;
            const int k = f >> 4, u = f & 15;
            cp16(bb + k * 272 + u * 16, B + (size_t)(k0 + k) * ldb + col0 + u * 8);
        }
    };

    issue(0, 0);  CP_COMMIT();
    issue(32, 1); CP_COMMIT();

    const int lrow = (lane & 7) + ((lane >> 3) & 1) * 8;
    const int lcol = ((lane >> 4) & 1) * 8;
    const int aoff = (warp_m + (lane & 15)) * AST + (lane >> 4) * 16;

    for (int kt = 0; kt < 32; kt++) {
        if (kt + 2 < 32) issue((kt + 2) * 32, (kt + 2) & 3);
        CP_COMMIT();
        CP_WAIT2();
        __syncthreads();

        const unsigned ab = smem_u32(As + (kt & 3) * A_STAGE);
        const unsigned bb = smem_u32(Bs + (kt & 3) * B_STAGE);
#pragma unroll
        for (int kc = 0; kc < 2; kc++) {
            unsigned a[2][4];
#pragma unroll
            for (int mt = 0; mt < 2; mt++)
                ldmx4(a[mt][0], a[mt][1], a[mt][2], a[mt][3],
                      ab + aoff + mt * 16 * AST + kc * 32);
#pragma unroll
            for (int p = 0; p < 4; p++) {
                unsigned r0, r1, r2, r3;
                ldmx4t(r0, r1, r2, r3,
                       bb + (kc * 16 + lrow) * 272 + (warp_n + p * 16 + lcol) * 2);
                unsigned b0[2] = {r0, r1}, b1[2] = {r2, r3};
#pragma unroll
                for (int mt = 0; mt < 2; mt++) {
                    MMA_F16(c[mt][2 * p],     a[mt], b0);
                    MMA_F16(c[mt][2 * p + 1], a[mt], b1);
                }
            }
        }
    }

#pragma unroll
    for (int mt = 0; mt < 2; mt++) {
#pragma unroll
        for (int nt = 0; nt < 8; nt++) {
            const int cb = col0 + warp_n + nt * 8 + 2 * tig;
#pragma unroll
            for (int hf = 0; hf < 2; hf++) {
                const int r = row0 + warp_m + mt * 16 + gid + 8 * hf;
                float v0 = c[mt][nt][hf * 2], v1 = c[mt][nt][hf * 2 + 1];
                if (epi == 1) {
                    __half2 h = __floats2half2_rn(v0, v1);
                    if (cb < DIN)
                        *(__half2*)(kh + (size_t)r * DIN + cb) = h;
                    else
                        *(__half2*)(vh + (size_t)r * DIN + cb - DIN) = h;
                } else if (epi == 2) {
                    *(__half2*)(quo + (size_t)r * DIN + cb) =
                        __floats2half2_rn(v0 + ubias[cb], v1 + ubias[cb + 1]);
                    *(__half2*)(qvo + (size_t)r * DIN + cb) =
                        __floats2half2_rn(v0 + vbias[cb], v1 + vbias[cb + 1]);
                } else {
                    *(__half2*)(ph + (size_t)r * DIN + cb) =
                        __floats2half2_rn(v0, v1);
                }
            }
        }
    }
}

// ============ output projection GEMM (fp32 out + residual), same pipeline ========
__global__ __launch_bounds__(256, 2) void out_gemm(
    const __half* __restrict__ A, const __half* __restrict__ B,
    float* __restrict__ O, const float* __restrict__ resid)
{
    const int tid  = threadIdx.x;
    const int lane = tid & 31, wid = tid >> 5;
    const int gid  = lane >> 2, tig = lane & 3;
    const int warp_m = (wid & 3) * 32;
    const int warp_n = (wid >> 2) * 64;
    const int row0 = blockIdx.y * 128;
    const int col0 = blockIdx.x * 128;

    char* As = dsm;
    char* Bs = dsm + 4 * A_STAGE;

    float c[2][8][4];
#pragma unroll
    for (int mt = 0; mt < 2; mt++)
#pragma unroll
        for (int nt = 0; nt < 8; nt++)
#pragma unroll
            for (int q = 0; q < 4; q++) c[mt][nt][q] = 0.f;

    auto issue = [&](int k0, int buf) {
        unsigned ab = smem_u32(As + buf * A_STAGE);
        unsigned bb = smem_u32(Bs + buf * B_STAGE);
#pragma unroll
        for (int it = 0; it < 2; it++) {
            const int f = tid + it * 256;
            const int r = f >> 2, u = f & 3;
            cp16(ab + r * AST + u * 16, A + (size_t)(row0 + r) * DIN + k0 + u * 8);
        }
#pragma unroll
        for (int it = 0; it < 2; it++) {
            const int f = tid + it * 256;
            const int k = f >> 4, u = f & 15;
            cp16(bb + k * 272 + u * 16, B + (size_t)(k0 + k) * DIN + col0 + u * 8);
        }
    };

    issue(0, 0);  CP_COMMIT();
    issue(32, 1); CP_COMMIT();

    const int lrow = (lane & 7) + ((lane >> 3) & 1) * 8;
    const int lcol = ((lane >> 4) & 1) * 8;
    const int aoff = (warp_m + (lane & 15)) * AST + (lane >> 4) * 16;

    for (int kt = 0; kt < 32; kt++) {
        if (kt + 2 < 32) issue((kt + 2) * 32, (kt + 2) & 3);
        CP_COMMIT();
        CP_WAIT2();
        __syncthreads();

        const unsigned ab = smem_u32(As + (kt & 3) * A_STAGE);
        const unsigned bb = smem_u32(Bs + (kt & 3) * B_STAGE);
#pragma unroll
        for (int kc = 0; kc < 2; kc++) {
            unsigned a[2][4];
#pragma unroll
            for (int mt = 0; mt < 2; mt++)
                ldmx4(a[mt][0], a[mt][1], a[mt][2], a[mt][3],
                      ab + aoff + mt * 16 * AST + kc * 32);
#pragma unroll
            for (int p = 0; p < 4; p++) {
                unsigned r0, r1, r2, r3;
                ldmx4t(r0, r1, r2, r3,
                       bb + (kc * 16 + lrow) * 272 + (warp_n + p * 16 + lcol) * 2);
                unsigned b0[2] = {r0, r1}, b1[2] = {r2, r3};
#pragma unroll
                for (int mt = 0; mt < 2; mt++) {
                    MMA_F16(c[mt][2 * p],     a[mt], b0);
                    MMA_F16(c[mt][2 * p + 1], a[mt], b1);
                }
            }
        }
    }

#pragma unroll
    for (int mt = 0; mt < 2; mt++)
#pragma unroll
        for (int nt = 0; nt < 8; nt++) {
            const int cb = col0 + warp_n + nt * 8 + 2 * tig;
#pragma unroll
            for (int hf = 0; hf < 2; hf++) {
                const int r = row0 + warp_m + mt * 16 + gid + 8 * hf;
                O[(size_t)r * DIN + cb]     = c[mt][nt][hf * 2]     + resid[(size_t)r * DIN + cb];
                O[(size_t)r * DIN + cb + 1] = c[mt][nt][hf * 2 + 1] + resid[(size_t)r * DIN + cb + 1];
            }
        }
}

// ============ fused flash attention, FA2 layout (m-split warps) — proven R9 ======
// Block: one (b,h), 128 q-rows, 8 warps each owning 16 full rows.
// smem (96256 B): sK 2x9216 @0 | sV 2x9216 @18432 | P ring 256x144 @36864
//                 sSp 8 x (16 x 88 half) @73728
__global__ __launch_bounds__(256, 2) void flash_attn(
    const __half* __restrict__ qug, const __half* __restrict__ qvg,
    const __half* __restrict__ kg,  const __half* __restrict__ vg,
    const __half* __restrict__ pg,  __half* __restrict__ awv)
{
    char* base = dsm;
    char* sKb = base;
    char* sVb = base + 18432;
    char* sPr = base + 36864;
    const unsigned* Pring = (const unsigned*)sPr;

    const int tid = threadIdx.x;
    const int lane = tid & 31, wid = tid >> 5;
    const int gid = lane >> 2, tig = lane & 3;
    const int i0 = (3 - (int)blockIdx.x) * 128;     // heavy tiles first
    const int bh = blockIdx.y;
    const int b = bh >> 4, h = bh & 15;
    const int lrow = (lane & 7) + ((lane >> 3) & 1) * 8;
    const int lcol = ((lane >> 4) & 1) * 8;
    const int rb0 = 384 - i0;                       // P window base at step 0
    const int nsteps = i0 / 64 + 10;

    __half* sSpW = (__half*)(base + 73728 + wid * 2816);   // 16 x 88 halves

    // ---- prologue: issue step-0 group (P rows rb0..rb0+191, K/V j0=0) ----
    {
#pragma unroll
        for (int it = 0; it < 6; it++) {
            const int f = tid + it * 256;
            const int rl = f >> 3, u = f & 7;
            const int r = rb0 + rl;
            const int slot = r & 255;
            const int src = min(r, TOT - 1);
            cp16(smem_u32(sPr + slot * 144 + u * 16),
                 pg + (size_t)src * DIN + h * HD + u * 8);
        }
        const __half* kb = kg + (size_t)b * DIN + h * HD;
        const __half* vb = vg + (size_t)b * DIN + h * HD;
#pragma unroll
        for (int it = 0; it < 2; it++) {
            const int f = tid + it * 256;
            const int r = f >> 3, u = f & 7;
            cp16(smem_u32(sKb + r * 144 + u * 16), kb + (size_t)r * BSZ * DIN + u * 8);
            cp16(smem_u32(sVb + r * 144 + u * 16), vb + (size_t)r * BSZ * DIN + u * 8);
        }
        CP_COMMIT();
    }

    // ---- Q fragments: load from global into registers (held all kernel) ----
    unsigned qu_f[4][4], qv_f[4][4];
    {
        const int r0 = i0 + wid * 16 + gid;
        const __half* a0 = qug + ((size_t)r0 * BSZ + b) * DIN + h * HD;
        const __half* a8 = a0 + (size_t)8 * BSZ * DIN;
        const __half* v0 = qvg + ((size_t)r0 * BSZ + b) * DIN + h * HD;
        const __half* v8 = v0 + (size_t)8 * BSZ * DIN;
#pragma unroll
        for (int kc = 0; kc < 4; kc++) {
            qu_f[kc][0] = *(const unsigned*)(a0 + kc * 16 + 2 * tig);
            qu_f[kc][1] = *(const unsigned*)(a8 + kc * 16 + 2 * tig);
            qu_f[kc][2] = *(const unsigned*)(a0 + kc * 16 + 8 + 2 * tig);
            qu_f[kc][3] = *(const unsigned*)(a8 + kc * 16 + 8 + 2 * tig);
            qv_f[kc][0] = *(const unsigned*)(v0 + kc * 16 + 2 * tig);
            qv_f[kc][1] = *(const unsigned*)(v8 + kc * 16 + 2 * tig);
            qv_f[kc][2] = *(const unsigned*)(v0 + kc * 16 + 8 + 2 * tig);
            qv_f[kc][3] = *(const unsigned*)(v8 + kc * 16 + 8 + 2 * tig);
        }
    }

    float o[8][4];
#pragma unroll
    for (int nt = 0; nt < 8; nt++)
#pragma unroll
        for (int e = 0; e < 4; e++) o[nt][e] = 0.f;
    float l0 = 0.f, l1 = 0.f;

    for (int s = 0; s < nsteps; s++) {
        const int j0 = s * 64;
        if (s + 1 < nsteps) {
            const int buf = (s + 1) & 1;
            const __half* kb = kg + ((size_t)(j0 + 64) * BSZ + b) * DIN + h * HD;
            const __half* vb = vg + ((size_t)(j0 + 64) * BSZ + b) * DIN + h * HD;
            const unsigned kd = smem_u32(sKb + buf * 9216);
            const unsigned vd = smem_u32(sVb + buf * 9216);
#pragma unroll
            for (int it = 0; it < 2; it++) {
                const int f = tid + it * 256;
                const int r = f >> 3, u = f & 7;
                cp16(kd + r * 144 + u * 16, kb + (size_t)r * BSZ * DIN + u * 8);
                cp16(vd + r * 144 + u * 16, vb + (size_t)r * BSZ * DIN + u * 8);
            }
            const int wb = rb0 + 64 * (s + 1) + 128;   // new 64 P rows for window s+1
#pragma unroll
            for (int it = 0; it < 2; it++) {
                const int f = tid + it * 256;
                const int rl = f >> 3, u = f & 7;
                const int r = wb + rl;
                const int slot = r & 255;
                const int src = min(r, TOT - 1);
                cp16(smem_u32(sPr + slot * 144 + u * 16),
                     pg + (size_t)src * DIN + h * HD + u * 8);
            }
        }
        CP_COMMIT();
        CP_WAIT1();
        __syncthreads();

        const int di = i0 + 16 * wid + 512 - j0;       // mask: lj <= di + li
        if (di + 15 >= 0) {                            // warp has unmasked work
            const unsigned* Ku = (const unsigned*)(sKb + (s & 1) * 9216);
            const unsigned  vB = smem_u32(sVb + (s & 1) * 9216);

            // ---- S_p = Qv_warp(16x64) @ P_slice(80x64)^T, staged in 2 halves ----
            const int rsg = j0 + 496 - i0 - 16 * wid + gid;   // ring row for this gid
#pragma unroll
            for (int half = 0; half < 2; half++) {
                float cp5[5][4];
#pragma unroll
                for (int nt = 0; nt < 5; nt++)
#pragma unroll
                    for (int e = 0; e < 4; e++) cp5[nt][e] = 0.f;
#pragma unroll
                for (int kc = 0; kc < 4; kc++) {
#pragma unroll
                    for (int nt = 0; nt < 5; nt++) {
                        const int slot = (rsg + half * 40 + nt * 8) & 255;
                        unsigned bf[2];
                        bf[0] = Pring[slot * 36 + kc * 8 + tig];
                        bf[1] = Pring[slot * 36 + kc * 8 + tig + 4];
                        MMA_F16(cp5[nt], qv_f[kc], bf);
                    }
                }
#pragma unroll
                for (int nt = 0; nt < 5; nt++) {
                    const int cn = (half * 5 + nt) * 8 + 2 * tig;
                    *(__half2*)&sSpW[gid * 88 + cn] =
                        __floats2half2_rn(cp5[nt][0], cp5[nt][1]);
                    *(__half2*)&sSpW[(gid + 8) * 88 + cn] =
                        __floats2half2_rn(cp5[nt][2], cp5[nt][3]);
                }
            }
            __syncwarp();

            // ---- S_c = Qu_warp(16x64) @ K^T(64x64) ----
            float cc[8][4];
#pragma unroll
            for (int nt = 0; nt < 8; nt++)
#pragma unroll
                for (int e = 0; e < 4; e++) cc[nt][e] = 0.f;
#pragma unroll
            for (int kc = 0; kc < 4; kc++)
#pragma unroll
                for (int nt = 0; nt < 8; nt++) {
                    unsigned bf[2];
                    bf[0] = Ku[(nt * 8 + gid) * 36 + kc * 8 + tig];
                    bf[1] = Ku[(nt * 8 + gid) * 36 + kc * 8 + tig + 4];
                    MMA_F16(cc[nt], qu_f[kc], bf);
                }

            // ---- combine + mask + exp (no-max) + pack; accumulate row sums ----
            unsigned pa[4][4];
            float ls0 = 0.f, ls1 = 0.f;
#pragma unroll
            for (int nt = 0; nt < 8; nt++) {
                const int lj = nt * 8 + 2 * tig;
                const int liA = gid, liB = gid + 8;
                float spA0 = __half2float(sSpW[liA * 88 + lj + 15 - liA]);
                float spA1 = __half2float(sSpW[liA * 88 + lj + 16 - liA]);
                float spB0 = __half2float(sSpW[liB * 88 + lj + 15 - liB]);
                float spB1 = __half2float(sSpW[liB * 88 + lj + 16 - liB]);
                float eA0 = (lj     <= di + liA) ? __expf((cc[nt][0] + spA0) * 0.125f) : 0.f;
                float eA1 = (lj + 1 <= di + liA) ? __expf((cc[nt][1] + spA1) * 0.125f) : 0.f;
                float eB0 = (lj     <= di + liB) ? __expf((cc[nt][2] + spB0) * 0.125f) : 0.f;
                float eB1 = (lj + 1 <= di + liB) ? __expf((cc[nt][3] + spB1) * 0.125f) : 0.f;
                ls0 += eA0 + eA1;
                ls1 += eB0 + eB1;
                __half2 hA = __floats2half2_rn(eA0, eA1);
                __half2 hB = __floats2half2_rn(eB0, eB1);
                pa[nt >> 1][(nt & 1) * 2]     = *(unsigned*)&hA;
                pa[nt >> 1][(nt & 1) * 2 + 1] = *(unsigned*)&hB;
            }
            ls0 += __shfl_xor_sync(0xffffffffu, ls0, 1);
            ls0 += __shfl_xor_sync(0xffffffffu, ls0, 2);
            ls1 += __shfl_xor_sync(0xffffffffu, ls1, 1);
            ls1 += __shfl_xor_sync(0xffffffffu, ls1, 2);
            l0 += ls0; l1 += ls1;

            // ---- O += P @ V (probs already in A-fragment registers) ----
#pragma unroll
            for (int kc = 0; kc < 4; kc++) {
#pragma unroll
                for (int np = 0; np < 4; np++) {
                    unsigned r0, r1, r2, r3;
                    ldmx4t(r0, r1, r2, r3,
                           vB + (kc * 16 + lrow) * 144 + (np * 16 + lcol) * 2);
                    unsigned b0[2] = {r0, r1}, b1[2] = {r2, r3};
                    MMA_F16(o[2 * np],     pa[kc], b0);
                    MMA_F16(o[2 * np + 1], pa[kc], b1);
                }
            }
        }
        __syncthreads();   // buffers + ring + sSp free for next step
    }

    // ---- write awv = O / l (fp16) ----
    const float inv0 = 1.f / l0, inv1 = 1.f / l1;
    const int r0 = i0 + wid * 16 + gid;
#pragma unroll
    for (int nt = 0; nt < 8; nt++) {
        const int c = nt * 8 + 2 * tig;
        *(__half2*)&awv[((size_t)r0 * BSZ + b) * DIN + h * HD + c] =
            __floats2half2_rn(o[nt][0] * inv0, o[nt][1] * inv0);
        *(__half2*)&awv[((size_t)(r0 + 8) * BSZ + b) * DIN + h * HD + c] =
            __floats2half2_rn(o[nt][2] * inv1, o[nt][3] * inv1);
    }
}

// ---------------- LayerNorm over last dim (1024), one block per row ------------
__global__ __launch_bounds__(256) void ln_kernel(
    const float* __restrict__ x, const float* __restrict__ gamma,
    const float* __restrict__ beta, float* __restrict__ out)
{
    const size_t row = blockIdx.x;
    const int tid = threadIdx.x;
    const float4 v = ((const float4*)(x + row * DIN))[tid];
    __shared__ float red[8];

    float s = v.x + v.y + v.z + v.w;
#pragma unroll
    for (int o = 16; o; o >>= 1) s += __shfl_xor_sync(0xffffffffu, s, o);
    if ((tid & 31) == 0) red[tid >> 5] = s;
    __syncthreads();
    s = red[0];
#pragma unroll
    for (int w = 1; w < 8; w++) s += red[w];
    const float mu = s * (1.0f / DIN);
    __syncthreads();

    const float d0 = v.x - mu, d1 = v.y - mu, d2 = v.z - mu, d3 = v.w - mu;
    float s2 = d0 * d0 + d1 * d1 + d2 * d2 + d3 * d3;
#pragma unroll
    for (int o = 16; o; o >>= 1) s2 += __shfl_xor_sync(0xffffffffu, s2, o);
    if ((tid & 31) == 0) red[tid >> 5] = s2;
    __syncthreads();
    s2 = red[0];
#pragma unroll
    for (int w = 1; w < 8; w++) s2 += red[w];
    const float inv = rsqrtf(s2 * (1.0f / DIN) + 1e-5f);

    const float4 g  = ((const float4*)gamma)[tid];
    const float4 bb = ((const float4*)beta)[tid];
    float4 o4;
    o4.x = d0 * inv * g.x + bb.x;
    o4.y = d1 * inv * g.y + bb.y;
    o4.z = d2 * inv * g.z + bb.z;
    o4.w = d3 * inv * g.w + bb.w;
    ((float4*)(out + row * DIN))[tid] = o4;
}

// ---------------- launch ---------------------------------------------------------
extern "C" void kernel_launch(void* const* d_in, const int* in_sizes, int n_in,
                              void* d_out, int out_size)
{
    const float* input_ = (const float*)d_in[0];
    const float* pos    = (const float*)d_in[1];
    const float* memory = (const float*)d_in[2];
    const float* u      = (const float*)d_in[3];
    const float* vvec   = (const float*)d_in[4];
    // d_in[5] = mask (analytic: j <= i + PREV)
    const float* W_kv   = (const float*)d_in[6];
    const float* W_q    = (const float*)d_in[7];
    const float* W_p    = (const float*)d_in[8];
    const float* W_out  = (const float*)d_in[9];
    const float* gamma  = (const float*)d_in[10];
    const float* beta   = (const float*)d_in[11];
    float* out = (float*)d_out;

    __half *pin, *pmem, *ppos, *pwkv, *pwq, *pwp, *pwo;
    __half *pk, *pv, *pp, *pqu, *pqv, *pawv;
    float* pout;
    cudaGetSymbolAddress((void**)&pin,  g_in16);
    cudaGetSymbolAddress((void**)&pmem, g_mem16);
    cudaGetSymbolAddress((void**)&ppos, g_pos16);
    cudaGetSymbolAddress((void**)&pwkv, g_wkv16);
    cudaGetSymbolAddress((void**)&pwq,  g_wq16);
    cudaGetSymbolAddress((void**)&pwp,  g_wp16);
    cudaGetSymbolAddress((void**)&pwo,  g_wo16);
    cudaGetSymbolAddress((void**)&pk,   g_kh);
    cudaGetSymbolAddress((void**)&pv,   g_vh);
    cudaGetSymbolAddress((void**)&pp,   g_ph);
    cudaGetSymbolAddress((void**)&pqu,  g_qu);
    cudaGetSymbolAddress((void**)&pqv,  g_qv);
    cudaGetSymbolAddress((void**)&pawv, g_awv);
    cudaGetSymbolAddress((void**)&pout, g_out);

    const int GEMM_SMEM = 4 * A_STAGE + 4 * B_STAGE;   // 75776
    const int FA_SMEM   = 96256;
    cudaFuncSetAttribute(proj_mega, cudaFuncAttributeMaxDynamicSharedMemorySize, GEMM_SMEM);
    cudaFuncSetAttribute(out_gemm,  cudaFuncAttributeMaxDynamicSharedMemorySize, GEMM_SMEM);
    cudaFuncSetAttribute(flash_attn, cudaFuncAttributeMaxDynamicSharedMemorySize, FA_SMEM);

    // 0) fp32 -> fp16 conversions, single launch
    CvtSegs segs;
    segs.src[0] = (const float4*)input_; segs.dst[0] = (__half2*)pin;  segs.n4[0] = SEQ * BSZ * DIN / 4;
    segs.src[1] = (const float4*)memory; segs.dst[1] = (__half2*)pmem; segs.n4[1] = PREV * BSZ * DIN / 4;
    segs.src[2] = (const float4*)pos;    segs.dst[2] = (__half2*)ppos; segs.n4[2] = TOT * DIN / 4;
    segs.src[3] = (const float4*)W_kv;   segs.dst[3] = (__half2*)pwkv; segs.n4[3] = DIN * 2 * DIN / 4;
    segs.src[4] = (const float4*)W_q;    segs.dst[4] = (__half2*)pwq;  segs.n4[4] = DIN * DIN / 4;
    segs.src[5] = (const float4*)W_p;    segs.dst[5] = (__half2*)pwp;  segs.n4[5] = DIN * DIN / 4;
    segs.src[6] = (const float4*)W_out;  segs.dst[6] = (__half2*)pwo;  segs.n4[6] = DIN * DIN / 4;
    int total4 = 0;
    for (int k = 0; k < 7; k++) total4 += segs.n4[k];
    cvt_all<<<(total4 + 255) / 256, 256>>>(segs);

    // 1) all projections (kv | q | p) in one launch
    proj_mega<<<1344, 256, GEMM_SMEM>>>(
        pin, pmem, ppos, pwkv, pwq, pwp,
        pk, pv, pqu, pqv, pp, u, vvec);

    // 2) fused attention -> awv (fp16)
    flash_attn<<<dim3(4, BSZ * NH), 256, FA_SMEM>>>(
        pqu, pqv, pk, pv, pp, pawv);

    // 3) out_pre = input_ + awv @ W_out (fp32)
    out_gemm<<<dim3(8, 32), 256, GEMM_SMEM>>>(pawv, pwo, pout, input_);

    // 4) LayerNorm -> d_out
    ln_kernel<<<SEQ * BSZ, 256>>>(pout, gamma, beta, out);
}